// round 1
// baseline (speedup 1.0000x reference)
#include <cuda_runtime.h>
#include <math.h>
#include <stdint.h>

// ---------------- problem constants ----------------
#define SEQ   2048
#define HDIM  2048
#define NHEAD 16
#define DQK   192
#define DV    128
#define NOPE  128
#define ROPED 64
#define QRNK  768
#define KVRNK 512
#define NEXP  16
#define TOPK  4
#define MINT  1024
#define NSLOT (SEQ*TOPK)

// ---------------- scratch (global device arrays; no allocation) ----------------
__device__ float g_h1[SEQ*HDIM];
__device__ float g_qa[SEQ*QRNK];
__device__ float g_kva[SEQ*KVRNK];
__device__ float g_q[SEQ*NHEAD*DQK];
__device__ float g_kv[SEQ*NHEAD*(DQK+DV)];
__device__ float g_ctx[SEQ*NHEAD*DV];
__device__ float g_xmid[SEQ*HDIM];
__device__ float g_h2[SEQ*HDIM];
__device__ float g_logits[SEQ*NEXP];
__device__ float g_wtop[SEQ*TOPK];
__device__ int   g_topi[SEQ*TOPK];
__device__ int   g_slot[SEQ*TOPK];
__device__ int   g_cnt[NEXP];
__device__ int   g_off[NEXP+1];
__device__ int   g_fill[NEXP];
__device__ int   g_tok[NSLOT];
__device__ float g_gate[(size_t)NSLOT*MINT];
__device__ float g_up[(size_t)NSLOT*MINT];
__device__ float g_down[(size_t)NSLOT*HDIM];
__device__ float g_sg[SEQ*MINT];
__device__ float g_su[SEQ*MINT];
__device__ float g_shr[SEQ*HDIM];

// ---------------- RMSNorm: one block per row ----------------
__global__ void rmsnorm_kernel(const float* in, const float* w, float* out, int D) {
    int t = blockIdx.x;
    const float* row = in + (size_t)t * D;
    float ss = 0.f;
    for (int i = threadIdx.x; i < D; i += blockDim.x) { float v = row[i]; ss += v * v; }
    // reduce
    __shared__ float sred[32];
    for (int o = 16; o > 0; o >>= 1) ss += __shfl_down_sync(0xffffffffu, ss, o);
    int lane = threadIdx.x & 31, warp = threadIdx.x >> 5;
    if (lane == 0) sred[warp] = ss;
    __syncthreads();
    int nw = blockDim.x >> 5;
    if (threadIdx.x == 0) {
        float tot = 0.f;
        for (int i = 0; i < nw; i++) tot += sred[i];
        sred[0] = 1.0f / sqrtf(tot / (float)D + 1e-6f);
    }
    __syncthreads();
    float scale = sred[0];
    for (int i = threadIdx.x; i < D; i += blockDim.x)
        out[(size_t)t * D + i] = row[i] * scale * w[i];
}

// ---------------- Generic SGEMM: C[M,N] = A[M,K] @ B[N,K]^T (+ addsrc) ----------------
// BM=BN=128, BK=16, 256 threads, 8x8 register tile per thread.
__global__ __launch_bounds__(256) void gemm_nt(
    const float* __restrict__ A, const float* __restrict__ B, float* __restrict__ C,
    const float* __restrict__ addsrc, int M, int N, int K)
{
    __shared__ float As[16][128];
    __shared__ float Bs[16][128];
    int m0 = blockIdx.y * 128, n0 = blockIdx.x * 128;
    int tid = threadIdx.x;
    int tr = tid >> 4, tc = tid & 15;
    float acc[8][8];
#pragma unroll
    for (int i = 0; i < 8; i++)
#pragma unroll
        for (int j = 0; j < 8; j++) acc[i][j] = 0.f;

    for (int k0 = 0; k0 < K; k0 += 16) {
#pragma unroll
        for (int i = 0; i < 2; i++) {
            int idx = tid + i * 256;
            int row = idx >> 2, kc = (idx & 3) << 2;
            float4 v = make_float4(0.f, 0.f, 0.f, 0.f);
            int gr = m0 + row;
            if (gr < M) v = *(const float4*)(A + (size_t)gr * K + k0 + kc);
            As[kc + 0][row] = v.x; As[kc + 1][row] = v.y;
            As[kc + 2][row] = v.z; As[kc + 3][row] = v.w;
        }
#pragma unroll
        for (int i = 0; i < 2; i++) {
            int idx = tid + i * 256;
            int row = idx >> 2, kc = (idx & 3) << 2;
            float4 v = make_float4(0.f, 0.f, 0.f, 0.f);
            int gc = n0 + row;
            if (gc < N) v = *(const float4*)(B + (size_t)gc * K + k0 + kc);
            Bs[kc + 0][row] = v.x; Bs[kc + 1][row] = v.y;
            Bs[kc + 2][row] = v.z; Bs[kc + 3][row] = v.w;
        }
        __syncthreads();
#pragma unroll
        for (int k = 0; k < 16; k++) {
            float a[8], b[8];
            *(float4*)&a[0] = *(const float4*)&As[k][tr * 8];
            *(float4*)&a[4] = *(const float4*)&As[k][tr * 8 + 4];
            *(float4*)&b[0] = *(const float4*)&Bs[k][tc * 8];
            *(float4*)&b[4] = *(const float4*)&Bs[k][tc * 8 + 4];
#pragma unroll
            for (int i = 0; i < 8; i++)
#pragma unroll
                for (int j = 0; j < 8; j++) acc[i][j] += a[i] * b[j];
        }
        __syncthreads();
    }
#pragma unroll
    for (int i = 0; i < 8; i++) {
        int gr = m0 + tr * 8 + i;
        if (gr >= M) continue;
#pragma unroll
        for (int j = 0; j < 8; j++) {
            int gc = n0 + tc * 8 + j;
            if (gc >= N) continue;
            float v = acc[i][j];
            if (addsrc) v += addsrc[(size_t)gr * N + gc];
            C[(size_t)gr * N + gc] = v;
        }
    }
}

// ---------------- Grouped/gathered SGEMM for MoE ----------------
// Per expert e (blockIdx.z): rows are slots [off[e], off[e+1]).
// A row index = gather ? gather[slot] : slot. Output written slot-major C[slot*N+n].
__global__ __launch_bounds__(256) void gemm_moe_nt(
    const float* __restrict__ A, const int* __restrict__ gather,
    const float* __restrict__ Bbase, size_t strideB,
    float* __restrict__ C, int N, int K, const int* __restrict__ off)
{
    int e = blockIdx.z;
    int start = off[e];
    int cnt = off[e + 1] - start;
    int m0 = blockIdx.y * 128;
    if (m0 >= cnt) return;
    int n0 = blockIdx.x * 128;
    const float* B = Bbase + (size_t)e * strideB;

    __shared__ float As[16][128];
    __shared__ float Bs[16][128];
    __shared__ int rowmap[128];
    int tid = threadIdx.x;
    if (tid < 128) {
        int r = m0 + tid;
        int g = -1;
        if (r < cnt) g = gather ? gather[start + r] : (start + r);
        rowmap[tid] = g;
    }
    __syncthreads();

    int tr = tid >> 4, tc = tid & 15;
    float acc[8][8];
#pragma unroll
    for (int i = 0; i < 8; i++)
#pragma unroll
        for (int j = 0; j < 8; j++) acc[i][j] = 0.f;

    for (int k0 = 0; k0 < K; k0 += 16) {
#pragma unroll
        for (int i = 0; i < 2; i++) {
            int idx = tid + i * 256;
            int row = idx >> 2, kc = (idx & 3) << 2;
            float4 v = make_float4(0.f, 0.f, 0.f, 0.f);
            int gr = rowmap[row];
            if (gr >= 0) v = *(const float4*)(A + (size_t)gr * K + k0 + kc);
            As[kc + 0][row] = v.x; As[kc + 1][row] = v.y;
            As[kc + 2][row] = v.z; As[kc + 3][row] = v.w;
        }
#pragma unroll
        for (int i = 0; i < 2; i++) {
            int idx = tid + i * 256;
            int row = idx >> 2, kc = (idx & 3) << 2;
            float4 v = make_float4(0.f, 0.f, 0.f, 0.f);
            int gc = n0 + row;
            if (gc < N) v = *(const float4*)(B + (size_t)gc * K + k0 + kc);
            Bs[kc + 0][row] = v.x; Bs[kc + 1][row] = v.y;
            Bs[kc + 2][row] = v.z; Bs[kc + 3][row] = v.w;
        }
        __syncthreads();
#pragma unroll
        for (int k = 0; k < 16; k++) {
            float a[8], b[8];
            *(float4*)&a[0] = *(const float4*)&As[k][tr * 8];
            *(float4*)&a[4] = *(const float4*)&As[k][tr * 8 + 4];
            *(float4*)&b[0] = *(const float4*)&Bs[k][tc * 8];
            *(float4*)&b[4] = *(const float4*)&Bs[k][tc * 8 + 4];
#pragma unroll
            for (int i = 0; i < 8; i++)
#pragma unroll
                for (int j = 0; j < 8; j++) acc[i][j] += a[i] * b[j];
        }
        __syncthreads();
    }
#pragma unroll
    for (int i = 0; i < 8; i++) {
        int r = m0 + tr * 8 + i;
        if (r >= cnt) continue;
#pragma unroll
        for (int j = 0; j < 8; j++) {
            int gc = n0 + tc * 8 + j;
            if (gc >= N) continue;
            C[(size_t)(start + r) * N + gc] = acc[i][j];
        }
    }
}

// ---------------- RoPE applied in-place to q and k_rope slices ----------------
__global__ void rope_kernel() {
    int idx = blockIdx.x * blockDim.x + threadIdx.x;
    int total = SEQ * NHEAD * (ROPED / 2);
    if (idx >= total) return;
    int i = idx & 31;
    int h = (idx >> 5) & (NHEAD - 1);
    int t = idx >> 9;
    float inv_freq = powf(10000.0f, -(float)(2 * i) / (float)ROPED);
    float f = (float)t * inv_freq;
    float c = cosf(f), s = sinf(f);
    float* qp = g_q + ((size_t)t * NHEAD + h) * DQK + NOPE;
    float x1 = qp[i], x2 = qp[i + 32];
    qp[i] = x1 * c - x2 * s;
    qp[i + 32] = x2 * c + x1 * s;
    float* kp = g_kv + ((size_t)t * NHEAD + h) * (DQK + DV) + NOPE;
    x1 = kp[i]; x2 = kp[i + 32];
    kp[i] = x1 * c - x2 * s;
    kp[i + 32] = x2 * c + x1 * s;
}

// ---------------- Flash attention: 1 thread per query, 128 queries/block ----------------
#define ATTN_SMEM ((128*193 + 64*192 + 64*128) * 4)
__global__ __launch_bounds__(128) void attn_kernel() {
    extern __shared__ float sm[];
    float* Qs = sm;                 // [128][193]
    float* Ks = sm + 128 * 193;     // [64][192]
    float* Vs = Ks + 64 * 192;      // [64][128]

    int h = blockIdx.y;
    int q0 = blockIdx.x * 128;
    int tid = threadIdx.x;
    int qi = q0 + tid;

    // load Q tile
    for (int idx = tid; idx < 128 * 192; idx += 128) {
        int r = idx / 192, d = idx - r * 192;
        Qs[r * 193 + d] = g_q[((size_t)(q0 + r) * NHEAD + h) * DQK + d];
    }

    float acc[128];
#pragma unroll
    for (int d = 0; d < 128; d++) acc[d] = 0.f;
    float mval = -1e30f, lsum = 0.f;
    const float scale = 0.07216878364870323f; // 1/sqrt(192)

    int ntiles = blockIdx.x * 2 + 2;
    for (int tile = 0; tile < ntiles; tile++) {
        int t0 = tile * 64;
        __syncthreads();
        for (int idx = tid; idx < 64 * 192; idx += 128) {
            int r = idx / 192, d = idx - r * 192;
            Ks[r * 192 + d] = g_kv[((size_t)(t0 + r) * NHEAD + h) * (DQK + DV) + d];
        }
        for (int idx = tid; idx < 64 * 128; idx += 128) {
            int r = idx >> 7, d = idx & 127;
            Vs[r * 128 + d] = g_kv[((size_t)(t0 + r) * NHEAD + h) * (DQK + DV) + DQK + d];
        }
        __syncthreads();

        const float* qrow = &Qs[tid * 193];
        for (int j = 0; j < 64; j++) {
            int kj = t0 + j;
            if (kj > qi) break;
            const float* krow = &Ks[j * 192];
            float s = 0.f;
#pragma unroll 8
            for (int d = 0; d < 192; d++) s += qrow[d] * krow[d];
            s *= scale;
            const float* vrow = &Vs[j * 128];
            if (s <= mval) {
                float p = __expf(s - mval);
                lsum += p;
#pragma unroll
                for (int d = 0; d < 128; d++) acc[d] += p * vrow[d];
            } else {
                float cfac = __expf(mval - s);
                lsum = lsum * cfac + 1.f;
#pragma unroll
                for (int d = 0; d < 128; d++) acc[d] = acc[d] * cfac + vrow[d];
                mval = s;
            }
        }
    }
    float inv = 1.0f / lsum;
#pragma unroll
    for (int d = 0; d < 128; d++)
        g_ctx[(size_t)qi * (NHEAD * DV) + h * DV + d] = acc[d] * inv;
}

// ---------------- Router logits: one block per token ----------------
__global__ void router_kernel(const float* __restrict__ rw, const float* __restrict__ rb) {
    int t = blockIdx.x;
    float part[NEXP];
#pragma unroll
    for (int e = 0; e < NEXP; e++) part[e] = 0.f;
    for (int hh = threadIdx.x; hh < HDIM; hh += 128) {
        float xv = g_h2[(size_t)t * HDIM + hh];
#pragma unroll
        for (int e = 0; e < NEXP; e++) part[e] += xv * rw[(size_t)e * HDIM + hh];
    }
    __shared__ float sred[4][NEXP];
#pragma unroll
    for (int e = 0; e < NEXP; e++)
        for (int o = 16; o > 0; o >>= 1) part[e] += __shfl_down_sync(0xffffffffu, part[e], o);
    int lane = threadIdx.x & 31, warp = threadIdx.x >> 5;
    if (lane == 0)
#pragma unroll
        for (int e = 0; e < NEXP; e++) sred[warp][e] = part[e];
    __syncthreads();
    if (threadIdx.x < NEXP) {
        int e = threadIdx.x;
        g_logits[t * NEXP + e] = sred[0][e] + sred[1][e] + sred[2][e] + sred[3][e] + rb[e];
    }
}

__global__ void zero_kernel() {
    if (threadIdx.x < NEXP) { g_cnt[threadIdx.x] = 0; g_fill[threadIdx.x] = 0; }
}

__global__ void topk_kernel() {
    int t = blockIdx.x * blockDim.x + threadIdx.x;
    if (t >= SEQ) return;
    float p[NEXP];
#pragma unroll
    for (int e = 0; e < NEXP; e++) p[e] = 1.0f / (1.0f + expf(-g_logits[t * NEXP + e]));
    float vals[TOPK]; int ids[TOPK];
    float sum = 0.f;
#pragma unroll
    for (int k = 0; k < TOPK; k++) {
        float best = -1e30f; int bi = 0;
#pragma unroll
        for (int e = 0; e < NEXP; e++)
            if (p[e] > best) { best = p[e]; bi = e; }
        vals[k] = best; ids[k] = bi; p[bi] = -1e30f; sum += best;
    }
    float w = 2.5f / (sum + 1e-9f);
#pragma unroll
    for (int k = 0; k < TOPK; k++) {
        g_wtop[t * TOPK + k] = vals[k] * w;
        g_topi[t * TOPK + k] = ids[k];
        atomicAdd(&g_cnt[ids[k]], 1);
    }
}

__global__ void offsets_kernel() {
    if (threadIdx.x == 0) {
        g_off[0] = 0;
        for (int e = 0; e < NEXP; e++) g_off[e + 1] = g_off[e] + g_cnt[e];
    }
}

__global__ void scatter_kernel() {
    int t = blockIdx.x * blockDim.x + threadIdx.x;
    if (t >= SEQ) return;
#pragma unroll
    for (int k = 0; k < TOPK; k++) {
        int e = g_topi[t * TOPK + k];
        int pos = atomicAdd(&g_fill[e], 1);
        int slot = g_off[e] + pos;
        g_slot[t * TOPK + k] = slot;
        g_tok[slot] = t;
    }
}

// ---------------- SiLU(a)*b elementwise (in place into a) ----------------
__global__ void act_kernel(float* a, const float* b, size_t n) {
    size_t i = (size_t)blockIdx.x * blockDim.x + threadIdx.x;
    if (i >= n) return;
    float g = a[i];
    float sg = g / (1.0f + expf(-g));
    a[i] = sg * b[i];
}

// ---------------- Final combine: residual + shared + weighted routed ----------------
__global__ void combine_kernel(float* out) {
    int t = blockIdx.x;
    float w[TOPK]; int s[TOPK];
#pragma unroll
    for (int k = 0; k < TOPK; k++) { w[k] = g_wtop[t * TOPK + k]; s[k] = g_slot[t * TOPK + k]; }
    for (int hh = threadIdx.x; hh < HDIM; hh += 256) {
        float v = g_xmid[(size_t)t * HDIM + hh] + g_shr[(size_t)t * HDIM + hh];
#pragma unroll
        for (int k = 0; k < TOPK; k++)
            v += w[k] * g_down[(size_t)s[k] * HDIM + hh];
        out[(size_t)t * HDIM + hh] = v;
    }
}

// ---------------- host ----------------
static float* symf(const void* sym) { void* p = nullptr; cudaGetSymbolAddress(&p, sym); return (float*)p; }
static int*   symi(const void* sym) { void* p = nullptr; cudaGetSymbolAddress(&p, sym); return (int*)p; }

extern "C" void kernel_launch(void* const* d_in, const int* in_sizes, int n_in,
                              void* d_out, int out_size)
{
    const float* x      = (const float*)d_in[0];
    // d_in[1] attention_mask (pure causal; implemented directly)
    const float* ln1_w  = (const float*)d_in[2];
    const float* ln2_w  = (const float*)d_in[3];
    const float* q_a_w  = (const float*)d_in[4];
    const float* q_a_ln = (const float*)d_in[5];
    const float* q_b_w  = (const float*)d_in[6];
    const float* kv_a_w = (const float*)d_in[7];
    const float* kv_a_ln= (const float*)d_in[8];
    const float* kv_b_w = (const float*)d_in[9];
    const float* o_w    = (const float*)d_in[10];
    const float* rout_w = (const float*)d_in[11];
    const float* rout_b = (const float*)d_in[12];
    const float* gate_w = (const float*)d_in[13];
    const float* up_w   = (const float*)d_in[14];
    const float* down_w = (const float*)d_in[15];
    const float* sg_w   = (const float*)d_in[16];
    const float* su_w   = (const float*)d_in[17];
    const float* sd_w   = (const float*)d_in[18];
    float* out = (float*)d_out;

    float* h1   = symf(g_h1);
    float* qa   = symf(g_qa);
    float* kva  = symf(g_kva);
    float* q    = symf(g_q);
    float* kv   = symf(g_kv);
    float* ctx  = symf(g_ctx);
    float* xmid = symf(g_xmid);
    float* h2   = symf(g_h2);
    float* gate = symf(g_gate);
    float* up   = symf(g_up);
    float* down = symf(g_down);
    float* sg   = symf(g_sg);
    float* su   = symf(g_su);
    float* shr  = symf(g_shr);
    int*   tok  = symi(g_tok);
    int*   off  = symi(g_off);

    cudaFuncSetAttribute(attn_kernel, cudaFuncAttributeMaxDynamicSharedMemorySize, ATTN_SMEM);

    // ---- attention branch ----
    rmsnorm_kernel<<<SEQ, 256>>>(x, ln1_w, h1, HDIM);
    gemm_nt<<<dim3(QRNK / 128, SEQ / 128), 256>>>(h1, q_a_w, qa, nullptr, SEQ, QRNK, HDIM);
    rmsnorm_kernel<<<SEQ, 256>>>(qa, q_a_ln, qa, QRNK);
    gemm_nt<<<dim3(KVRNK / 128, SEQ / 128), 256>>>(h1, kv_a_w, kva, nullptr, SEQ, KVRNK, HDIM);
    rmsnorm_kernel<<<SEQ, 256>>>(kva, kv_a_ln, kva, KVRNK);
    gemm_nt<<<dim3(NHEAD * DQK / 128, SEQ / 128), 256>>>(qa, q_b_w, q, nullptr, SEQ, NHEAD * DQK, QRNK);
    gemm_nt<<<dim3(NHEAD * (DQK + DV) / 128, SEQ / 128), 256>>>(kva, kv_b_w, kv, nullptr, SEQ, NHEAD * (DQK + DV), KVRNK);
    rope_kernel<<<(SEQ * NHEAD * (ROPED / 2) + 255) / 256, 256>>>();
    attn_kernel<<<dim3(SEQ / 128, NHEAD), 128, ATTN_SMEM>>>();
    gemm_nt<<<dim3(HDIM / 128, SEQ / 128), 256>>>(ctx, o_w, xmid, x, SEQ, HDIM, NHEAD * DV);

    // ---- MoE branch ----
    rmsnorm_kernel<<<SEQ, 256>>>(xmid, ln2_w, h2, HDIM);
    router_kernel<<<SEQ, 128>>>(rout_w, rout_b);
    zero_kernel<<<1, 32>>>();
    topk_kernel<<<SEQ / 256, 256>>>();
    offsets_kernel<<<1, 1>>>();
    scatter_kernel<<<SEQ / 256, 256>>>();

    gemm_moe_nt<<<dim3(MINT / 128, SEQ / 128, NEXP), 256>>>(h2, tok, gate_w, (size_t)MINT * HDIM, gate, MINT, HDIM, off);
    gemm_moe_nt<<<dim3(MINT / 128, SEQ / 128, NEXP), 256>>>(h2, tok, up_w, (size_t)MINT * HDIM, up, MINT, HDIM, off);
    act_kernel<<<(unsigned)(((size_t)NSLOT * MINT + 255) / 256), 256>>>(gate, up, (size_t)NSLOT * MINT);
    gemm_moe_nt<<<dim3(HDIM / 128, SEQ / 128, NEXP), 256>>>(gate, nullptr, down_w, (size_t)HDIM * MINT, down, HDIM, MINT, off);

    // shared expert
    gemm_nt<<<dim3(MINT / 128, SEQ / 128), 256>>>(h2, sg_w, sg, nullptr, SEQ, MINT, HDIM);
    gemm_nt<<<dim3(MINT / 128, SEQ / 128), 256>>>(h2, su_w, su, nullptr, SEQ, MINT, HDIM);
    act_kernel<<<(unsigned)(((size_t)SEQ * MINT + 255) / 256), 256>>>(sg, su, (size_t)SEQ * MINT);
    gemm_nt<<<dim3(HDIM / 128, SEQ / 128), 256>>>(sg, sd_w, shr, nullptr, SEQ, HDIM, MINT);

    combine_kernel<<<SEQ, 256>>>(out);
}

// round 2
// speedup vs baseline: 1.5759x; 1.5759x over previous
#include <cuda_runtime.h>
#include <math.h>
#include <stdint.h>

// ---------------- problem constants ----------------
#define SEQ   2048
#define HDIM  2048
#define NHEAD 16
#define DQK   192
#define DV    128
#define NOPE  128
#define ROPED 64
#define QRNK  768
#define KVRNK 512
#define NEXP  16
#define TOPK  4
#define MINT  1024
#define NSLOT (SEQ*TOPK)

// GEMM tiling
#define BM 128
#define BN 128
#define BK 32
#define PADK 36
#define GSMEM (2*(BM+BN)*PADK*4)

// ---------------- scratch ----------------
__device__ float g_h1[SEQ*HDIM];
__device__ float g_qa[SEQ*QRNK];
__device__ float g_kva[SEQ*KVRNK];
__device__ float g_q[SEQ*NHEAD*DQK];
__device__ float g_kv[SEQ*NHEAD*(DQK+DV)];
__device__ float g_ctx[SEQ*NHEAD*DV];
__device__ float g_xmid[SEQ*HDIM];
__device__ float g_h2[SEQ*HDIM];
__device__ float g_logits[SEQ*NEXP];
__device__ float g_wtop[SEQ*TOPK];
__device__ int   g_topi[SEQ*TOPK];
__device__ int   g_slot[SEQ*TOPK];
__device__ int   g_cnt[NEXP];
__device__ int   g_off[NEXP+1];
__device__ int   g_fill[NEXP];
__device__ int   g_tok[NSLOT];
__device__ float g_gate[(size_t)NSLOT*MINT];
__device__ float g_up[(size_t)NSLOT*MINT];
__device__ float g_down[(size_t)NSLOT*HDIM];
__device__ float g_sg[SEQ*MINT];
__device__ float g_su[SEQ*MINT];
__device__ float g_shr[SEQ*HDIM];

// ---------------- helpers ----------------
__device__ __forceinline__ uint32_t f2tf32(float f) {
    uint32_t r;
    asm("cvt.rna.tf32.f32 %0, %1;" : "=r"(r) : "f"(f));
    return r;
}
__device__ __forceinline__ void cp16(uint32_t dst, const void* src, int szbytes) {
    asm volatile("cp.async.cg.shared.global [%0], [%1], 16, %2;\n"
                 :: "r"(dst), "l"(src), "r"(szbytes));
}
__device__ __forceinline__ void cp_commit() { asm volatile("cp.async.commit_group;\n"); }
__device__ __forceinline__ void cp_wait0()  { asm volatile("cp.async.wait_group 0;\n"); }
__device__ __forceinline__ void cp_wait1()  { asm volatile("cp.async.wait_group 1;\n"); }

__device__ __forceinline__ void mma_tf32(float* c, const uint32_t* a, const uint32_t* b) {
    asm volatile(
        "mma.sync.aligned.m16n8k8.row.col.f32.tf32.tf32.f32 "
        "{%0,%1,%2,%3}, {%4,%5,%6,%7}, {%8,%9}, {%0,%1,%2,%3};\n"
        : "+f"(c[0]), "+f"(c[1]), "+f"(c[2]), "+f"(c[3])
        : "r"(a[0]), "r"(a[1]), "r"(a[2]), "r"(a[3]), "r"(b[0]), "r"(b[1]));
}

// ---------------- TF32 tensor-core GEMM: C[M,N] = A[M,K] @ B[N,K]^T (+ addsrc) ----------------
__global__ __launch_bounds__(256) void gemm_tf32(
    const float* __restrict__ A, const float* __restrict__ B, float* __restrict__ C,
    const float* __restrict__ addsrc, int M, int N, int K)
{
    extern __shared__ float sm[];
    float* As0 = sm;                       // [BM][PADK] x2
    float* Bs0 = sm + 2 * BM * PADK;       // [BN][PADK] x2

    const int tid = threadIdx.x;
    const int warp = tid >> 5, lane = tid & 31;
    const int g = lane >> 2, tig = lane & 3;
    const int warp_m = (warp & 1) * 64, warp_n = (warp >> 1) * 32;
    const int m0 = blockIdx.y * BM, n0 = blockIdx.x * BN;

    const int ldrow = tid >> 3;            // 0..31 within 256-thread pass of 1024 chunks? no:
    // chunk id scheme: cid = tid + i*256 ; row = cid>>3 ; kq = (cid&7)<<2
    float acc[4][4][4];
#pragma unroll
    for (int a = 0; a < 4; a++)
#pragma unroll
        for (int b = 0; b < 4; b++)
#pragma unroll
            for (int c = 0; c < 4; c++) acc[a][b][c] = 0.f;

    const int nk = K / BK;
    uint32_t smA[2], smB[2];
    smA[0] = (uint32_t)__cvta_generic_to_shared(As0);
    smA[1] = (uint32_t)__cvta_generic_to_shared(As0 + BM * PADK);
    smB[0] = (uint32_t)__cvta_generic_to_shared(Bs0);
    smB[1] = (uint32_t)__cvta_generic_to_shared(Bs0 + BN * PADK);

    // prologue: tile 0 -> buf 0
    {
        const int k0 = 0;
#pragma unroll
        for (int i = 0; i < 4; i++) {
            int cid = tid + i * 256;
            int row = cid >> 3, kq = (cid & 7) << 2;
            cp16(smA[0] + (row * PADK + kq) * 4, A + (size_t)(m0 + row) * K + k0 + kq, 16);
        }
#pragma unroll
        for (int i = 0; i < 4; i++) {
            int cid = tid + i * 256;
            int row = cid >> 3, kq = (cid & 7) << 2;
            cp16(smB[0] + (row * PADK + kq) * 4, B + (size_t)(n0 + row) * K + k0 + kq, 16);
        }
        cp_commit();
    }

    for (int kt = 0; kt < nk; kt++) {
        int cur = kt & 1;
        if (kt + 1 < nk) {
            int nb = cur ^ 1;
            int k0 = (kt + 1) * BK;
#pragma unroll
            for (int i = 0; i < 4; i++) {
                int cid = tid + i * 256;
                int row = cid >> 3, kq = (cid & 7) << 2;
                cp16(smA[nb] + (row * PADK + kq) * 4, A + (size_t)(m0 + row) * K + k0 + kq, 16);
            }
#pragma unroll
            for (int i = 0; i < 4; i++) {
                int cid = tid + i * 256;
                int row = cid >> 3, kq = (cid & 7) << 2;
                cp16(smB[nb] + (row * PADK + kq) * 4, B + (size_t)(n0 + row) * K + k0 + kq, 16);
            }
            cp_commit();
            cp_wait1();
        } else {
            cp_wait0();
        }
        __syncthreads();

        const float* As_ = As0 + cur * BM * PADK;
        const float* Bs_ = Bs0 + cur * BN * PADK;
#pragma unroll
        for (int ks = 0; ks < 4; ks++) {
            const int kk = ks * 8;
            uint32_t af[4][4], bf[4][2];
#pragma unroll
            for (int mt = 0; mt < 4; mt++) {
                const float* ap = As_ + (warp_m + mt * 16 + g) * PADK + kk;
                af[mt][0] = f2tf32(ap[tig]);
                af[mt][1] = f2tf32(ap[8 * PADK + tig]);
                af[mt][2] = f2tf32(ap[tig + 4]);
                af[mt][3] = f2tf32(ap[8 * PADK + tig + 4]);
            }
#pragma unroll
            for (int nt = 0; nt < 4; nt++) {
                const float* bp = Bs_ + (warp_n + nt * 8 + g) * PADK + kk;
                bf[nt][0] = f2tf32(bp[tig]);
                bf[nt][1] = f2tf32(bp[tig + 4]);
            }
#pragma unroll
            for (int mt = 0; mt < 4; mt++)
#pragma unroll
                for (int nt = 0; nt < 4; nt++)
                    mma_tf32(acc[mt][nt], af[mt], bf[nt]);
        }
        __syncthreads();
    }

    // epilogue
#pragma unroll
    for (int mt = 0; mt < 4; mt++) {
        int r0 = m0 + warp_m + mt * 16 + g;
#pragma unroll
        for (int nt = 0; nt < 4; nt++) {
            int gc = n0 + warp_n + nt * 8 + tig * 2;
            float v0 = acc[mt][nt][0], v1 = acc[mt][nt][1];
            float v2 = acc[mt][nt][2], v3 = acc[mt][nt][3];
            if (addsrc) {
                v0 += addsrc[(size_t)r0 * N + gc];
                v1 += addsrc[(size_t)r0 * N + gc + 1];
                v2 += addsrc[(size_t)(r0 + 8) * N + gc];
                v3 += addsrc[(size_t)(r0 + 8) * N + gc + 1];
            }
            *(float2*)(C + (size_t)r0 * N + gc) = make_float2(v0, v1);
            *(float2*)(C + (size_t)(r0 + 8) * N + gc) = make_float2(v2, v3);
        }
    }
}

// ---------------- TF32 grouped/gathered GEMM for MoE ----------------
// expert e = blockIdx.z; rows = slots [off[e], off[e+1]); A row = gather?gather[slot]:slot
__global__ __launch_bounds__(256) void gemm_tf32_moe(
    const float* __restrict__ A, const int* __restrict__ gather,
    const float* __restrict__ Bbase, size_t strideB,
    float* __restrict__ C, int N, int K, const int* __restrict__ off)
{
    const int e = blockIdx.z;
    const int start = off[e];
    const int cnt = off[e + 1] - start;
    const int m0 = blockIdx.y * BM;
    if (m0 >= cnt) return;
    const int n0 = blockIdx.x * BN;
    const float* B = Bbase + (size_t)e * strideB;

    extern __shared__ float sm[];
    float* As0 = sm;
    float* Bs0 = sm + 2 * BM * PADK;
    __shared__ int rowmap[BM];

    const int tid = threadIdx.x;
    if (tid < BM) {
        int r = m0 + tid;
        int gr = -1;
        if (r < cnt) gr = gather ? gather[start + r] : (start + r);
        rowmap[tid] = gr;
    }
    __syncthreads();

    const int warp = tid >> 5, lane = tid & 31;
    const int g = lane >> 2, tig = lane & 3;
    const int warp_m = (warp & 1) * 64, warp_n = (warp >> 1) * 32;

    float acc[4][4][4];
#pragma unroll
    for (int a = 0; a < 4; a++)
#pragma unroll
        for (int b = 0; b < 4; b++)
#pragma unroll
            for (int c = 0; c < 4; c++) acc[a][b][c] = 0.f;

    const int nk = K / BK;
    uint32_t smA[2], smB[2];
    smA[0] = (uint32_t)__cvta_generic_to_shared(As0);
    smA[1] = (uint32_t)__cvta_generic_to_shared(As0 + BM * PADK);
    smB[0] = (uint32_t)__cvta_generic_to_shared(Bs0);
    smB[1] = (uint32_t)__cvta_generic_to_shared(Bs0 + BN * PADK);

    {
#pragma unroll
        for (int i = 0; i < 4; i++) {
            int cid = tid + i * 256;
            int row = cid >> 3, kq = (cid & 7) << 2;
            int gr = rowmap[row];
            const float* src = (gr >= 0) ? (A + (size_t)gr * K + kq) : A;
            cp16(smA[0] + (row * PADK + kq) * 4, src, (gr >= 0) ? 16 : 0);
        }
#pragma unroll
        for (int i = 0; i < 4; i++) {
            int cid = tid + i * 256;
            int row = cid >> 3, kq = (cid & 7) << 2;
            cp16(smB[0] + (row * PADK + kq) * 4, B + (size_t)(n0 + row) * K + kq, 16);
        }
        cp_commit();
    }

    for (int kt = 0; kt < nk; kt++) {
        int cur = kt & 1;
        if (kt + 1 < nk) {
            int nb = cur ^ 1;
            int k0 = (kt + 1) * BK;
#pragma unroll
            for (int i = 0; i < 4; i++) {
                int cid = tid + i * 256;
                int row = cid >> 3, kq = (cid & 7) << 2;
                int gr = rowmap[row];
                const float* src = (gr >= 0) ? (A + (size_t)gr * K + k0 + kq) : A;
                cp16(smA[nb] + (row * PADK + kq) * 4, src, (gr >= 0) ? 16 : 0);
            }
#pragma unroll
            for (int i = 0; i < 4; i++) {
                int cid = tid + i * 256;
                int row = cid >> 3, kq = (cid & 7) << 2;
                cp16(smB[nb] + (row * PADK + kq) * 4, B + (size_t)(n0 + row) * K + k0 + kq, 16);
            }
            cp_commit();
            cp_wait1();
        } else {
            cp_wait0();
        }
        __syncthreads();

        const float* As_ = As0 + cur * BM * PADK;
        const float* Bs_ = Bs0 + cur * BN * PADK;
#pragma unroll
        for (int ks = 0; ks < 4; ks++) {
            const int kk = ks * 8;
            uint32_t af[4][4], bf[4][2];
#pragma unroll
            for (int mt = 0; mt < 4; mt++) {
                const float* ap = As_ + (warp_m + mt * 16 + g) * PADK + kk;
                af[mt][0] = f2tf32(ap[tig]);
                af[mt][1] = f2tf32(ap[8 * PADK + tig]);
                af[mt][2] = f2tf32(ap[tig + 4]);
                af[mt][3] = f2tf32(ap[8 * PADK + tig + 4]);
            }
#pragma unroll
            for (int nt = 0; nt < 4; nt++) {
                const float* bp = Bs_ + (warp_n + nt * 8 + g) * PADK + kk;
                bf[nt][0] = f2tf32(bp[tig]);
                bf[nt][1] = f2tf32(bp[tig + 4]);
            }
#pragma unroll
            for (int mt = 0; mt < 4; mt++)
#pragma unroll
                for (int nt = 0; nt < 4; nt++)
                    mma_tf32(acc[mt][nt], af[mt], bf[nt]);
        }
        __syncthreads();
    }

#pragma unroll
    for (int mt = 0; mt < 4; mt++) {
        int r = warp_m + mt * 16 + g;   // relative to m0
#pragma unroll
        for (int nt = 0; nt < 4; nt++) {
            int gc = n0 + warp_n + nt * 8 + tig * 2;
            if (m0 + r < cnt)
                *(float2*)(C + (size_t)(start + m0 + r) * N + gc) =
                    make_float2(acc[mt][nt][0], acc[mt][nt][1]);
            if (m0 + r + 8 < cnt)
                *(float2*)(C + (size_t)(start + m0 + r + 8) * N + gc) =
                    make_float2(acc[mt][nt][2], acc[mt][nt][3]);
        }
    }
}

// ---------------- RMSNorm ----------------
__global__ void rmsnorm_kernel(const float* in, const float* w, float* out, int D) {
    int t = blockIdx.x;
    const float* row = in + (size_t)t * D;
    float ss = 0.f;
    for (int i = threadIdx.x; i < D; i += blockDim.x) { float v = row[i]; ss += v * v; }
    __shared__ float sred[32];
    for (int o = 16; o > 0; o >>= 1) ss += __shfl_down_sync(0xffffffffu, ss, o);
    int lane = threadIdx.x & 31, warp = threadIdx.x >> 5;
    if (lane == 0) sred[warp] = ss;
    __syncthreads();
    int nw = blockDim.x >> 5;
    if (threadIdx.x == 0) {
        float tot = 0.f;
        for (int i = 0; i < nw; i++) tot += sred[i];
        sred[0] = 1.0f / sqrtf(tot / (float)D + 1e-6f);
    }
    __syncthreads();
    float scale = sred[0];
    for (int i = threadIdx.x; i < D; i += blockDim.x)
        out[(size_t)t * D + i] = row[i] * scale * w[i];
}

// ---------------- RoPE ----------------
__global__ void rope_kernel() {
    int idx = blockIdx.x * blockDim.x + threadIdx.x;
    int total = SEQ * NHEAD * (ROPED / 2);
    if (idx >= total) return;
    int i = idx & 31;
    int h = (idx >> 5) & (NHEAD - 1);
    int t = idx >> 9;
    float inv_freq = powf(10000.0f, -(float)(2 * i) / (float)ROPED);
    float f = (float)t * inv_freq;
    float c = cosf(f), s = sinf(f);
    float* qp = g_q + ((size_t)t * NHEAD + h) * DQK + NOPE;
    float x1 = qp[i], x2 = qp[i + 32];
    qp[i] = x1 * c - x2 * s;
    qp[i + 32] = x2 * c + x1 * s;
    float* kp = g_kv + ((size_t)t * NHEAD + h) * (DQK + DV) + NOPE;
    x1 = kp[i]; x2 = kp[i + 32];
    kp[i] = x1 * c - x2 * s;
    kp[i + 32] = x2 * c + x1 * s;
}

// ---------------- Flash attention (SIMT, 1 thread/query) ----------------
#define ATTN_SMEM ((128*193 + 64*192 + 64*128) * 4)
__global__ __launch_bounds__(128) void attn_kernel() {
    extern __shared__ float smf[];
    float* Qs = smf;
    float* Ks = smf + 128 * 193;
    float* Vs = Ks + 64 * 192;

    int h = blockIdx.y;
    int q0 = blockIdx.x * 128;
    int tid = threadIdx.x;
    int qi = q0 + tid;

    for (int idx = tid; idx < 128 * 192; idx += 128) {
        int r = idx / 192, d = idx - r * 192;
        Qs[r * 193 + d] = g_q[((size_t)(q0 + r) * NHEAD + h) * DQK + d];
    }

    float acc[128];
#pragma unroll
    for (int d = 0; d < 128; d++) acc[d] = 0.f;
    float mval = -1e30f, lsum = 0.f;
    const float scale = 0.07216878364870323f;

    int ntiles = blockIdx.x * 2 + 2;
    for (int tile = 0; tile < ntiles; tile++) {
        int t0 = tile * 64;
        __syncthreads();
        for (int idx = tid; idx < 64 * 192; idx += 128) {
            int r = idx / 192, d = idx - r * 192;
            Ks[r * 192 + d] = g_kv[((size_t)(t0 + r) * NHEAD + h) * (DQK + DV) + d];
        }
        for (int idx = tid; idx < 64 * 128; idx += 128) {
            int r = idx >> 7, d = idx & 127;
            Vs[r * 128 + d] = g_kv[((size_t)(t0 + r) * NHEAD + h) * (DQK + DV) + DQK + d];
        }
        __syncthreads();

        const float* qrow = &Qs[tid * 193];
        for (int j = 0; j < 64; j++) {
            int kj = t0 + j;
            if (kj > qi) break;
            const float* krow = &Ks[j * 192];
            float s = 0.f;
#pragma unroll 8
            for (int d = 0; d < 192; d++) s += qrow[d] * krow[d];
            s *= scale;
            const float* vrow = &Vs[j * 128];
            if (s <= mval) {
                float p = __expf(s - mval);
                lsum += p;
#pragma unroll
                for (int d = 0; d < 128; d++) acc[d] += p * vrow[d];
            } else {
                float cfac = __expf(mval - s);
                lsum = lsum * cfac + 1.f;
#pragma unroll
                for (int d = 0; d < 128; d++) acc[d] = acc[d] * cfac + vrow[d];
                mval = s;
            }
        }
    }
    float inv = 1.0f / lsum;
#pragma unroll
    for (int d = 0; d < 128; d++)
        g_ctx[(size_t)qi * (NHEAD * DV) + h * DV + d] = acc[d] * inv;
}

// ---------------- Router ----------------
__global__ void router_kernel(const float* __restrict__ rw, const float* __restrict__ rb) {
    int t = blockIdx.x;
    float part[NEXP];
#pragma unroll
    for (int e = 0; e < NEXP; e++) part[e] = 0.f;
    for (int hh = threadIdx.x; hh < HDIM; hh += 128) {
        float xv = g_h2[(size_t)t * HDIM + hh];
#pragma unroll
        for (int e = 0; e < NEXP; e++) part[e] += xv * rw[(size_t)e * HDIM + hh];
    }
    __shared__ float sred[4][NEXP];
#pragma unroll
    for (int e = 0; e < NEXP; e++)
        for (int o = 16; o > 0; o >>= 1) part[e] += __shfl_down_sync(0xffffffffu, part[e], o);
    int lane = threadIdx.x & 31, warp = threadIdx.x >> 5;
    if (lane == 0)
#pragma unroll
        for (int e = 0; e < NEXP; e++) sred[warp][e] = part[e];
    __syncthreads();
    if (threadIdx.x < NEXP) {
        int e = threadIdx.x;
        g_logits[t * NEXP + e] = sred[0][e] + sred[1][e] + sred[2][e] + sred[3][e] + rb[e];
    }
}

__global__ void zero_kernel() {
    if (threadIdx.x < NEXP) { g_cnt[threadIdx.x] = 0; g_fill[threadIdx.x] = 0; }
}

__global__ void topk_kernel() {
    int t = blockIdx.x * blockDim.x + threadIdx.x;
    if (t >= SEQ) return;
    float p[NEXP];
#pragma unroll
    for (int e = 0; e < NEXP; e++) p[e] = 1.0f / (1.0f + expf(-g_logits[t * NEXP + e]));
    float vals[TOPK]; int ids[TOPK];
    float sum = 0.f;
#pragma unroll
    for (int k = 0; k < TOPK; k++) {
        float best = -1e30f; int bi = 0;
#pragma unroll
        for (int e = 0; e < NEXP; e++)
            if (p[e] > best) { best = p[e]; bi = e; }
        vals[k] = best; ids[k] = bi; p[bi] = -1e30f; sum += best;
    }
    float w = 2.5f / (sum + 1e-9f);
#pragma unroll
    for (int k = 0; k < TOPK; k++) {
        g_wtop[t * TOPK + k] = vals[k] * w;
        g_topi[t * TOPK + k] = ids[k];
        atomicAdd(&g_cnt[ids[k]], 1);
    }
}

__global__ void offsets_kernel() {
    if (threadIdx.x == 0) {
        g_off[0] = 0;
        for (int e = 0; e < NEXP; e++) g_off[e + 1] = g_off[e] + g_cnt[e];
    }
}

__global__ void scatter_kernel() {
    int t = blockIdx.x * blockDim.x + threadIdx.x;
    if (t >= SEQ) return;
#pragma unroll
    for (int k = 0; k < TOPK; k++) {
        int e = g_topi[t * TOPK + k];
        int pos = atomicAdd(&g_fill[e], 1);
        int slot = g_off[e] + pos;
        g_slot[t * TOPK + k] = slot;
        g_tok[slot] = t;
    }
}

// ---------------- SiLU(a)*b ----------------
__global__ void act_kernel(float* a, const float* b, size_t n) {
    size_t i = (size_t)blockIdx.x * blockDim.x + threadIdx.x;
    if (i >= n) return;
    float g = a[i];
    float sg = g / (1.0f + expf(-g));
    a[i] = sg * b[i];
}

// ---------------- Final combine ----------------
__global__ void combine_kernel(float* out) {
    int t = blockIdx.x;
    float w[TOPK]; int s[TOPK];
#pragma unroll
    for (int k = 0; k < TOPK; k++) { w[k] = g_wtop[t * TOPK + k]; s[k] = g_slot[t * TOPK + k]; }
    for (int hh = threadIdx.x; hh < HDIM; hh += 256) {
        float v = g_xmid[(size_t)t * HDIM + hh] + g_shr[(size_t)t * HDIM + hh];
#pragma unroll
        for (int k = 0; k < TOPK; k++)
            v += w[k] * g_down[(size_t)s[k] * HDIM + hh];
        out[(size_t)t * HDIM + hh] = v;
    }
}

// ---------------- host ----------------
static float* symf(const void* sym) { void* p = nullptr; cudaGetSymbolAddress(&p, sym); return (float*)p; }
static int*   symi(const void* sym) { void* p = nullptr; cudaGetSymbolAddress(&p, sym); return (int*)p; }

extern "C" void kernel_launch(void* const* d_in, const int* in_sizes, int n_in,
                              void* d_out, int out_size)
{
    const float* x      = (const float*)d_in[0];
    const float* ln1_w  = (const float*)d_in[2];
    const float* ln2_w  = (const float*)d_in[3];
    const float* q_a_w  = (const float*)d_in[4];
    const float* q_a_ln = (const float*)d_in[5];
    const float* q_b_w  = (const float*)d_in[6];
    const float* kv_a_w = (const float*)d_in[7];
    const float* kv_a_ln= (const float*)d_in[8];
    const float* kv_b_w = (const float*)d_in[9];
    const float* o_w    = (const float*)d_in[10];
    const float* rout_w = (const float*)d_in[11];
    const float* rout_b = (const float*)d_in[12];
    const float* gate_w = (const float*)d_in[13];
    const float* up_w   = (const float*)d_in[14];
    const float* down_w = (const float*)d_in[15];
    const float* sg_w   = (const float*)d_in[16];
    const float* su_w   = (const float*)d_in[17];
    const float* sd_w   = (const float*)d_in[18];
    float* out = (float*)d_out;

    float* h1   = symf(g_h1);
    float* qa   = symf(g_qa);
    float* kva  = symf(g_kva);
    float* q    = symf(g_q);
    float* kv   = symf(g_kv);
    float* ctx  = symf(g_ctx);
    float* xmid = symf(g_xmid);
    float* h2   = symf(g_h2);
    float* gate = symf(g_gate);
    float* up   = symf(g_up);
    float* down = symf(g_down);
    float* sg   = symf(g_sg);
    float* su   = symf(g_su);
    float* shr  = symf(g_shr);
    int*   tok  = symi(g_tok);
    int*   off  = symi(g_off);

    cudaFuncSetAttribute(gemm_tf32, cudaFuncAttributeMaxDynamicSharedMemorySize, GSMEM);
    cudaFuncSetAttribute(gemm_tf32_moe, cudaFuncAttributeMaxDynamicSharedMemorySize, GSMEM);
    cudaFuncSetAttribute(attn_kernel, cudaFuncAttributeMaxDynamicSharedMemorySize, ATTN_SMEM);

    // ---- attention branch ----
    rmsnorm_kernel<<<SEQ, 256>>>(x, ln1_w, h1, HDIM);
    gemm_tf32<<<dim3(QRNK / BN, SEQ / BM), 256, GSMEM>>>(h1, q_a_w, qa, nullptr, SEQ, QRNK, HDIM);
    rmsnorm_kernel<<<SEQ, 256>>>(qa, q_a_ln, qa, QRNK);
    gemm_tf32<<<dim3(KVRNK / BN, SEQ / BM), 256, GSMEM>>>(h1, kv_a_w, kva, nullptr, SEQ, KVRNK, HDIM);
    rmsnorm_kernel<<<SEQ, 256>>>(kva, kv_a_ln, kva, KVRNK);
    gemm_tf32<<<dim3(NHEAD * DQK / BN, SEQ / BM), 256, GSMEM>>>(qa, q_b_w, q, nullptr, SEQ, NHEAD * DQK, QRNK);
    gemm_tf32<<<dim3(NHEAD * (DQK + DV) / BN, SEQ / BM), 256, GSMEM>>>(kva, kv_b_w, kv, nullptr, SEQ, NHEAD * (DQK + DV), KVRNK);
    rope_kernel<<<(SEQ * NHEAD * (ROPED / 2) + 255) / 256, 256>>>();
    attn_kernel<<<dim3(SEQ / 128, NHEAD), 128, ATTN_SMEM>>>();
    gemm_tf32<<<dim3(HDIM / BN, SEQ / BM), 256, GSMEM>>>(ctx, o_w, xmid, x, SEQ, HDIM, NHEAD * DV);

    // ---- MoE branch ----
    rmsnorm_kernel<<<SEQ, 256>>>(xmid, ln2_w, h2, HDIM);
    router_kernel<<<SEQ, 128>>>(rout_w, rout_b);
    zero_kernel<<<1, 32>>>();
    topk_kernel<<<SEQ / 256, 256>>>();
    offsets_kernel<<<1, 1>>>();
    scatter_kernel<<<SEQ / 256, 256>>>();

    gemm_tf32_moe<<<dim3(MINT / BN, SEQ / BM, NEXP), 256, GSMEM>>>(h2, tok, gate_w, (size_t)MINT * HDIM, gate, MINT, HDIM, off);
    gemm_tf32_moe<<<dim3(MINT / BN, SEQ / BM, NEXP), 256, GSMEM>>>(h2, tok, up_w, (size_t)MINT * HDIM, up, MINT, HDIM, off);
    act_kernel<<<(unsigned)(((size_t)NSLOT * MINT + 255) / 256), 256>>>(gate, up, (size_t)NSLOT * MINT);
    gemm_tf32_moe<<<dim3(HDIM / BN, SEQ / BM, NEXP), 256, GSMEM>>>(gate, nullptr, down_w, (size_t)HDIM * MINT, down, HDIM, MINT, off);

    // shared expert
    gemm_tf32<<<dim3(MINT / BN, SEQ / BM), 256, GSMEM>>>(h2, sg_w, sg, nullptr, SEQ, MINT, HDIM);
    gemm_tf32<<<dim3(MINT / BN, SEQ / BM), 256, GSMEM>>>(h2, su_w, su, nullptr, SEQ, MINT, HDIM);
    act_kernel<<<(unsigned)(((size_t)SEQ * MINT + 255) / 256), 256>>>(sg, su, (size_t)SEQ * MINT);
    gemm_tf32<<<dim3(HDIM / BN, SEQ / BM), 256, GSMEM>>>(sg, sd_w, shr, nullptr, SEQ, HDIM, MINT);

    combine_kernel<<<SEQ, 256>>>(out);
}

// round 3
// speedup vs baseline: 4.8486x; 3.0767x over previous
#include <cuda_runtime.h>
#include <math.h>
#include <stdint.h>

// ---------------- problem constants ----------------
#define SEQ   2048
#define HDIM  2048
#define NHEAD 16
#define DQK   192
#define DV    128
#define NOPE  128
#define ROPED 64
#define QRNK  768
#define KVRNK 512
#define NEXP  16
#define TOPK  4
#define MINT  1024
#define NSLOT (SEQ*TOPK)

// GEMM tiling
#define BM 128
#define BN 128
#define BK 32
#define PADK 36
#define GSMEM (2*(BM+BN)*PADK*4)

// attention tiling
#define AQ 128
#define AK 64
#define QSTR 196
#define KSTR 196
#define VSTR 136
#define PSTR 68
#define ATTN_SMEM ((AQ*QSTR + AK*KSTR + AK*VSTR + AQ*PSTR)*4)

// ---------------- scratch ----------------
__device__ float g_h1[SEQ*HDIM];
__device__ float g_qa[SEQ*QRNK];
__device__ float g_kva[SEQ*KVRNK];
__device__ float g_q[SEQ*NHEAD*DQK];
__device__ float g_kv[SEQ*NHEAD*(DQK+DV)];
__device__ float g_ctx[SEQ*NHEAD*DV];
__device__ float g_xmid[SEQ*HDIM];
__device__ float g_h2[SEQ*HDIM];
__device__ float g_logits[SEQ*NEXP];
__device__ float g_wtop[SEQ*TOPK];
__device__ int   g_topi[SEQ*TOPK];
__device__ int   g_slot[SEQ*TOPK];
__device__ int   g_cnt[NEXP];
__device__ int   g_off[NEXP+1];
__device__ int   g_fill[NEXP];
__device__ int   g_tok[NSLOT];
__device__ float g_gate[(size_t)NSLOT*MINT];
__device__ float g_up[(size_t)NSLOT*MINT];
__device__ float g_down[(size_t)NSLOT*HDIM];
__device__ float g_sg[SEQ*MINT];
__device__ float g_su[SEQ*MINT];
__device__ float g_shr[SEQ*HDIM];

// ---------------- helpers ----------------
__device__ __forceinline__ uint32_t f2tf32(float f) {
    uint32_t r;
    asm("cvt.rna.tf32.f32 %0, %1;" : "=r"(r) : "f"(f));
    return r;
}
__device__ __forceinline__ void cp16(uint32_t dst, const void* src, int szbytes) {
    asm volatile("cp.async.cg.shared.global [%0], [%1], 16, %2;\n"
                 :: "r"(dst), "l"(src), "r"(szbytes));
}
__device__ __forceinline__ void cp_commit() { asm volatile("cp.async.commit_group;\n"); }
__device__ __forceinline__ void cp_wait0()  { asm volatile("cp.async.wait_group 0;\n"); }
__device__ __forceinline__ void cp_wait1()  { asm volatile("cp.async.wait_group 1;\n"); }

__device__ __forceinline__ void mma_tf32(float* c, const uint32_t* a, const uint32_t* b) {
    asm volatile(
        "mma.sync.aligned.m16n8k8.row.col.f32.tf32.tf32.f32 "
        "{%0,%1,%2,%3}, {%4,%5,%6,%7}, {%8,%9}, {%0,%1,%2,%3};\n"
        : "+f"(c[0]), "+f"(c[1]), "+f"(c[2]), "+f"(c[3])
        : "r"(a[0]), "r"(a[1]), "r"(a[2]), "r"(a[3]), "r"(b[0]), "r"(b[1]));
}

// ---------------- TF32 tensor-core GEMM: C[M,N] = A[M,K] @ B[N,K]^T (+ addsrc) ----------------
__global__ __launch_bounds__(256, 2) void gemm_tf32(
    const float* __restrict__ A, const float* __restrict__ B, float* __restrict__ C,
    const float* __restrict__ addsrc, int M, int N, int K)
{
    extern __shared__ float sm[];
    float* As0 = sm;
    float* Bs0 = sm + 2 * BM * PADK;

    const int tid = threadIdx.x;
    const int warp = tid >> 5, lane = tid & 31;
    const int g = lane >> 2, tig = lane & 3;
    const int warp_m = (warp & 1) * 64, warp_n = (warp >> 1) * 32;
    const int m0 = blockIdx.y * BM, n0 = blockIdx.x * BN;

    float acc[4][4][4];
#pragma unroll
    for (int a = 0; a < 4; a++)
#pragma unroll
        for (int b = 0; b < 4; b++)
#pragma unroll
            for (int c = 0; c < 4; c++) acc[a][b][c] = 0.f;

    const int nk = K / BK;
    uint32_t smA[2], smB[2];
    smA[0] = (uint32_t)__cvta_generic_to_shared(As0);
    smA[1] = (uint32_t)__cvta_generic_to_shared(As0 + BM * PADK);
    smB[0] = (uint32_t)__cvta_generic_to_shared(Bs0);
    smB[1] = (uint32_t)__cvta_generic_to_shared(Bs0 + BN * PADK);

    {
#pragma unroll
        for (int i = 0; i < 4; i++) {
            int cid = tid + i * 256;
            int row = cid >> 3, kq = (cid & 7) << 2;
            cp16(smA[0] + (row * PADK + kq) * 4, A + (size_t)(m0 + row) * K + kq, 16);
        }
#pragma unroll
        for (int i = 0; i < 4; i++) {
            int cid = tid + i * 256;
            int row = cid >> 3, kq = (cid & 7) << 2;
            cp16(smB[0] + (row * PADK + kq) * 4, B + (size_t)(n0 + row) * K + kq, 16);
        }
        cp_commit();
    }

    for (int kt = 0; kt < nk; kt++) {
        int cur = kt & 1;
        if (kt + 1 < nk) {
            int nb = cur ^ 1;
            int k0 = (kt + 1) * BK;
#pragma unroll
            for (int i = 0; i < 4; i++) {
                int cid = tid + i * 256;
                int row = cid >> 3, kq = (cid & 7) << 2;
                cp16(smA[nb] + (row * PADK + kq) * 4, A + (size_t)(m0 + row) * K + k0 + kq, 16);
            }
#pragma unroll
            for (int i = 0; i < 4; i++) {
                int cid = tid + i * 256;
                int row = cid >> 3, kq = (cid & 7) << 2;
                cp16(smB[nb] + (row * PADK + kq) * 4, B + (size_t)(n0 + row) * K + k0 + kq, 16);
            }
            cp_commit();
            cp_wait1();
        } else {
            cp_wait0();
        }
        __syncthreads();

        const float* As_ = As0 + cur * BM * PADK;
        const float* Bs_ = Bs0 + cur * BN * PADK;
#pragma unroll
        for (int ks = 0; ks < 4; ks++) {
            const int kk = ks * 8;
            uint32_t af[4][4], bf[4][2];
#pragma unroll
            for (int mt = 0; mt < 4; mt++) {
                const float* ap = As_ + (warp_m + mt * 16 + g) * PADK + kk;
                af[mt][0] = f2tf32(ap[tig]);
                af[mt][1] = f2tf32(ap[8 * PADK + tig]);
                af[mt][2] = f2tf32(ap[tig + 4]);
                af[mt][3] = f2tf32(ap[8 * PADK + tig + 4]);
            }
#pragma unroll
            for (int nt = 0; nt < 4; nt++) {
                const float* bp = Bs_ + (warp_n + nt * 8 + g) * PADK + kk;
                bf[nt][0] = f2tf32(bp[tig]);
                bf[nt][1] = f2tf32(bp[tig + 4]);
            }
#pragma unroll
            for (int mt = 0; mt < 4; mt++)
#pragma unroll
                for (int nt = 0; nt < 4; nt++)
                    mma_tf32(acc[mt][nt], af[mt], bf[nt]);
        }
        __syncthreads();
    }

#pragma unroll
    for (int mt = 0; mt < 4; mt++) {
        int r0 = m0 + warp_m + mt * 16 + g;
#pragma unroll
        for (int nt = 0; nt < 4; nt++) {
            int gc = n0 + warp_n + nt * 8 + tig * 2;
            float v0 = acc[mt][nt][0], v1 = acc[mt][nt][1];
            float v2 = acc[mt][nt][2], v3 = acc[mt][nt][3];
            if (addsrc) {
                v0 += addsrc[(size_t)r0 * N + gc];
                v1 += addsrc[(size_t)r0 * N + gc + 1];
                v2 += addsrc[(size_t)(r0 + 8) * N + gc];
                v3 += addsrc[(size_t)(r0 + 8) * N + gc + 1];
            }
            *(float2*)(C + (size_t)r0 * N + gc) = make_float2(v0, v1);
            *(float2*)(C + (size_t)(r0 + 8) * N + gc) = make_float2(v2, v3);
        }
    }
}

// ---------------- TF32 grouped/gathered GEMM for MoE ----------------
__global__ __launch_bounds__(256, 2) void gemm_tf32_moe(
    const float* __restrict__ A, const int* __restrict__ gather,
    const float* __restrict__ Bbase, size_t strideB,
    float* __restrict__ C, int N, int K, const int* __restrict__ off)
{
    const int e = blockIdx.z;
    const int start = off[e];
    const int cnt = off[e + 1] - start;
    const int m0 = blockIdx.y * BM;
    if (m0 >= cnt) return;
    const int n0 = blockIdx.x * BN;
    const float* B = Bbase + (size_t)e * strideB;

    extern __shared__ float sm[];
    float* As0 = sm;
    float* Bs0 = sm + 2 * BM * PADK;
    __shared__ int rowmap[BM];

    const int tid = threadIdx.x;
    if (tid < BM) {
        int r = m0 + tid;
        int gr = -1;
        if (r < cnt) gr = gather ? gather[start + r] : (start + r);
        rowmap[tid] = gr;
    }
    __syncthreads();

    const int warp = tid >> 5, lane = tid & 31;
    const int g = lane >> 2, tig = lane & 3;
    const int warp_m = (warp & 1) * 64, warp_n = (warp >> 1) * 32;

    float acc[4][4][4];
#pragma unroll
    for (int a = 0; a < 4; a++)
#pragma unroll
        for (int b = 0; b < 4; b++)
#pragma unroll
            for (int c = 0; c < 4; c++) acc[a][b][c] = 0.f;

    const int nk = K / BK;
    uint32_t smA[2], smB[2];
    smA[0] = (uint32_t)__cvta_generic_to_shared(As0);
    smA[1] = (uint32_t)__cvta_generic_to_shared(As0 + BM * PADK);
    smB[0] = (uint32_t)__cvta_generic_to_shared(Bs0);
    smB[1] = (uint32_t)__cvta_generic_to_shared(Bs0 + BN * PADK);

    {
#pragma unroll
        for (int i = 0; i < 4; i++) {
            int cid = tid + i * 256;
            int row = cid >> 3, kq = (cid & 7) << 2;
            int gr = rowmap[row];
            const float* src = (gr >= 0) ? (A + (size_t)gr * K + kq) : A;
            cp16(smA[0] + (row * PADK + kq) * 4, src, (gr >= 0) ? 16 : 0);
        }
#pragma unroll
        for (int i = 0; i < 4; i++) {
            int cid = tid + i * 256;
            int row = cid >> 3, kq = (cid & 7) << 2;
            cp16(smB[0] + (row * PADK + kq) * 4, B + (size_t)(n0 + row) * K + kq, 16);
        }
        cp_commit();
    }

    for (int kt = 0; kt < nk; kt++) {
        int cur = kt & 1;
        if (kt + 1 < nk) {
            int nb = cur ^ 1;
            int k0 = (kt + 1) * BK;
#pragma unroll
            for (int i = 0; i < 4; i++) {
                int cid = tid + i * 256;
                int row = cid >> 3, kq = (cid & 7) << 2;
                int gr = rowmap[row];
                const float* src = (gr >= 0) ? (A + (size_t)gr * K + k0 + kq) : A;
                cp16(smA[nb] + (row * PADK + kq) * 4, src, (gr >= 0) ? 16 : 0);
            }
#pragma unroll
            for (int i = 0; i < 4; i++) {
                int cid = tid + i * 256;
                int row = cid >> 3, kq = (cid & 7) << 2;
                cp16(smB[nb] + (row * PADK + kq) * 4, B + (size_t)(n0 + row) * K + k0 + kq, 16);
            }
            cp_commit();
            cp_wait1();
        } else {
            cp_wait0();
        }
        __syncthreads();

        const float* As_ = As0 + cur * BM * PADK;
        const float* Bs_ = Bs0 + cur * BN * PADK;
#pragma unroll
        for (int ks = 0; ks < 4; ks++) {
            const int kk = ks * 8;
            uint32_t af[4][4], bf[4][2];
#pragma unroll
            for (int mt = 0; mt < 4; mt++) {
                const float* ap = As_ + (warp_m + mt * 16 + g) * PADK + kk;
                af[mt][0] = f2tf32(ap[tig]);
                af[mt][1] = f2tf32(ap[8 * PADK + tig]);
                af[mt][2] = f2tf32(ap[tig + 4]);
                af[mt][3] = f2tf32(ap[8 * PADK + tig + 4]);
            }
#pragma unroll
            for (int nt = 0; nt < 4; nt++) {
                const float* bp = Bs_ + (warp_n + nt * 8 + g) * PADK + kk;
                bf[nt][0] = f2tf32(bp[tig]);
                bf[nt][1] = f2tf32(bp[tig + 4]);
            }
#pragma unroll
            for (int mt = 0; mt < 4; mt++)
#pragma unroll
                for (int nt = 0; nt < 4; nt++)
                    mma_tf32(acc[mt][nt], af[mt], bf[nt]);
        }
        __syncthreads();
    }

#pragma unroll
    for (int mt = 0; mt < 4; mt++) {
        int r = warp_m + mt * 16 + g;
#pragma unroll
        for (int nt = 0; nt < 4; nt++) {
            int gc = n0 + warp_n + nt * 8 + tig * 2;
            if (m0 + r < cnt)
                *(float2*)(C + (size_t)(start + m0 + r) * N + gc) =
                    make_float2(acc[mt][nt][0], acc[mt][nt][1]);
            if (m0 + r + 8 < cnt)
                *(float2*)(C + (size_t)(start + m0 + r + 8) * N + gc) =
                    make_float2(acc[mt][nt][2], acc[mt][nt][3]);
        }
    }
}

// ---------------- Tensor-core flash attention ----------------
// block: 128 queries x 1 head, 8 warps (16 q-rows each), K/V tiles of 64.
__global__ __launch_bounds__(256) void attn_mma_kernel() {
    extern __shared__ float smf[];
    float* Qs = smf;                    // [AQ][QSTR]
    float* Ks = Qs + AQ * QSTR;         // [AK][KSTR]
    float* Vs = Ks + AK * KSTR;         // [AK][VSTR]
    float* Ps = Vs + AK * VSTR;         // [AQ][PSTR]

    const int h = blockIdx.y;
    const int qb = gridDim.x - 1 - blockIdx.x;  // longest blocks first
    const int q0 = qb * AQ;
    const int tid = threadIdx.x;
    const int warp = tid >> 5, lane = tid & 31;
    const int g = lane >> 2, tig = lane & 3;
    const int row0 = warp * 16 + g;
    const int qi0 = q0 + row0, qi1 = qi0 + 8;

    // load Q tile
#pragma unroll
    for (int i = 0; i < 24; i++) {
        int idx = tid + i * 256;
        int r = idx / 48, c = (idx % 48) * 4;
        *(float4*)(Qs + r * QSTR + c) =
            *(const float4*)(g_q + ((size_t)(q0 + r) * NHEAD + h) * DQK + c);
    }

    float acc[16][4];
#pragma unroll
    for (int n = 0; n < 16; n++)
#pragma unroll
        for (int c = 0; c < 4; c++) acc[n][c] = 0.f;
    float m0 = -1e30f, m1 = -1e30f, l0 = 0.f, l1 = 0.f;
    const float scale = 0.07216878364870323f; // 1/sqrt(192)

    const int ntiles = qb * 2 + 2;
    for (int tile = 0; tile < ntiles; tile++) {
        int t0 = tile * AK;
        __syncthreads();
        // load K,V tiles
#pragma unroll
        for (int i = 0; i < 12; i++) {
            int idx = tid + i * 256;
            int r = idx / 48, c = (idx % 48) * 4;
            *(float4*)(Ks + r * KSTR + c) =
                *(const float4*)(g_kv + ((size_t)(t0 + r) * NHEAD + h) * (DQK + DV) + c);
        }
#pragma unroll
        for (int i = 0; i < 8; i++) {
            int idx = tid + i * 256;
            int r = idx >> 5, c = (idx & 31) * 4;
            *(float4*)(Vs + r * VSTR + c) =
                *(const float4*)(g_kv + ((size_t)(t0 + r) * NHEAD + h) * (DQK + DV) + DQK + c);
        }
        __syncthreads();

        // S = Q @ K^T
        float s[8][4];
#pragma unroll
        for (int n = 0; n < 8; n++)
#pragma unroll
            for (int c = 0; c < 4; c++) s[n][c] = 0.f;
#pragma unroll
        for (int ks = 0; ks < 24; ks++) {
            const int kk = ks * 8;
            const float* ap = Qs + row0 * QSTR + kk;
            uint32_t af[4];
            af[0] = f2tf32(ap[tig]);
            af[1] = f2tf32(ap[8 * QSTR + tig]);
            af[2] = f2tf32(ap[tig + 4]);
            af[3] = f2tf32(ap[8 * QSTR + tig + 4]);
#pragma unroll
            for (int nt = 0; nt < 8; nt++) {
                const float* bp = Ks + (nt * 8 + g) * KSTR + kk;
                uint32_t bf[2];
                bf[0] = f2tf32(bp[tig]);
                bf[1] = f2tf32(bp[tig + 4]);
                mma_tf32(s[nt], af, bf);
            }
        }

        // scale + causal mask
        const bool domask = (t0 + AK - 1 > q0);
#pragma unroll
        for (int nt = 0; nt < 8; nt++) {
#pragma unroll
            for (int c = 0; c < 4; c++) s[nt][c] *= scale;
            if (domask) {
                int kj = t0 + nt * 8 + tig * 2;
                if (kj > qi0)     s[nt][0] = -1e30f;
                if (kj + 1 > qi0) s[nt][1] = -1e30f;
                if (kj > qi1)     s[nt][2] = -1e30f;
                if (kj + 1 > qi1) s[nt][3] = -1e30f;
            }
        }

        // row max (quad reduce)
        float mx0 = -1e30f, mx1 = -1e30f;
#pragma unroll
        for (int nt = 0; nt < 8; nt++) {
            mx0 = fmaxf(mx0, fmaxf(s[nt][0], s[nt][1]));
            mx1 = fmaxf(mx1, fmaxf(s[nt][2], s[nt][3]));
        }
        mx0 = fmaxf(mx0, __shfl_xor_sync(0xffffffffu, mx0, 1));
        mx0 = fmaxf(mx0, __shfl_xor_sync(0xffffffffu, mx0, 2));
        mx1 = fmaxf(mx1, __shfl_xor_sync(0xffffffffu, mx1, 1));
        mx1 = fmaxf(mx1, __shfl_xor_sync(0xffffffffu, mx1, 2));

        float mn0 = fmaxf(m0, mx0), mn1 = fmaxf(m1, mx1);
        float cf0 = __expf(m0 - mn0), cf1 = __expf(m1 - mn1);
        m0 = mn0; m1 = mn1;

        float sum0 = 0.f, sum1 = 0.f;
#pragma unroll
        for (int nt = 0; nt < 8; nt++) {
            float p0 = __expf(s[nt][0] - m0);
            float p1 = __expf(s[nt][1] - m0);
            float p2 = __expf(s[nt][2] - m1);
            float p3 = __expf(s[nt][3] - m1);
            sum0 += p0 + p1; sum1 += p2 + p3;
            *(float2*)(Ps + row0 * PSTR + nt * 8 + tig * 2) = make_float2(p0, p1);
            *(float2*)(Ps + (row0 + 8) * PSTR + nt * 8 + tig * 2) = make_float2(p2, p3);
        }
        sum0 += __shfl_xor_sync(0xffffffffu, sum0, 1);
        sum0 += __shfl_xor_sync(0xffffffffu, sum0, 2);
        sum1 += __shfl_xor_sync(0xffffffffu, sum1, 1);
        sum1 += __shfl_xor_sync(0xffffffffu, sum1, 2);
        l0 = l0 * cf0 + sum0;
        l1 = l1 * cf1 + sum1;
#pragma unroll
        for (int nt = 0; nt < 16; nt++) {
            acc[nt][0] *= cf0; acc[nt][1] *= cf0;
            acc[nt][2] *= cf1; acc[nt][3] *= cf1;
        }
        __syncwarp();

        // O += P @ V
#pragma unroll
        for (int ks = 0; ks < 8; ks++) {
            const int kk = ks * 8;
            const float* pp = Ps + row0 * PSTR + kk;
            uint32_t af[4];
            af[0] = f2tf32(pp[tig]);
            af[1] = f2tf32(pp[8 * PSTR + tig]);
            af[2] = f2tf32(pp[tig + 4]);
            af[3] = f2tf32(pp[8 * PSTR + tig + 4]);
#pragma unroll
            for (int nt = 0; nt < 16; nt++) {
                uint32_t bf[2];
                bf[0] = f2tf32(Vs[(kk + tig) * VSTR + nt * 8 + g]);
                bf[1] = f2tf32(Vs[(kk + tig + 4) * VSTR + nt * 8 + g]);
                mma_tf32(acc[nt], af, bf);
            }
        }
    }

    float inv0 = 1.0f / l0, inv1 = 1.0f / l1;
#pragma unroll
    for (int nt = 0; nt < 16; nt++) {
        int col = h * DV + nt * 8 + tig * 2;
        *(float2*)(g_ctx + (size_t)qi0 * (NHEAD * DV) + col) =
            make_float2(acc[nt][0] * inv0, acc[nt][1] * inv0);
        *(float2*)(g_ctx + (size_t)qi1 * (NHEAD * DV) + col) =
            make_float2(acc[nt][2] * inv1, acc[nt][3] * inv1);
    }
}

// ---------------- RMSNorm ----------------
__global__ void rmsnorm_kernel(const float* in, const float* w, float* out, int D) {
    int t = blockIdx.x;
    const float* row = in + (size_t)t * D;
    float ss = 0.f;
    for (int i = threadIdx.x; i < D; i += blockDim.x) { float v = row[i]; ss += v * v; }
    __shared__ float sred[32];
    for (int o = 16; o > 0; o >>= 1) ss += __shfl_down_sync(0xffffffffu, ss, o);
    int lane = threadIdx.x & 31, warp = threadIdx.x >> 5;
    if (lane == 0) sred[warp] = ss;
    __syncthreads();
    int nw = blockDim.x >> 5;
    if (threadIdx.x == 0) {
        float tot = 0.f;
        for (int i = 0; i < nw; i++) tot += sred[i];
        sred[0] = 1.0f / sqrtf(tot / (float)D + 1e-6f);
    }
    __syncthreads();
    float scale = sred[0];
    for (int i = threadIdx.x; i < D; i += blockDim.x)
        out[(size_t)t * D + i] = row[i] * scale * w[i];
}

// ---------------- RoPE ----------------
__global__ void rope_kernel() {
    int idx = blockIdx.x * blockDim.x + threadIdx.x;
    int total = SEQ * NHEAD * (ROPED / 2);
    if (idx >= total) return;
    int i = idx & 31;
    int h = (idx >> 5) & (NHEAD - 1);
    int t = idx >> 9;
    float inv_freq = powf(10000.0f, -(float)(2 * i) / (float)ROPED);
    float f = (float)t * inv_freq;
    float c = cosf(f), s = sinf(f);
    float* qp = g_q + ((size_t)t * NHEAD + h) * DQK + NOPE;
    float x1 = qp[i], x2 = qp[i + 32];
    qp[i] = x1 * c - x2 * s;
    qp[i + 32] = x2 * c + x1 * s;
    float* kp = g_kv + ((size_t)t * NHEAD + h) * (DQK + DV) + NOPE;
    x1 = kp[i]; x2 = kp[i + 32];
    kp[i] = x1 * c - x2 * s;
    kp[i + 32] = x2 * c + x1 * s;
}

// ---------------- Router ----------------
__global__ void router_kernel(const float* __restrict__ rw, const float* __restrict__ rb) {
    int t = blockIdx.x;
    float part[NEXP];
#pragma unroll
    for (int e = 0; e < NEXP; e++) part[e] = 0.f;
    for (int hh = threadIdx.x; hh < HDIM; hh += 128) {
        float xv = g_h2[(size_t)t * HDIM + hh];
#pragma unroll
        for (int e = 0; e < NEXP; e++) part[e] += xv * rw[(size_t)e * HDIM + hh];
    }
    __shared__ float sred[4][NEXP];
#pragma unroll
    for (int e = 0; e < NEXP; e++)
        for (int o = 16; o > 0; o >>= 1) part[e] += __shfl_down_sync(0xffffffffu, part[e], o);
    int lane = threadIdx.x & 31, warp = threadIdx.x >> 5;
    if (lane == 0)
#pragma unroll
        for (int e = 0; e < NEXP; e++) sred[warp][e] = part[e];
    __syncthreads();
    if (threadIdx.x < NEXP) {
        int e = threadIdx.x;
        g_logits[t * NEXP + e] = sred[0][e] + sred[1][e] + sred[2][e] + sred[3][e] + rb[e];
    }
}

__global__ void zero_kernel() {
    if (threadIdx.x < NEXP) { g_cnt[threadIdx.x] = 0; g_fill[threadIdx.x] = 0; }
}

__global__ void topk_kernel() {
    int t = blockIdx.x * blockDim.x + threadIdx.x;
    if (t >= SEQ) return;
    float p[NEXP];
#pragma unroll
    for (int e = 0; e < NEXP; e++) p[e] = 1.0f / (1.0f + expf(-g_logits[t * NEXP + e]));
    float vals[TOPK]; int ids[TOPK];
    float sum = 0.f;
#pragma unroll
    for (int k = 0; k < TOPK; k++) {
        float best = -1e30f; int bi = 0;
#pragma unroll
        for (int e = 0; e < NEXP; e++)
            if (p[e] > best) { best = p[e]; bi = e; }
        vals[k] = best; ids[k] = bi; p[bi] = -1e30f; sum += best;
    }
    float w = 2.5f / (sum + 1e-9f);
#pragma unroll
    for (int k = 0; k < TOPK; k++) {
        g_wtop[t * TOPK + k] = vals[k] * w;
        g_topi[t * TOPK + k] = ids[k];
        atomicAdd(&g_cnt[ids[k]], 1);
    }
}

__global__ void offsets_kernel() {
    if (threadIdx.x == 0) {
        g_off[0] = 0;
        for (int e = 0; e < NEXP; e++) g_off[e + 1] = g_off[e] + g_cnt[e];
    }
}

__global__ void scatter_kernel() {
    int t = blockIdx.x * blockDim.x + threadIdx.x;
    if (t >= SEQ) return;
#pragma unroll
    for (int k = 0; k < TOPK; k++) {
        int e = g_topi[t * TOPK + k];
        int pos = atomicAdd(&g_fill[e], 1);
        int slot = g_off[e] + pos;
        g_slot[t * TOPK + k] = slot;
        g_tok[slot] = t;
    }
}

// ---------------- SiLU(a)*b ----------------
__global__ void act_kernel(float* a, const float* b, size_t n) {
    size_t i = (size_t)blockIdx.x * blockDim.x + threadIdx.x;
    if (i >= n) return;
    float g = a[i];
    float sg = g / (1.0f + expf(-g));
    a[i] = sg * b[i];
}

// ---------------- Final combine ----------------
__global__ void combine_kernel(float* out) {
    int t = blockIdx.x;
    float w[TOPK]; int s[TOPK];
#pragma unroll
    for (int k = 0; k < TOPK; k++) { w[k] = g_wtop[t * TOPK + k]; s[k] = g_slot[t * TOPK + k]; }
    for (int hh = threadIdx.x; hh < HDIM; hh += 256) {
        float v = g_xmid[(size_t)t * HDIM + hh] + g_shr[(size_t)t * HDIM + hh];
#pragma unroll
        for (int k = 0; k < TOPK; k++)
            v += w[k] * g_down[(size_t)s[k] * HDIM + hh];
        out[(size_t)t * HDIM + hh] = v;
    }
}

// ---------------- host ----------------
static float* symf(const void* sym) { void* p = nullptr; cudaGetSymbolAddress(&p, sym); return (float*)p; }
static int*   symi(const void* sym) { void* p = nullptr; cudaGetSymbolAddress(&p, sym); return (int*)p; }

extern "C" void kernel_launch(void* const* d_in, const int* in_sizes, int n_in,
                              void* d_out, int out_size)
{
    const float* x      = (const float*)d_in[0];
    const float* ln1_w  = (const float*)d_in[2];
    const float* ln2_w  = (const float*)d_in[3];
    const float* q_a_w  = (const float*)d_in[4];
    const float* q_a_ln = (const float*)d_in[5];
    const float* q_b_w  = (const float*)d_in[6];
    const float* kv_a_w = (const float*)d_in[7];
    const float* kv_a_ln= (const float*)d_in[8];
    const float* kv_b_w = (const float*)d_in[9];
    const float* o_w    = (const float*)d_in[10];
    const float* rout_w = (const float*)d_in[11];
    const float* rout_b = (const float*)d_in[12];
    const float* gate_w = (const float*)d_in[13];
    const float* up_w   = (const float*)d_in[14];
    const float* down_w = (const float*)d_in[15];
    const float* sg_w   = (const float*)d_in[16];
    const float* su_w   = (const float*)d_in[17];
    const float* sd_w   = (const float*)d_in[18];
    float* out = (float*)d_out;

    float* h1   = symf(g_h1);
    float* qa   = symf(g_qa);
    float* kva  = symf(g_kva);
    float* q    = symf(g_q);
    float* kv   = symf(g_kv);
    float* ctx  = symf(g_ctx);
    float* xmid = symf(g_xmid);
    float* h2   = symf(g_h2);
    float* gate = symf(g_gate);
    float* up   = symf(g_up);
    float* down = symf(g_down);
    float* sg   = symf(g_sg);
    float* su   = symf(g_su);
    float* shr  = symf(g_shr);
    int*   tok  = symi(g_tok);
    int*   off  = symi(g_off);

    cudaFuncSetAttribute(gemm_tf32, cudaFuncAttributeMaxDynamicSharedMemorySize, GSMEM);
    cudaFuncSetAttribute(gemm_tf32_moe, cudaFuncAttributeMaxDynamicSharedMemorySize, GSMEM);
    cudaFuncSetAttribute(attn_mma_kernel, cudaFuncAttributeMaxDynamicSharedMemorySize, ATTN_SMEM);

    // ---- attention branch ----
    rmsnorm_kernel<<<SEQ, 256>>>(x, ln1_w, h1, HDIM);
    gemm_tf32<<<dim3(QRNK / BN, SEQ / BM), 256, GSMEM>>>(h1, q_a_w, qa, nullptr, SEQ, QRNK, HDIM);
    rmsnorm_kernel<<<SEQ, 256>>>(qa, q_a_ln, qa, QRNK);
    gemm_tf32<<<dim3(KVRNK / BN, SEQ / BM), 256, GSMEM>>>(h1, kv_a_w, kva, nullptr, SEQ, KVRNK, HDIM);
    rmsnorm_kernel<<<SEQ, 256>>>(kva, kv_a_ln, kva, KVRNK);
    gemm_tf32<<<dim3(NHEAD * DQK / BN, SEQ / BM), 256, GSMEM>>>(qa, q_b_w, q, nullptr, SEQ, NHEAD * DQK, QRNK);
    gemm_tf32<<<dim3(NHEAD * (DQK + DV) / BN, SEQ / BM), 256, GSMEM>>>(kva, kv_b_w, kv, nullptr, SEQ, NHEAD * (DQK + DV), KVRNK);
    rope_kernel<<<(SEQ * NHEAD * (ROPED / 2) + 255) / 256, 256>>>();
    attn_mma_kernel<<<dim3(SEQ / AQ, NHEAD), 256, ATTN_SMEM>>>();
    gemm_tf32<<<dim3(HDIM / BN, SEQ / BM), 256, GSMEM>>>(ctx, o_w, xmid, x, SEQ, HDIM, NHEAD * DV);

    // ---- MoE branch ----
    rmsnorm_kernel<<<SEQ, 256>>>(xmid, ln2_w, h2, HDIM);
    router_kernel<<<SEQ, 128>>>(rout_w, rout_b);
    zero_kernel<<<1, 32>>>();
    topk_kernel<<<SEQ / 256, 256>>>();
    offsets_kernel<<<1, 1>>>();
    scatter_kernel<<<SEQ / 256, 256>>>();

    gemm_tf32_moe<<<dim3(MINT / BN, SEQ / BM, NEXP), 256, GSMEM>>>(h2, tok, gate_w, (size_t)MINT * HDIM, gate, MINT, HDIM, off);
    gemm_tf32_moe<<<dim3(MINT / BN, SEQ / BM, NEXP), 256, GSMEM>>>(h2, tok, up_w, (size_t)MINT * HDIM, up, MINT, HDIM, off);
    act_kernel<<<(unsigned)(((size_t)NSLOT * MINT + 255) / 256), 256>>>(gate, up, (size_t)NSLOT * MINT);
    gemm_tf32_moe<<<dim3(HDIM / BN, SEQ / BM, NEXP), 256, GSMEM>>>(gate, nullptr, down_w, (size_t)HDIM * MINT, down, HDIM, MINT, off);

    // shared expert
    gemm_tf32<<<dim3(MINT / BN, SEQ / BM), 256, GSMEM>>>(h2, sg_w, sg, nullptr, SEQ, MINT, HDIM);
    gemm_tf32<<<dim3(MINT / BN, SEQ / BM), 256, GSMEM>>>(h2, su_w, su, nullptr, SEQ, MINT, HDIM);
    act_kernel<<<(unsigned)(((size_t)SEQ * MINT + 255) / 256), 256>>>(sg, su, (size_t)SEQ * MINT);
    gemm_tf32<<<dim3(HDIM / BN, SEQ / BM), 256, GSMEM>>>(sg, sd_w, shr, nullptr, SEQ, HDIM, MINT);

    combine_kernel<<<SEQ, 256>>>(out);
}

// round 5
// speedup vs baseline: 8.9037x; 1.8363x over previous
#include <cuda_runtime.h>
#include <cuda_fp16.h>
#include <math.h>
#include <stdint.h>

// ---------------- problem constants ----------------
#define SEQ   2048
#define HDIM  2048
#define NHEAD 16
#define DQK   192
#define DV    128
#define NOPE  128
#define ROPED 64
#define QRNK  768
#define KVRNK 512
#define NEXP  16
#define TOPK  4
#define MINT  1024
#define NSLOT (SEQ*TOPK)

// GEMM tiling (fp16, m16n8k16)
#define BM 128
#define BN 128
#define BK 64
#define SKS 72            // smem row stride in halves (64 + 8 pad)
#define GSMEM (2*(BM+BN)*SKS*2)

// attention tiling
#define AQ 128
#define AK 64
#define QST 200
#define KST 200
#define VTS 72
#define PST 72
#define ATTN_SMEM ((AQ*QST + AK*KST + DV*VTS + AQ*PST)*2)

// ---------------- fp32 scratch ----------------
__device__ float g_qa[SEQ*QRNK];
__device__ float g_kva[SEQ*KVRNK];
__device__ float g_xmid[SEQ*HDIM];
__device__ float g_h2f[SEQ*HDIM];
__device__ float g_down[(size_t)NSLOT*HDIM];
__device__ float g_shr[SEQ*HDIM];
__device__ float g_logits[SEQ*NEXP];
__device__ float g_wtop[SEQ*TOPK];
__device__ int   g_topi[SEQ*TOPK];
__device__ int   g_slot[SEQ*TOPK];
__device__ int   g_cnt[NEXP];
__device__ int   g_off[NEXP+1];
__device__ int   g_fill[NEXP];
__device__ int   g_tok[NSLOT];

// ---------------- fp16 weights ----------------
__device__ __half w_qa[QRNK*HDIM];
__device__ __half w_kva[KVRNK*HDIM];
__device__ __half w_qb[NHEAD*DQK*QRNK];
__device__ __half w_kvb[NHEAD*(DQK+DV)*KVRNK];
__device__ __half w_o[HDIM*NHEAD*DV];
__device__ __half w_gate[(size_t)NEXP*MINT*HDIM];
__device__ __half w_up[(size_t)NEXP*MINT*HDIM];
__device__ __half w_down[(size_t)NEXP*HDIM*MINT];
__device__ __half w_sg[MINT*HDIM];
__device__ __half w_su[MINT*HDIM];
__device__ __half w_sd[HDIM*MINT];

// ---------------- fp16 activations ----------------
__device__ __half a_h1[SEQ*HDIM];
__device__ __half a_qa[SEQ*QRNK];
__device__ __half a_kva[SEQ*KVRNK];
__device__ __half a_q[SEQ*NHEAD*DQK];
__device__ __half a_kv[SEQ*NHEAD*(DQK+DV)];
__device__ __half a_ctx[SEQ*NHEAD*DV];
__device__ __half a_h2[SEQ*HDIM];
__device__ __half a_gate[(size_t)NSLOT*MINT];
__device__ __half a_up[(size_t)NSLOT*MINT];
__device__ __half a_sg[SEQ*MINT];
__device__ __half a_su[SEQ*MINT];

// ---------------- helpers ----------------
__device__ __forceinline__ void cp16(uint32_t dst, const void* src, int szbytes) {
    asm volatile("cp.async.cg.shared.global [%0], [%1], 16, %2;\n"
                 :: "r"(dst), "l"(src), "r"(szbytes));
}
__device__ __forceinline__ void cp_commit() { asm volatile("cp.async.commit_group;\n"); }
__device__ __forceinline__ void cp_wait0()  { asm volatile("cp.async.wait_group 0;\n"); }
__device__ __forceinline__ void cp_wait1()  { asm volatile("cp.async.wait_group 1;\n"); }

__device__ __forceinline__ void mma_h(float* c, const uint32_t* a, const uint32_t* b) {
    asm volatile(
        "mma.sync.aligned.m16n8k16.row.col.f32.f16.f16.f32 "
        "{%0,%1,%2,%3}, {%4,%5,%6,%7}, {%8,%9}, {%0,%1,%2,%3};\n"
        : "+f"(c[0]), "+f"(c[1]), "+f"(c[2]), "+f"(c[3])
        : "r"(a[0]), "r"(a[1]), "r"(a[2]), "r"(a[3]), "r"(b[0]), "r"(b[1]));
}
__device__ __forceinline__ uint32_t ldu32(const __half* p) { return *(const uint32_t*)p; }

// ---------------- fp32 -> fp16 convert ----------------
__global__ void conv_f2h(const float* __restrict__ in, __half* __restrict__ out, int n4) {
    int i = blockIdx.x * blockDim.x + threadIdx.x;
    if (i >= n4) return;
    float4 v = ((const float4*)in)[i];
    __half2* o = (__half2*)out + (size_t)i * 2;
    o[0] = __floats2half2_rn(v.x, v.y);
    o[1] = __floats2half2_rn(v.z, v.w);
}

// ---------------- fp16 tensor-core GEMM (dual-B): C = A @ B^T ----------------
__global__ __launch_bounds__(256, 2) void gemm_h(
    const __half* __restrict__ A,
    const __half* __restrict__ B1, float* C1, __half* C1h, const float* add1, int N1,
    const __half* __restrict__ B2, float* C2, __half* C2h, int N2,
    int M, int K)
{
    extern __shared__ __half smh[];
    __half* As0 = smh;
    __half* Bs0 = smh + 2 * BM * SKS;

    int n0 = blockIdx.x * BN;
    const __half* B; float* C; __half* Ch; const float* addsrc; int N;
    if (n0 < N1) { B = B1; C = C1; Ch = C1h; addsrc = add1; N = N1; }
    else { n0 -= N1; B = B2; C = C2; Ch = C2h; addsrc = nullptr; N = N2; }

    const int tid = threadIdx.x;
    const int warp = tid >> 5, lane = tid & 31;
    const int g = lane >> 2, tig = lane & 3;
    const int warp_m = (warp & 1) * 64, warp_n = (warp >> 1) * 32;
    const int m0 = blockIdx.y * BM;

    float acc[4][4][4];
#pragma unroll
    for (int a = 0; a < 4; a++)
#pragma unroll
        for (int b = 0; b < 4; b++)
#pragma unroll
            for (int c = 0; c < 4; c++) acc[a][b][c] = 0.f;

    const int nk = K / BK;
    uint32_t smA[2], smB[2];
    smA[0] = (uint32_t)__cvta_generic_to_shared(As0);
    smA[1] = (uint32_t)__cvta_generic_to_shared(As0 + BM * SKS);
    smB[0] = (uint32_t)__cvta_generic_to_shared(Bs0);
    smB[1] = (uint32_t)__cvta_generic_to_shared(Bs0 + BN * SKS);

    {
#pragma unroll
        for (int i = 0; i < 4; i++) {
            int cid = tid + i * 256;
            int row = cid >> 3, c8 = (cid & 7) << 3;
            cp16(smA[0] + (row * SKS + c8) * 2, A + (size_t)(m0 + row) * K + c8, 16);
        }
#pragma unroll
        for (int i = 0; i < 4; i++) {
            int cid = tid + i * 256;
            int row = cid >> 3, c8 = (cid & 7) << 3;
            cp16(smB[0] + (row * SKS + c8) * 2, B + (size_t)(n0 + row) * K + c8, 16);
        }
        cp_commit();
    }

    for (int kt = 0; kt < nk; kt++) {
        int cur = kt & 1;
        if (kt + 1 < nk) {
            int nb = cur ^ 1;
            int k0 = (kt + 1) * BK;
#pragma unroll
            for (int i = 0; i < 4; i++) {
                int cid = tid + i * 256;
                int row = cid >> 3, c8 = (cid & 7) << 3;
                cp16(smA[nb] + (row * SKS + c8) * 2, A + (size_t)(m0 + row) * K + k0 + c8, 16);
            }
#pragma unroll
            for (int i = 0; i < 4; i++) {
                int cid = tid + i * 256;
                int row = cid >> 3, c8 = (cid & 7) << 3;
                cp16(smB[nb] + (row * SKS + c8) * 2, B + (size_t)(n0 + row) * K + k0 + c8, 16);
            }
            cp_commit();
            cp_wait1();
        } else {
            cp_wait0();
        }
        __syncthreads();

        const __half* As_ = As0 + cur * BM * SKS;
        const __half* Bs_ = Bs0 + cur * BN * SKS;
#pragma unroll
        for (int ks = 0; ks < 4; ks++) {
            const int kk = ks * 16;
            uint32_t af[4][4], bf[4][2];
#pragma unroll
            for (int mt = 0; mt < 4; mt++) {
                const __half* ap = As_ + (warp_m + mt * 16 + g) * SKS + kk + 2 * tig;
                af[mt][0] = ldu32(ap);
                af[mt][1] = ldu32(ap + 8 * SKS);
                af[mt][2] = ldu32(ap + 8);
                af[mt][3] = ldu32(ap + 8 * SKS + 8);
            }
#pragma unroll
            for (int nt = 0; nt < 4; nt++) {
                const __half* bp = Bs_ + (warp_n + nt * 8 + g) * SKS + kk + 2 * tig;
                bf[nt][0] = ldu32(bp);
                bf[nt][1] = ldu32(bp + 8);
            }
#pragma unroll
            for (int mt = 0; mt < 4; mt++)
#pragma unroll
                for (int nt = 0; nt < 4; nt++)
                    mma_h(acc[mt][nt], af[mt], bf[nt]);
        }
        __syncthreads();
    }

#pragma unroll
    for (int mt = 0; mt < 4; mt++) {
        int r0 = m0 + warp_m + mt * 16 + g;
#pragma unroll
        for (int nt = 0; nt < 4; nt++) {
            int gc = n0 + warp_n + nt * 8 + tig * 2;
            float v0 = acc[mt][nt][0], v1 = acc[mt][nt][1];
            float v2 = acc[mt][nt][2], v3 = acc[mt][nt][3];
            if (addsrc) {
                v0 += addsrc[(size_t)r0 * N + gc];
                v1 += addsrc[(size_t)r0 * N + gc + 1];
                v2 += addsrc[(size_t)(r0 + 8) * N + gc];
                v3 += addsrc[(size_t)(r0 + 8) * N + gc + 1];
            }
            if (C) {
                *(float2*)(C + (size_t)r0 * N + gc) = make_float2(v0, v1);
                *(float2*)(C + (size_t)(r0 + 8) * N + gc) = make_float2(v2, v3);
            }
            if (Ch) {
                *(__half2*)(Ch + (size_t)r0 * N + gc) = __floats2half2_rn(v0, v1);
                *(__half2*)(Ch + (size_t)(r0 + 8) * N + gc) = __floats2half2_rn(v2, v3);
            }
        }
    }
}

// ---------------- fp16 grouped MoE GEMM (dual-B, gathered A) ----------------
__global__ __launch_bounds__(256, 2) void gemm_h_moe(
    const __half* __restrict__ A, const int* __restrict__ gather,
    const __half* __restrict__ B1b, float* C1, __half* C1h, int N1,
    const __half* __restrict__ B2b, __half* C2h, int N2,
    size_t strideB, int K, const int* __restrict__ off)
{
    const int e = blockIdx.z;
    const int start = off[e];
    const int cnt = off[e + 1] - start;
    const int m0 = blockIdx.y * BM;
    if (m0 >= cnt) return;

    int n0 = blockIdx.x * BN;
    const __half* B; float* C; __half* Ch; int N;
    if (n0 < N1) { B = B1b + (size_t)e * strideB; C = C1; Ch = C1h; N = N1; }
    else { n0 -= N1; B = B2b + (size_t)e * strideB; C = nullptr; Ch = C2h; N = N2; }

    extern __shared__ __half smh[];
    __half* As0 = smh;
    __half* Bs0 = smh + 2 * BM * SKS;
    __shared__ int rowmap[BM];

    const int tid = threadIdx.x;
    if (tid < BM) {
        int r = m0 + tid;
        int gr = -1;
        if (r < cnt) gr = gather ? gather[start + r] : (start + r);
        rowmap[tid] = gr;
    }
    __syncthreads();

    const int warp = tid >> 5, lane = tid & 31;
    const int g = lane >> 2, tig = lane & 3;
    const int warp_m = (warp & 1) * 64, warp_n = (warp >> 1) * 32;

    float acc[4][4][4];
#pragma unroll
    for (int a = 0; a < 4; a++)
#pragma unroll
        for (int b = 0; b < 4; b++)
#pragma unroll
            for (int c = 0; c < 4; c++) acc[a][b][c] = 0.f;

    const int nk = K / BK;
    uint32_t smA[2], smB[2];
    smA[0] = (uint32_t)__cvta_generic_to_shared(As0);
    smA[1] = (uint32_t)__cvta_generic_to_shared(As0 + BM * SKS);
    smB[0] = (uint32_t)__cvta_generic_to_shared(Bs0);
    smB[1] = (uint32_t)__cvta_generic_to_shared(Bs0 + BN * SKS);

    {
#pragma unroll
        for (int i = 0; i < 4; i++) {
            int cid = tid + i * 256;
            int row = cid >> 3, c8 = (cid & 7) << 3;
            int gr = rowmap[row];
            const __half* src = (gr >= 0) ? (A + (size_t)gr * K + c8) : A;
            cp16(smA[0] + (row * SKS + c8) * 2, src, (gr >= 0) ? 16 : 0);
        }
#pragma unroll
        for (int i = 0; i < 4; i++) {
            int cid = tid + i * 256;
            int row = cid >> 3, c8 = (cid & 7) << 3;
            cp16(smB[0] + (row * SKS + c8) * 2, B + (size_t)(n0 + row) * K + c8, 16);
        }
        cp_commit();
    }

    for (int kt = 0; kt < nk; kt++) {
        int cur = kt & 1;
        if (kt + 1 < nk) {
            int nb = cur ^ 1;
            int k0 = (kt + 1) * BK;
#pragma unroll
            for (int i = 0; i < 4; i++) {
                int cid = tid + i * 256;
                int row = cid >> 3, c8 = (cid & 7) << 3;
                int gr = rowmap[row];
                const __half* src = (gr >= 0) ? (A + (size_t)gr * K + k0 + c8) : A;
                cp16(smA[nb] + (row * SKS + c8) * 2, src, (gr >= 0) ? 16 : 0);
            }
#pragma unroll
            for (int i = 0; i < 4; i++) {
                int cid = tid + i * 256;
                int row = cid >> 3, c8 = (cid & 7) << 3;
                cp16(smB[nb] + (row * SKS + c8) * 2, B + (size_t)(n0 + row) * K + k0 + c8, 16);
            }
            cp_commit();
            cp_wait1();
        } else {
            cp_wait0();
        }
        __syncthreads();

        const __half* As_ = As0 + cur * BM * SKS;
        const __half* Bs_ = Bs0 + cur * BN * SKS;
#pragma unroll
        for (int ks = 0; ks < 4; ks++) {
            const int kk = ks * 16;
            uint32_t af[4][4], bf[4][2];
#pragma unroll
            for (int mt = 0; mt < 4; mt++) {
                const __half* ap = As_ + (warp_m + mt * 16 + g) * SKS + kk + 2 * tig;
                af[mt][0] = ldu32(ap);
                af[mt][1] = ldu32(ap + 8 * SKS);
                af[mt][2] = ldu32(ap + 8);
                af[mt][3] = ldu32(ap + 8 * SKS + 8);
            }
#pragma unroll
            for (int nt = 0; nt < 4; nt++) {
                const __half* bp = Bs_ + (warp_n + nt * 8 + g) * SKS + kk + 2 * tig;
                bf[nt][0] = ldu32(bp);
                bf[nt][1] = ldu32(bp + 8);
            }
#pragma unroll
            for (int mt = 0; mt < 4; mt++)
#pragma unroll
                for (int nt = 0; nt < 4; nt++)
                    mma_h(acc[mt][nt], af[mt], bf[nt]);
        }
        __syncthreads();
    }

#pragma unroll
    for (int mt = 0; mt < 4; mt++) {
        int r = warp_m + mt * 16 + g;
#pragma unroll
        for (int nt = 0; nt < 4; nt++) {
            int gc = n0 + warp_n + nt * 8 + tig * 2;
            if (m0 + r < cnt) {
                size_t o = (size_t)(start + m0 + r) * N + gc;
                if (C) *(float2*)(C + o) = make_float2(acc[mt][nt][0], acc[mt][nt][1]);
                if (Ch) *(__half2*)(Ch + o) = __floats2half2_rn(acc[mt][nt][0], acc[mt][nt][1]);
            }
            if (m0 + r + 8 < cnt) {
                size_t o = (size_t)(start + m0 + r + 8) * N + gc;
                if (C) *(float2*)(C + o) = make_float2(acc[mt][nt][2], acc[mt][nt][3]);
                if (Ch) *(__half2*)(Ch + o) = __floats2half2_rn(acc[mt][nt][2], acc[mt][nt][3]);
            }
        }
    }
}

// ---------------- fp16 tensor-core flash attention ----------------
__global__ __launch_bounds__(256) void attn_h_kernel() {
    extern __shared__ __half smh[];
    __half* Qs = smh;                     // [AQ][QST]
    __half* Ks = Qs + AQ * QST;           // [AK][KST]
    __half* Vt = Ks + AK * KST;           // [DV][VTS] transposed
    __half* Ps = Vt + DV * VTS;           // [AQ][PST]

    const int h = blockIdx.y;
    const int qb = gridDim.x - 1 - blockIdx.x;
    const int q0 = qb * AQ;
    const int tid = threadIdx.x;
    const int warp = tid >> 5, lane = tid & 31;
    const int g = lane >> 2, tig = lane & 3;
    const int row0 = warp * 16 + g;
    const int qi0 = q0 + row0, qi1 = qi0 + 8;

#pragma unroll
    for (int i = 0; i < 12; i++) {
        int idx = tid + i * 256;
        int r = idx / 24, c = (idx % 24) * 8;
        *(float4*)(Qs + r * QST + c) =
            *(const float4*)(a_q + ((size_t)(q0 + r) * NHEAD + h) * DQK + c);
    }

    float acc[16][4];
#pragma unroll
    for (int n = 0; n < 16; n++)
#pragma unroll
        for (int c = 0; c < 4; c++) acc[n][c] = 0.f;
    float m0 = -1e30f, m1 = -1e30f, l0 = 0.f, l1 = 0.f;
    const float scale = 0.07216878364870323f; // 1/sqrt(192)

    const int ntiles = qb * 2 + 2;
    for (int tile = 0; tile < ntiles; tile++) {
        int t0 = tile * AK;
        __syncthreads();
#pragma unroll
        for (int i = 0; i < 6; i++) {
            int idx = tid + i * 256;
            int r = idx / 24, c = (idx % 24) * 8;
            *(float4*)(Ks + r * KST + c) =
                *(const float4*)(a_kv + ((size_t)(t0 + r) * NHEAD + h) * (DQK + DV) + c);
        }
#pragma unroll
        for (int i = 0; i < 16; i++) {
            int idx = tid + i * 256;
            int s = idx >> 6, d2 = idx & 63;
            __half2 v = *(const __half2*)(a_kv + ((size_t)(t0 + s) * NHEAD + h) * (DQK + DV) + DQK + 2 * d2);
            Vt[(2 * d2) * VTS + s] = __low2half(v);
            Vt[(2 * d2 + 1) * VTS + s] = __high2half(v);
        }
        __syncthreads();

        float s[8][4];
#pragma unroll
        for (int n = 0; n < 8; n++)
#pragma unroll
            for (int c = 0; c < 4; c++) s[n][c] = 0.f;
#pragma unroll
        for (int ks = 0; ks < 12; ks++) {
            const int kk = ks * 16;
            const __half* ap = Qs + row0 * QST + kk + 2 * tig;
            uint32_t af[4];
            af[0] = ldu32(ap);
            af[1] = ldu32(ap + 8 * QST);
            af[2] = ldu32(ap + 8);
            af[3] = ldu32(ap + 8 * QST + 8);
#pragma unroll
            for (int nt = 0; nt < 8; nt++) {
                const __half* bp = Ks + (nt * 8 + g) * KST + kk + 2 * tig;
                uint32_t bf[2];
                bf[0] = ldu32(bp);
                bf[1] = ldu32(bp + 8);
                mma_h(s[nt], af, bf);
            }
        }

        const bool domask = (t0 + AK - 1 > q0);
#pragma unroll
        for (int nt = 0; nt < 8; nt++) {
#pragma unroll
            for (int c = 0; c < 4; c++) s[nt][c] *= scale;
            if (domask) {
                int kj = t0 + nt * 8 + tig * 2;
                if (kj > qi0)     s[nt][0] = -1e30f;
                if (kj + 1 > qi0) s[nt][1] = -1e30f;
                if (kj > qi1)     s[nt][2] = -1e30f;
                if (kj + 1 > qi1) s[nt][3] = -1e30f;
            }
        }

        float mx0 = -1e30f, mx1 = -1e30f;
#pragma unroll
        for (int nt = 0; nt < 8; nt++) {
            mx0 = fmaxf(mx0, fmaxf(s[nt][0], s[nt][1]));
            mx1 = fmaxf(mx1, fmaxf(s[nt][2], s[nt][3]));
        }
        mx0 = fmaxf(mx0, __shfl_xor_sync(0xffffffffu, mx0, 1));
        mx0 = fmaxf(mx0, __shfl_xor_sync(0xffffffffu, mx0, 2));
        mx1 = fmaxf(mx1, __shfl_xor_sync(0xffffffffu, mx1, 1));
        mx1 = fmaxf(mx1, __shfl_xor_sync(0xffffffffu, mx1, 2));

        float mn0 = fmaxf(m0, mx0), mn1 = fmaxf(m1, mx1);
        float cf0 = __expf(m0 - mn0), cf1 = __expf(m1 - mn1);
        m0 = mn0; m1 = mn1;

        float sum0 = 0.f, sum1 = 0.f;
#pragma unroll
        for (int nt = 0; nt < 8; nt++) {
            float p0 = __expf(s[nt][0] - m0);
            float p1 = __expf(s[nt][1] - m0);
            float p2 = __expf(s[nt][2] - m1);
            float p3 = __expf(s[nt][3] - m1);
            sum0 += p0 + p1; sum1 += p2 + p3;
            *(__half2*)(Ps + row0 * PST + nt * 8 + tig * 2) = __floats2half2_rn(p0, p1);
            *(__half2*)(Ps + (row0 + 8) * PST + nt * 8 + tig * 2) = __floats2half2_rn(p2, p3);
        }
        sum0 += __shfl_xor_sync(0xffffffffu, sum0, 1);
        sum0 += __shfl_xor_sync(0xffffffffu, sum0, 2);
        sum1 += __shfl_xor_sync(0xffffffffu, sum1, 1);
        sum1 += __shfl_xor_sync(0xffffffffu, sum1, 2);
        l0 = l0 * cf0 + sum0;
        l1 = l1 * cf1 + sum1;
#pragma unroll
        for (int nt = 0; nt < 16; nt++) {
            acc[nt][0] *= cf0; acc[nt][1] *= cf0;
            acc[nt][2] *= cf1; acc[nt][3] *= cf1;
        }
        __syncwarp();

#pragma unroll
        for (int ks = 0; ks < 4; ks++) {
            const int kk = ks * 16;
            const __half* pp = Ps + row0 * PST + kk + 2 * tig;
            uint32_t af[4];
            af[0] = ldu32(pp);
            af[1] = ldu32(pp + 8 * PST);
            af[2] = ldu32(pp + 8);
            af[3] = ldu32(pp + 8 * PST + 8);
#pragma unroll
            for (int nt = 0; nt < 16; nt++) {
                const __half* bp = Vt + (nt * 8 + g) * VTS + kk + 2 * tig;
                uint32_t bf[2];
                bf[0] = ldu32(bp);
                bf[1] = ldu32(bp + 8);
                mma_h(acc[nt], af, bf);
            }
        }
    }

    float inv0 = 1.0f / l0, inv1 = 1.0f / l1;
#pragma unroll
    for (int nt = 0; nt < 16; nt++) {
        int col = h * DV + nt * 8 + tig * 2;
        *(__half2*)(a_ctx + (size_t)qi0 * (NHEAD * DV) + col) =
            __floats2half2_rn(acc[nt][0] * inv0, acc[nt][1] * inv0);
        *(__half2*)(a_ctx + (size_t)qi1 * (NHEAD * DV) + col) =
            __floats2half2_rn(acc[nt][2] * inv1, acc[nt][3] * inv1);
    }
}

// ---------------- RMSNorm fp32 in -> fp16 out (optional fp32 dual-write) ----------------
__global__ void rmsnorm_h(const float* in, const float* w, __half* out, float* outf, int D) {
    int t = blockIdx.x;
    const float* row = in + (size_t)t * D;
    float ss = 0.f;
    for (int i = threadIdx.x; i < D; i += blockDim.x) { float v = row[i]; ss += v * v; }
    __shared__ float sred[32];
    for (int o = 16; o > 0; o >>= 1) ss += __shfl_down_sync(0xffffffffu, ss, o);
    int lane = threadIdx.x & 31, warp = threadIdx.x >> 5;
    if (lane == 0) sred[warp] = ss;
    __syncthreads();
    int nw = blockDim.x >> 5;
    if (threadIdx.x == 0) {
        float tot = 0.f;
        for (int i = 0; i < nw; i++) tot += sred[i];
        sred[0] = 1.0f / sqrtf(tot / (float)D + 1e-6f);
    }
    __syncthreads();
    float scale = sred[0];
    for (int i = threadIdx.x; i < D; i += blockDim.x) {
        float v = row[i] * scale * w[i];
        out[(size_t)t * D + i] = __float2half(v);
        if (outf) outf[(size_t)t * D + i] = v;
    }
}

// ---------------- RoPE (half, in place) ----------------
__global__ void rope_h_kernel() {
    int idx = blockIdx.x * blockDim.x + threadIdx.x;
    int total = SEQ * NHEAD * (ROPED / 2);
    if (idx >= total) return;
    int i = idx & 31;
    int h = (idx >> 5) & (NHEAD - 1);
    int t = idx >> 9;
    float inv_freq = powf(10000.0f, -(float)(2 * i) / (float)ROPED);
    float f = (float)t * inv_freq;
    float c = cosf(f), s = sinf(f);
    __half* qp = a_q + ((size_t)t * NHEAD + h) * DQK + NOPE;
    float x1 = __half2float(qp[i]), x2 = __half2float(qp[i + 32]);
    qp[i] = __float2half(x1 * c - x2 * s);
    qp[i + 32] = __float2half(x2 * c + x1 * s);
    __half* kp = a_kv + ((size_t)t * NHEAD + h) * (DQK + DV) + NOPE;
    x1 = __half2float(kp[i]); x2 = __half2float(kp[i + 32]);
    kp[i] = __float2half(x1 * c - x2 * s);
    kp[i + 32] = __float2half(x2 * c + x1 * s);
}

// ---------------- Router (reads fp32 h2 for exact-enough top-k) ----------------
__global__ void router_kernel(const float* __restrict__ rw, const float* __restrict__ rb) {
    int t = blockIdx.x;
    float part[NEXP];
#pragma unroll
    for (int e = 0; e < NEXP; e++) part[e] = 0.f;
    for (int hh = threadIdx.x; hh < HDIM; hh += 128) {
        float xv = g_h2f[(size_t)t * HDIM + hh];
#pragma unroll
        for (int e = 0; e < NEXP; e++) part[e] += xv * rw[(size_t)e * HDIM + hh];
    }
    __shared__ float sred[4][NEXP];
#pragma unroll
    for (int e = 0; e < NEXP; e++)
        for (int o = 16; o > 0; o >>= 1) part[e] += __shfl_down_sync(0xffffffffu, part[e], o);
    int lane = threadIdx.x & 31, warp = threadIdx.x >> 5;
    if (lane == 0)
#pragma unroll
        for (int e = 0; e < NEXP; e++) sred[warp][e] = part[e];
    __syncthreads();
    if (threadIdx.x < NEXP) {
        int e = threadIdx.x;
        g_logits[t * NEXP + e] = sred[0][e] + sred[1][e] + sred[2][e] + sred[3][e] + rb[e];
    }
}

__global__ void zero_kernel() {
    if (threadIdx.x < NEXP) { g_cnt[threadIdx.x] = 0; g_fill[threadIdx.x] = 0; }
}

__global__ void topk_kernel() {
    int t = blockIdx.x * blockDim.x + threadIdx.x;
    if (t >= SEQ) return;
    float p[NEXP];
#pragma unroll
    for (int e = 0; e < NEXP; e++) p[e] = 1.0f / (1.0f + expf(-g_logits[t * NEXP + e]));
    float vals[TOPK]; int ids[TOPK];
    float sum = 0.f;
#pragma unroll
    for (int k = 0; k < TOPK; k++) {
        float best = -1e30f; int bi = 0;
#pragma unroll
        for (int e = 0; e < NEXP; e++)
            if (p[e] > best) { best = p[e]; bi = e; }
        vals[k] = best; ids[k] = bi; p[bi] = -1e30f; sum += best;
    }
    float w = 2.5f / (sum + 1e-9f);
#pragma unroll
    for (int k = 0; k < TOPK; k++) {
        g_wtop[t * TOPK + k] = vals[k] * w;
        g_topi[t * TOPK + k] = ids[k];
        atomicAdd(&g_cnt[ids[k]], 1);
    }
}

__global__ void offsets_kernel() {
    if (threadIdx.x == 0) {
        g_off[0] = 0;
        for (int e = 0; e < NEXP; e++) g_off[e + 1] = g_off[e] + g_cnt[e];
    }
}

__global__ void scatter_kernel() {
    int t = blockIdx.x * blockDim.x + threadIdx.x;
    if (t >= SEQ) return;
#pragma unroll
    for (int k = 0; k < TOPK; k++) {
        int e = g_topi[t * TOPK + k];
        int pos = atomicAdd(&g_fill[e], 1);
        int slot = g_off[e] + pos;
        g_slot[t * TOPK + k] = slot;
        g_tok[slot] = t;
    }
}

// ---------------- SiLU(a)*b, fp16 (writes into a) ----------------
__global__ void act_h_kernel(__half2* a, const __half2* b, size_t n2) {
    size_t i = (size_t)blockIdx.x * blockDim.x + threadIdx.x;
    if (i >= n2) return;
    float2 gg = __half22float2(a[i]);
    float2 uu = __half22float2(b[i]);
    gg.x = gg.x / (1.0f + expf(-gg.x)) * uu.x;
    gg.y = gg.y / (1.0f + expf(-gg.y)) * uu.y;
    a[i] = __floats2half2_rn(gg.x, gg.y);
}

// ---------------- Final combine ----------------
__global__ void combine_kernel(float* out) {
    int t = blockIdx.x;
    float w[TOPK]; int s[TOPK];
#pragma unroll
    for (int k = 0; k < TOPK; k++) { w[k] = g_wtop[t * TOPK + k]; s[k] = g_slot[t * TOPK + k]; }
    for (int hh = threadIdx.x; hh < HDIM; hh += 256) {
        float v = g_xmid[(size_t)t * HDIM + hh] + g_shr[(size_t)t * HDIM + hh];
#pragma unroll
        for (int k = 0; k < TOPK; k++)
            v += w[k] * g_down[(size_t)s[k] * HDIM + hh];
        out[(size_t)t * HDIM + hh] = v;
    }
}

// ---------------- host ----------------
static float* symf(const void* sym) { void* p = nullptr; cudaGetSymbolAddress(&p, sym); return (float*)p; }
static __half* symh(const void* sym) { void* p = nullptr; cudaGetSymbolAddress(&p, sym); return (__half*)p; }
static int*   symi(const void* sym) { void* p = nullptr; cudaGetSymbolAddress(&p, sym); return (int*)p; }

static void conv(const float* in, __half* out, size_t n) {
    int n4 = (int)(n / 4);
    conv_f2h<<<(n4 + 255) / 256, 256>>>(in, out, n4);
}

extern "C" void kernel_launch(void* const* d_in, const int* in_sizes, int n_in,
                              void* d_out, int out_size)
{
    const float* x      = (const float*)d_in[0];
    const float* ln1_w  = (const float*)d_in[2];
    const float* ln2_w  = (const float*)d_in[3];
    const float* q_a_w  = (const float*)d_in[4];
    const float* q_a_ln = (const float*)d_in[5];
    const float* q_b_w  = (const float*)d_in[6];
    const float* kv_a_w = (const float*)d_in[7];
    const float* kv_a_ln= (const float*)d_in[8];
    const float* kv_b_w = (const float*)d_in[9];
    const float* o_w    = (const float*)d_in[10];
    const float* rout_w = (const float*)d_in[11];
    const float* rout_b = (const float*)d_in[12];
    const float* gate_w = (const float*)d_in[13];
    const float* up_w   = (const float*)d_in[14];
    const float* down_w = (const float*)d_in[15];
    const float* sg_w   = (const float*)d_in[16];
    const float* su_w   = (const float*)d_in[17];
    const float* sd_w   = (const float*)d_in[18];
    float* out = (float*)d_out;

    __half* wqa  = symh(w_qa);   __half* wkva = symh(w_kva);
    __half* wqb  = symh(w_qb);   __half* wkvb = symh(w_kvb);
    __half* wo   = symh(w_o);
    __half* wg   = symh(w_gate); __half* wu   = symh(w_up);  __half* wd = symh(w_down);
    __half* wsg  = symh(w_sg);   __half* wsu  = symh(w_su);  __half* wsd = symh(w_sd);

    __half* h1h  = symh(a_h1);
    __half* qah  = symh(a_qa);   __half* kvah = symh(a_kva);
    __half* qh   = symh(a_q);    __half* kvh  = symh(a_kv);
    __half* ctxh = symh(a_ctx);  __half* h2h  = symh(a_h2);
    __half* gth  = symh(a_gate); __half* uph  = symh(a_up);
    __half* sgh  = symh(a_sg);   __half* suh  = symh(a_su);

    float* qaf  = symf(g_qa);   float* kvaf = symf(g_kva);
    float* xmid = symf(g_xmid); float* h2f  = symf(g_h2f);
    float* down = symf(g_down); float* shr  = symf(g_shr);
    int* tok = symi(g_tok);     int* off = symi(g_off);

    cudaFuncSetAttribute(gemm_h, cudaFuncAttributeMaxDynamicSharedMemorySize, GSMEM);
    cudaFuncSetAttribute(gemm_h_moe, cudaFuncAttributeMaxDynamicSharedMemorySize, GSMEM);
    cudaFuncSetAttribute(attn_h_kernel, cudaFuncAttributeMaxDynamicSharedMemorySize, ATTN_SMEM);

    // ---- weight conversion ----
    conv(q_a_w,  wqa,  (size_t)QRNK * HDIM);
    conv(kv_a_w, wkva, (size_t)KVRNK * HDIM);
    conv(q_b_w,  wqb,  (size_t)NHEAD * DQK * QRNK);
    conv(kv_b_w, wkvb, (size_t)NHEAD * (DQK + DV) * KVRNK);
    conv(o_w,    wo,   (size_t)HDIM * NHEAD * DV);
    conv(gate_w, wg,   (size_t)NEXP * MINT * HDIM);
    conv(up_w,   wu,   (size_t)NEXP * MINT * HDIM);
    conv(down_w, wd,   (size_t)NEXP * HDIM * MINT);
    conv(sg_w,   wsg,  (size_t)MINT * HDIM);
    conv(su_w,   wsu,  (size_t)MINT * HDIM);
    conv(sd_w,   wsd,  (size_t)HDIM * MINT);

    // ---- attention branch ----
    rmsnorm_h<<<SEQ, 256>>>(x, ln1_w, h1h, nullptr, HDIM);
    gemm_h<<<dim3((QRNK + KVRNK) / BN, SEQ / BM), 256, GSMEM>>>(
        h1h, wqa, qaf, nullptr, nullptr, QRNK, wkva, kvaf, nullptr, KVRNK, SEQ, HDIM);
    rmsnorm_h<<<SEQ, 256>>>(qaf, q_a_ln, qah, nullptr, QRNK);
    rmsnorm_h<<<SEQ, 256>>>(kvaf, kv_a_ln, kvah, nullptr, KVRNK);
    gemm_h<<<dim3(NHEAD * DQK / BN, SEQ / BM), 256, GSMEM>>>(
        qah, wqb, nullptr, qh, nullptr, NHEAD * DQK, nullptr, nullptr, nullptr, 0, SEQ, QRNK);
    gemm_h<<<dim3(NHEAD * (DQK + DV) / BN, SEQ / BM), 256, GSMEM>>>(
        kvah, wkvb, nullptr, kvh, nullptr, NHEAD * (DQK + DV), nullptr, nullptr, nullptr, 0, SEQ, KVRNK);
    rope_h_kernel<<<(SEQ * NHEAD * (ROPED / 2) + 255) / 256, 256>>>();
    attn_h_kernel<<<dim3(SEQ / AQ, NHEAD), 256, ATTN_SMEM>>>();
    gemm_h<<<dim3(HDIM / BN, SEQ / BM), 256, GSMEM>>>(
        ctxh, wo, xmid, nullptr, x, HDIM, nullptr, nullptr, nullptr, 0, SEQ, NHEAD * DV);

    // ---- MoE branch ----
    rmsnorm_h<<<SEQ, 256>>>(xmid, ln2_w, h2h, h2f, HDIM);   // dual-write: fp16 for GEMMs, fp32 for router
    router_kernel<<<SEQ, 128>>>(rout_w, rout_b);
    zero_kernel<<<1, 32>>>();
    topk_kernel<<<SEQ / 256, 256>>>();
    offsets_kernel<<<1, 1>>>();
    scatter_kernel<<<SEQ / 256, 256>>>();

    gemm_h_moe<<<dim3(2 * MINT / BN, SEQ / BM, NEXP), 256, GSMEM>>>(
        h2h, tok, wg, nullptr, gth, MINT, wu, uph, MINT, (size_t)MINT * HDIM, HDIM, off);
    act_h_kernel<<<(unsigned)(((size_t)NSLOT * MINT / 2 + 255) / 256), 256>>>(
        (__half2*)gth, (const __half2*)uph, (size_t)NSLOT * MINT / 2);
    gemm_h_moe<<<dim3(HDIM / BN, SEQ / BM, NEXP), 256, GSMEM>>>(
        gth, nullptr, wd, down, nullptr, HDIM, nullptr, nullptr, 0, (size_t)HDIM * MINT, MINT, off);

    gemm_h<<<dim3(2 * MINT / BN, SEQ / BM), 256, GSMEM>>>(
        h2h, wsg, nullptr, sgh, nullptr, MINT, wsu, nullptr, suh, MINT, SEQ, HDIM);
    act_h_kernel<<<(unsigned)(((size_t)SEQ * MINT / 2 + 255) / 256), 256>>>(
        (__half2*)sgh, (const __half2*)suh, (size_t)SEQ * MINT / 2);
    gemm_h<<<dim3(HDIM / BN, SEQ / BM), 256, GSMEM>>>(
        sgh, wsd, shr, nullptr, nullptr, HDIM, nullptr, nullptr, nullptr, 0, SEQ, MINT);

    combine_kernel<<<SEQ, 256>>>(out);
}

// round 6
// speedup vs baseline: 9.6375x; 1.0824x over previous
#include <cuda_runtime.h>
#include <cuda_fp16.h>
#include <math.h>
#include <stdint.h>

// ---------------- problem constants ----------------
#define SEQ   2048
#define HDIM  2048
#define NHEAD 16
#define DQK   192
#define DV    128
#define NOPE  128
#define ROPED 64
#define QRNK  768
#define KVRNK 512
#define NEXP  16
#define TOPK  4
#define MINT  1024
#define NSLOT (SEQ*TOPK)

// GEMM tiling (fp16, m16n8k16)
#define BM 128
#define BN 128
#define BK 64
#define SKS 72            // smem row stride in halves (64 + 8 pad)
#define GSMEM (2*(BM+BN)*SKS*2)

// attention tiling
#define AQ 128
#define AK 64
#define QST 200
#define KST 200
#define VTS 72
#define PST 72
#define ATTN_SMEM ((AQ*QST + AK*KST + DV*VTS + AQ*PST)*2)

// ---------------- fp32 scratch ----------------
__device__ float g_qa[SEQ*QRNK];
__device__ float g_kva[SEQ*KVRNK];
__device__ float g_xmid[SEQ*HDIM];
__device__ float g_h2f[SEQ*HDIM];
__device__ float g_down[(size_t)NSLOT*HDIM];
__device__ float g_shr[SEQ*HDIM];
__device__ float g_logits[SEQ*NEXP];
__device__ float g_wtop[SEQ*TOPK];
__device__ int   g_topi[SEQ*TOPK];
__device__ int   g_slot[SEQ*TOPK];
__device__ int   g_cnt[NEXP];
__device__ int   g_off[NEXP+1];
__device__ int   g_fill[NEXP];
__device__ int   g_tok[NSLOT];

// ---------------- fp16 weights ----------------
__device__ __half w_qa[QRNK*HDIM];
__device__ __half w_kva[KVRNK*HDIM];
__device__ __half w_qb[NHEAD*DQK*QRNK];
__device__ __half w_kvb[NHEAD*(DQK+DV)*KVRNK];
__device__ __half w_o[HDIM*NHEAD*DV];
__device__ __half w_gate[(size_t)NEXP*MINT*HDIM];
__device__ __half w_up[(size_t)NEXP*MINT*HDIM];
__device__ __half w_down[(size_t)NEXP*HDIM*MINT];
__device__ __half w_sg[MINT*HDIM];
__device__ __half w_su[MINT*HDIM];
__device__ __half w_sd[HDIM*MINT];

// ---------------- fp16 activations ----------------
__device__ __half a_h1[SEQ*HDIM];
__device__ __half a_qa[SEQ*QRNK];
__device__ __half a_kva[SEQ*KVRNK];
__device__ __half a_q[SEQ*NHEAD*DQK];
__device__ __half a_kv[SEQ*NHEAD*(DQK+DV)];
__device__ __half a_ctx[SEQ*NHEAD*DV];
__device__ __half a_h2[SEQ*HDIM];
__device__ __half a_gate[(size_t)NSLOT*MINT];
__device__ __half a_up[(size_t)NSLOT*MINT];
__device__ __half a_sg[SEQ*MINT];
__device__ __half a_su[SEQ*MINT];

// ---------------- helpers ----------------
__device__ __forceinline__ void cp16(uint32_t dst, const void* src, int szbytes) {
    asm volatile("cp.async.cg.shared.global [%0], [%1], 16, %2;\n"
                 :: "r"(dst), "l"(src), "r"(szbytes));
}
__device__ __forceinline__ void cp_commit() { asm volatile("cp.async.commit_group;\n"); }
__device__ __forceinline__ void cp_wait0()  { asm volatile("cp.async.wait_group 0;\n"); }
__device__ __forceinline__ void cp_wait1()  { asm volatile("cp.async.wait_group 1;\n"); }

__device__ __forceinline__ void mma_h(float* c, const uint32_t* a, const uint32_t* b) {
    asm volatile(
        "mma.sync.aligned.m16n8k16.row.col.f32.f16.f16.f32 "
        "{%0,%1,%2,%3}, {%4,%5,%6,%7}, {%8,%9}, {%0,%1,%2,%3};\n"
        : "+f"(c[0]), "+f"(c[1]), "+f"(c[2]), "+f"(c[3])
        : "r"(a[0]), "r"(a[1]), "r"(a[2]), "r"(a[3]), "r"(b[0]), "r"(b[1]));
}
__device__ __forceinline__ void ldm_x4(uint32_t* r, uint32_t addr) {
    asm volatile("ldmatrix.sync.aligned.m8n8.x4.shared.b16 {%0,%1,%2,%3}, [%4];"
                 : "=r"(r[0]), "=r"(r[1]), "=r"(r[2]), "=r"(r[3]) : "r"(addr));
}

// ---------------- fp32 -> fp16 convert ----------------
__global__ void conv_f2h(const float4* __restrict__ in, __half* __restrict__ out, int n4) {
    int i = blockIdx.x * blockDim.x + threadIdx.x;
    if (i >= n4) return;
    float4 v = in[i];
    __half2 p[2];
    p[0] = __floats2half2_rn(v.x, v.y);
    p[1] = __floats2half2_rn(v.z, v.w);
    *(float2*)(out + (size_t)i * 4) = *(float2*)p;
}

// ---------------- fp16 tensor-core GEMM (dual segment: own A,B,K per segment) ----------------
__global__ __launch_bounds__(256, 2) void gemm_h(
    const __half* __restrict__ A1,
    const __half* __restrict__ B1, float* C1, __half* C1h, const float* add1, int N1, int K1,
    const __half* __restrict__ A2,
    const __half* __restrict__ B2, float* C2, __half* C2h, int N2, int K2,
    int M)
{
    extern __shared__ __half smh[];
    __half* As0 = smh;
    __half* Bs0 = smh + 2 * BM * SKS;

    int n0 = blockIdx.x * BN;
    const __half *A, *B; float* C; __half* Ch; const float* addsrc; int N, K;
    if (n0 < N1) { A = A1; B = B1; C = C1; Ch = C1h; addsrc = add1; N = N1; K = K1; }
    else { n0 -= N1; A = A2; B = B2; C = C2; Ch = C2h; addsrc = nullptr; N = N2; K = K2; }

    const int tid = threadIdx.x;
    const int warp = tid >> 5, lane = tid & 31;
    const int g = lane >> 2, tig = lane & 3;
    const int warp_m = (warp & 1) * 64, warp_n = (warp >> 1) * 32;
    const int m0 = blockIdx.y * BM;

    float acc[4][4][4];
#pragma unroll
    for (int a = 0; a < 4; a++)
#pragma unroll
        for (int b = 0; b < 4; b++)
#pragma unroll
            for (int c = 0; c < 4; c++) acc[a][b][c] = 0.f;

    const int nk = K / BK;
    uint32_t smA[2], smB[2];
    smA[0] = (uint32_t)__cvta_generic_to_shared(As0);
    smA[1] = (uint32_t)__cvta_generic_to_shared(As0 + BM * SKS);
    smB[0] = (uint32_t)__cvta_generic_to_shared(Bs0);
    smB[1] = (uint32_t)__cvta_generic_to_shared(Bs0 + BN * SKS);

    // per-thread ldmatrix offsets (bytes)
    const uint32_t aoff = ((warp_m + (lane & 15)) * SKS + ((lane >> 4) << 3)) * 2;
    const uint32_t boff = ((warp_n + ((lane >> 4) & 1) * 8 + (lane & 7)) * SKS
                           + (((lane >> 3) & 1) << 3)) * 2;

    {
#pragma unroll
        for (int i = 0; i < 4; i++) {
            int cid = tid + i * 256;
            int row = cid >> 3, c8 = (cid & 7) << 3;
            cp16(smA[0] + (row * SKS + c8) * 2, A + (size_t)(m0 + row) * K + c8, 16);
        }
#pragma unroll
        for (int i = 0; i < 4; i++) {
            int cid = tid + i * 256;
            int row = cid >> 3, c8 = (cid & 7) << 3;
            cp16(smB[0] + (row * SKS + c8) * 2, B + (size_t)(n0 + row) * K + c8, 16);
        }
        cp_commit();
    }

    for (int kt = 0; kt < nk; kt++) {
        int cur = kt & 1;
        if (kt + 1 < nk) {
            int nb = cur ^ 1;
            int k0 = (kt + 1) * BK;
#pragma unroll
            for (int i = 0; i < 4; i++) {
                int cid = tid + i * 256;
                int row = cid >> 3, c8 = (cid & 7) << 3;
                cp16(smA[nb] + (row * SKS + c8) * 2, A + (size_t)(m0 + row) * K + k0 + c8, 16);
            }
#pragma unroll
            for (int i = 0; i < 4; i++) {
                int cid = tid + i * 256;
                int row = cid >> 3, c8 = (cid & 7) << 3;
                cp16(smB[nb] + (row * SKS + c8) * 2, B + (size_t)(n0 + row) * K + k0 + c8, 16);
            }
            cp_commit();
            cp_wait1();
        } else {
            cp_wait0();
        }
        __syncthreads();

        const uint32_t sA = smA[cur], sB = smB[cur];
#pragma unroll
        for (int ks = 0; ks < 4; ks++) {
            const uint32_t kk2 = ks * 32;   // 16 halves = 32 bytes
            uint32_t af[4][4], bf[4][2];
#pragma unroll
            for (int mt = 0; mt < 4; mt++)
                ldm_x4(af[mt], sA + aoff + mt * 16 * SKS * 2 + kk2);
#pragma unroll
            for (int ntp = 0; ntp < 2; ntp++) {
                uint32_t tmp[4];
                ldm_x4(tmp, sB + boff + ntp * 16 * SKS * 2 + kk2);
                bf[2 * ntp][0] = tmp[0]; bf[2 * ntp][1] = tmp[1];
                bf[2 * ntp + 1][0] = tmp[2]; bf[2 * ntp + 1][1] = tmp[3];
            }
#pragma unroll
            for (int mt = 0; mt < 4; mt++)
#pragma unroll
                for (int nt = 0; nt < 4; nt++)
                    mma_h(acc[mt][nt], af[mt], bf[nt]);
        }
        __syncthreads();
    }

#pragma unroll
    for (int mt = 0; mt < 4; mt++) {
        int r0 = m0 + warp_m + mt * 16 + g;
#pragma unroll
        for (int nt = 0; nt < 4; nt++) {
            int gc = n0 + warp_n + nt * 8 + tig * 2;
            float v0 = acc[mt][nt][0], v1 = acc[mt][nt][1];
            float v2 = acc[mt][nt][2], v3 = acc[mt][nt][3];
            if (addsrc) {
                v0 += addsrc[(size_t)r0 * N + gc];
                v1 += addsrc[(size_t)r0 * N + gc + 1];
                v2 += addsrc[(size_t)(r0 + 8) * N + gc];
                v3 += addsrc[(size_t)(r0 + 8) * N + gc + 1];
            }
            if (C) {
                *(float2*)(C + (size_t)r0 * N + gc) = make_float2(v0, v1);
                *(float2*)(C + (size_t)(r0 + 8) * N + gc) = make_float2(v2, v3);
            }
            if (Ch) {
                *(__half2*)(Ch + (size_t)r0 * N + gc) = __floats2half2_rn(v0, v1);
                *(__half2*)(Ch + (size_t)(r0 + 8) * N + gc) = __floats2half2_rn(v2, v3);
            }
        }
    }
}

// ---------------- fp16 grouped MoE GEMM (dual-B, gathered A) ----------------
__global__ __launch_bounds__(256, 2) void gemm_h_moe(
    const __half* __restrict__ A, const int* __restrict__ gather,
    const __half* __restrict__ B1b, float* C1, __half* C1h, int N1,
    const __half* __restrict__ B2b, __half* C2h, int N2,
    size_t strideB, int K, const int* __restrict__ off)
{
    const int e = blockIdx.z;
    const int start = off[e];
    const int cnt = off[e + 1] - start;
    const int m0 = blockIdx.y * BM;
    if (m0 >= cnt) return;

    int n0 = blockIdx.x * BN;
    const __half* B; float* C; __half* Ch; int N;
    if (n0 < N1) { B = B1b + (size_t)e * strideB; C = C1; Ch = C1h; N = N1; }
    else { n0 -= N1; B = B2b + (size_t)e * strideB; C = nullptr; Ch = C2h; N = N2; }

    extern __shared__ __half smh[];
    __half* As0 = smh;
    __half* Bs0 = smh + 2 * BM * SKS;
    __shared__ int rowmap[BM];

    const int tid = threadIdx.x;
    if (tid < BM) {
        int r = m0 + tid;
        int gr = -1;
        if (r < cnt) gr = gather ? gather[start + r] : (start + r);
        rowmap[tid] = gr;
    }
    __syncthreads();

    const int warp = tid >> 5, lane = tid & 31;
    const int g = lane >> 2, tig = lane & 3;
    const int warp_m = (warp & 1) * 64, warp_n = (warp >> 1) * 32;

    float acc[4][4][4];
#pragma unroll
    for (int a = 0; a < 4; a++)
#pragma unroll
        for (int b = 0; b < 4; b++)
#pragma unroll
            for (int c = 0; c < 4; c++) acc[a][b][c] = 0.f;

    const int nk = K / BK;
    uint32_t smA[2], smB[2];
    smA[0] = (uint32_t)__cvta_generic_to_shared(As0);
    smA[1] = (uint32_t)__cvta_generic_to_shared(As0 + BM * SKS);
    smB[0] = (uint32_t)__cvta_generic_to_shared(Bs0);
    smB[1] = (uint32_t)__cvta_generic_to_shared(Bs0 + BN * SKS);

    const uint32_t aoff = ((warp_m + (lane & 15)) * SKS + ((lane >> 4) << 3)) * 2;
    const uint32_t boff = ((warp_n + ((lane >> 4) & 1) * 8 + (lane & 7)) * SKS
                           + (((lane >> 3) & 1) << 3)) * 2;

    {
#pragma unroll
        for (int i = 0; i < 4; i++) {
            int cid = tid + i * 256;
            int row = cid >> 3, c8 = (cid & 7) << 3;
            int gr = rowmap[row];
            const __half* src = (gr >= 0) ? (A + (size_t)gr * K + c8) : A;
            cp16(smA[0] + (row * SKS + c8) * 2, src, (gr >= 0) ? 16 : 0);
        }
#pragma unroll
        for (int i = 0; i < 4; i++) {
            int cid = tid + i * 256;
            int row = cid >> 3, c8 = (cid & 7) << 3;
            cp16(smB[0] + (row * SKS + c8) * 2, B + (size_t)(n0 + row) * K + c8, 16);
        }
        cp_commit();
    }

    for (int kt = 0; kt < nk; kt++) {
        int cur = kt & 1;
        if (kt + 1 < nk) {
            int nb = cur ^ 1;
            int k0 = (kt + 1) * BK;
#pragma unroll
            for (int i = 0; i < 4; i++) {
                int cid = tid + i * 256;
                int row = cid >> 3, c8 = (cid & 7) << 3;
                int gr = rowmap[row];
                const __half* src = (gr >= 0) ? (A + (size_t)gr * K + k0 + c8) : A;
                cp16(smA[nb] + (row * SKS + c8) * 2, src, (gr >= 0) ? 16 : 0);
            }
#pragma unroll
            for (int i = 0; i < 4; i++) {
                int cid = tid + i * 256;
                int row = cid >> 3, c8 = (cid & 7) << 3;
                cp16(smB[nb] + (row * SKS + c8) * 2, B + (size_t)(n0 + row) * K + k0 + c8, 16);
            }
            cp_commit();
            cp_wait1();
        } else {
            cp_wait0();
        }
        __syncthreads();

        const uint32_t sA = smA[cur], sB = smB[cur];
#pragma unroll
        for (int ks = 0; ks < 4; ks++) {
            const uint32_t kk2 = ks * 32;
            uint32_t af[4][4], bf[4][2];
#pragma unroll
            for (int mt = 0; mt < 4; mt++)
                ldm_x4(af[mt], sA + aoff + mt * 16 * SKS * 2 + kk2);
#pragma unroll
            for (int ntp = 0; ntp < 2; ntp++) {
                uint32_t tmp[4];
                ldm_x4(tmp, sB + boff + ntp * 16 * SKS * 2 + kk2);
                bf[2 * ntp][0] = tmp[0]; bf[2 * ntp][1] = tmp[1];
                bf[2 * ntp + 1][0] = tmp[2]; bf[2 * ntp + 1][1] = tmp[3];
            }
#pragma unroll
            for (int mt = 0; mt < 4; mt++)
#pragma unroll
                for (int nt = 0; nt < 4; nt++)
                    mma_h(acc[mt][nt], af[mt], bf[nt]);
        }
        __syncthreads();
    }

#pragma unroll
    for (int mt = 0; mt < 4; mt++) {
        int r = warp_m + mt * 16 + g;
#pragma unroll
        for (int nt = 0; nt < 4; nt++) {
            int gc = n0 + warp_n + nt * 8 + tig * 2;
            if (m0 + r < cnt) {
                size_t o = (size_t)(start + m0 + r) * N + gc;
                if (C) *(float2*)(C + o) = make_float2(acc[mt][nt][0], acc[mt][nt][1]);
                if (Ch) *(__half2*)(Ch + o) = __floats2half2_rn(acc[mt][nt][0], acc[mt][nt][1]);
            }
            if (m0 + r + 8 < cnt) {
                size_t o = (size_t)(start + m0 + r + 8) * N + gc;
                if (C) *(float2*)(C + o) = make_float2(acc[mt][nt][2], acc[mt][nt][3]);
                if (Ch) *(__half2*)(Ch + o) = __floats2half2_rn(acc[mt][nt][2], acc[mt][nt][3]);
            }
        }
    }
}

// ---------------- fp16 tensor-core flash attention ----------------
__global__ __launch_bounds__(256) void attn_h_kernel() {
    extern __shared__ __half smh[];
    __half* Qs = smh;                     // [AQ][QST]
    __half* Ks = Qs + AQ * QST;           // [AK][KST]
    __half* Vt = Ks + AK * KST;           // [DV][VTS] transposed
    __half* Ps = Vt + DV * VTS;           // [AQ][PST]

    const int h = blockIdx.y;
    const int qb = gridDim.x - 1 - blockIdx.x;
    const int q0 = qb * AQ;
    const int tid = threadIdx.x;
    const int warp = tid >> 5, lane = tid & 31;
    const int g = lane >> 2, tig = lane & 3;
    const int row0 = warp * 16 + g;
    const int qi0 = q0 + row0, qi1 = qi0 + 8;

    const uint32_t smQ = (uint32_t)__cvta_generic_to_shared(Qs);
    const uint32_t smK = (uint32_t)__cvta_generic_to_shared(Ks);
    const uint32_t smV = (uint32_t)__cvta_generic_to_shared(Vt);
    const uint32_t smP = (uint32_t)__cvta_generic_to_shared(Ps);

    const uint32_t qoff = smQ + ((warp * 16 + (lane & 15)) * QST + ((lane >> 4) << 3)) * 2;
    const uint32_t koff = smK + ((((lane >> 4) & 1) * 8 + (lane & 7)) * KST
                                  + (((lane >> 3) & 1) << 3)) * 2;
    const uint32_t poff = smP + ((warp * 16 + (lane & 15)) * PST + ((lane >> 4) << 3)) * 2;
    const uint32_t voff = smV + ((((lane >> 4) & 1) * 8 + (lane & 7)) * VTS
                                  + (((lane >> 3) & 1) << 3)) * 2;

#pragma unroll
    for (int i = 0; i < 12; i++) {
        int idx = tid + i * 256;
        int r = idx / 24, c = (idx % 24) * 8;
        *(float4*)(Qs + r * QST + c) =
            *(const float4*)(a_q + ((size_t)(q0 + r) * NHEAD + h) * DQK + c);
    }

    float acc[16][4];
#pragma unroll
    for (int n = 0; n < 16; n++)
#pragma unroll
        for (int c = 0; c < 4; c++) acc[n][c] = 0.f;
    float m0 = -1e30f, m1 = -1e30f, l0 = 0.f, l1 = 0.f;
    const float scale = 0.07216878364870323f; // 1/sqrt(192)

    const int ntiles = qb * 2 + 2;
    for (int tile = 0; tile < ntiles; tile++) {
        int t0 = tile * AK;
        __syncthreads();
#pragma unroll
        for (int i = 0; i < 6; i++) {
            int idx = tid + i * 256;
            int r = idx / 24, c = (idx % 24) * 8;
            *(float4*)(Ks + r * KST + c) =
                *(const float4*)(a_kv + ((size_t)(t0 + r) * NHEAD + h) * (DQK + DV) + c);
        }
#pragma unroll
        for (int i = 0; i < 16; i++) {
            int idx = tid + i * 256;
            int s = idx >> 6, d2 = idx & 63;
            __half2 v = *(const __half2*)(a_kv + ((size_t)(t0 + s) * NHEAD + h) * (DQK + DV) + DQK + 2 * d2);
            Vt[(2 * d2) * VTS + s] = __low2half(v);
            Vt[(2 * d2 + 1) * VTS + s] = __high2half(v);
        }
        __syncthreads();

        // S = Q @ K^T
        float s[8][4];
#pragma unroll
        for (int n = 0; n < 8; n++)
#pragma unroll
            for (int c = 0; c < 4; c++) s[n][c] = 0.f;
#pragma unroll
        for (int ks = 0; ks < 12; ks++) {
            const uint32_t kk2 = ks * 32;
            uint32_t af[4];
            ldm_x4(af, qoff + kk2);
#pragma unroll
            for (int ntp = 0; ntp < 4; ntp++) {
                uint32_t tmp[4];
                ldm_x4(tmp, koff + ntp * 16 * KST * 2 + kk2);
                mma_h(s[2 * ntp],     af, tmp);
                mma_h(s[2 * ntp + 1], af, tmp + 2);
            }
        }

        const bool domask = (t0 + AK - 1 > q0);
#pragma unroll
        for (int nt = 0; nt < 8; nt++) {
#pragma unroll
            for (int c = 0; c < 4; c++) s[nt][c] *= scale;
            if (domask) {
                int kj = t0 + nt * 8 + tig * 2;
                if (kj > qi0)     s[nt][0] = -1e30f;
                if (kj + 1 > qi0) s[nt][1] = -1e30f;
                if (kj > qi1)     s[nt][2] = -1e30f;
                if (kj + 1 > qi1) s[nt][3] = -1e30f;
            }
        }

        float mx0 = -1e30f, mx1 = -1e30f;
#pragma unroll
        for (int nt = 0; nt < 8; nt++) {
            mx0 = fmaxf(mx0, fmaxf(s[nt][0], s[nt][1]));
            mx1 = fmaxf(mx1, fmaxf(s[nt][2], s[nt][3]));
        }
        mx0 = fmaxf(mx0, __shfl_xor_sync(0xffffffffu, mx0, 1));
        mx0 = fmaxf(mx0, __shfl_xor_sync(0xffffffffu, mx0, 2));
        mx1 = fmaxf(mx1, __shfl_xor_sync(0xffffffffu, mx1, 1));
        mx1 = fmaxf(mx1, __shfl_xor_sync(0xffffffffu, mx1, 2));

        float mn0 = fmaxf(m0, mx0), mn1 = fmaxf(m1, mx1);
        float cf0 = __expf(m0 - mn0), cf1 = __expf(m1 - mn1);
        m0 = mn0; m1 = mn1;

        float sum0 = 0.f, sum1 = 0.f;
#pragma unroll
        for (int nt = 0; nt < 8; nt++) {
            float p0 = __expf(s[nt][0] - m0);
            float p1 = __expf(s[nt][1] - m0);
            float p2 = __expf(s[nt][2] - m1);
            float p3 = __expf(s[nt][3] - m1);
            sum0 += p0 + p1; sum1 += p2 + p3;
            *(__half2*)(Ps + row0 * PST + nt * 8 + tig * 2) = __floats2half2_rn(p0, p1);
            *(__half2*)(Ps + (row0 + 8) * PST + nt * 8 + tig * 2) = __floats2half2_rn(p2, p3);
        }
        sum0 += __shfl_xor_sync(0xffffffffu, sum0, 1);
        sum0 += __shfl_xor_sync(0xffffffffu, sum0, 2);
        sum1 += __shfl_xor_sync(0xffffffffu, sum1, 1);
        sum1 += __shfl_xor_sync(0xffffffffu, sum1, 2);
        l0 = l0 * cf0 + sum0;
        l1 = l1 * cf1 + sum1;
#pragma unroll
        for (int nt = 0; nt < 16; nt++) {
            acc[nt][0] *= cf0; acc[nt][1] *= cf0;
            acc[nt][2] *= cf1; acc[nt][3] *= cf1;
        }
        __syncwarp();

        // O += P @ V
#pragma unroll
        for (int ks = 0; ks < 4; ks++) {
            const uint32_t kk2 = ks * 32;
            uint32_t af[4];
            ldm_x4(af, poff + kk2);
#pragma unroll
            for (int ntp = 0; ntp < 8; ntp++) {
                uint32_t tmp[4];
                ldm_x4(tmp, voff + ntp * 16 * VTS * 2 + kk2);
                mma_h(acc[2 * ntp],     af, tmp);
                mma_h(acc[2 * ntp + 1], af, tmp + 2);
            }
        }
    }

    float inv0 = 1.0f / l0, inv1 = 1.0f / l1;
#pragma unroll
    for (int nt = 0; nt < 16; nt++) {
        int col = h * DV + nt * 8 + tig * 2;
        *(__half2*)(a_ctx + (size_t)qi0 * (NHEAD * DV) + col) =
            __floats2half2_rn(acc[nt][0] * inv0, acc[nt][1] * inv0);
        *(__half2*)(a_ctx + (size_t)qi1 * (NHEAD * DV) + col) =
            __floats2half2_rn(acc[nt][2] * inv1, acc[nt][3] * inv1);
    }
}

// ---------------- RMSNorm fp32 in -> fp16 out (optional fp32 dual-write) ----------------
__global__ void rmsnorm_h(const float* in, const float* w, __half* out, float* outf, int D) {
    int t = blockIdx.x;
    const float* row = in + (size_t)t * D;
    float ss = 0.f;
    for (int i = threadIdx.x; i < D; i += blockDim.x) { float v = row[i]; ss += v * v; }
    __shared__ float sred[32];
    for (int o = 16; o > 0; o >>= 1) ss += __shfl_down_sync(0xffffffffu, ss, o);
    int lane = threadIdx.x & 31, warp = threadIdx.x >> 5;
    if (lane == 0) sred[warp] = ss;
    __syncthreads();
    int nw = blockDim.x >> 5;
    if (threadIdx.x == 0) {
        float tot = 0.f;
        for (int i = 0; i < nw; i++) tot += sred[i];
        sred[0] = 1.0f / sqrtf(tot / (float)D + 1e-6f);
    }
    __syncthreads();
    float scale = sred[0];
    for (int i = threadIdx.x; i < D; i += blockDim.x) {
        float v = row[i] * scale * w[i];
        out[(size_t)t * D + i] = __float2half(v);
        if (outf) outf[(size_t)t * D + i] = v;
    }
}

// ---------------- RoPE (half, in place) ----------------
__global__ void rope_h_kernel() {
    int idx = blockIdx.x * blockDim.x + threadIdx.x;
    int total = SEQ * NHEAD * (ROPED / 2);
    if (idx >= total) return;
    int i = idx & 31;
    int h = (idx >> 5) & (NHEAD - 1);
    int t = idx >> 9;
    float inv_freq = powf(10000.0f, -(float)(2 * i) / (float)ROPED);
    float f = (float)t * inv_freq;
    float c = cosf(f), s = sinf(f);
    __half* qp = a_q + ((size_t)t * NHEAD + h) * DQK + NOPE;
    float x1 = __half2float(qp[i]), x2 = __half2float(qp[i + 32]);
    qp[i] = __float2half(x1 * c - x2 * s);
    qp[i + 32] = __float2half(x2 * c + x1 * s);
    __half* kp = a_kv + ((size_t)t * NHEAD + h) * (DQK + DV) + NOPE;
    x1 = __half2float(kp[i]); x2 = __half2float(kp[i + 32]);
    kp[i] = __float2half(x1 * c - x2 * s);
    kp[i + 32] = __float2half(x2 * c + x1 * s);
}

// ---------------- Router (reads fp32 h2) ----------------
__global__ void router_kernel(const float* __restrict__ rw, const float* __restrict__ rb) {
    int t = blockIdx.x;
    float part[NEXP];
#pragma unroll
    for (int e = 0; e < NEXP; e++) part[e] = 0.f;
    for (int hh = threadIdx.x; hh < HDIM; hh += 128) {
        float xv = g_h2f[(size_t)t * HDIM + hh];
#pragma unroll
        for (int e = 0; e < NEXP; e++) part[e] += xv * rw[(size_t)e * HDIM + hh];
    }
    __shared__ float sred[4][NEXP];
#pragma unroll
    for (int e = 0; e < NEXP; e++)
        for (int o = 16; o > 0; o >>= 1) part[e] += __shfl_down_sync(0xffffffffu, part[e], o);
    int lane = threadIdx.x & 31, warp = threadIdx.x >> 5;
    if (lane == 0)
#pragma unroll
        for (int e = 0; e < NEXP; e++) sred[warp][e] = part[e];
    __syncthreads();
    if (threadIdx.x < NEXP) {
        int e = threadIdx.x;
        g_logits[t * NEXP + e] = sred[0][e] + sred[1][e] + sred[2][e] + sred[3][e] + rb[e];
    }
}

__global__ void zero_kernel() {
    if (threadIdx.x < NEXP) { g_cnt[threadIdx.x] = 0; g_fill[threadIdx.x] = 0; }
}

__global__ void topk_kernel() {
    int t = blockIdx.x * blockDim.x + threadIdx.x;
    if (t >= SEQ) return;
    float p[NEXP];
#pragma unroll
    for (int e = 0; e < NEXP; e++) p[e] = 1.0f / (1.0f + expf(-g_logits[t * NEXP + e]));
    float vals[TOPK]; int ids[TOPK];
    float sum = 0.f;
#pragma unroll
    for (int k = 0; k < TOPK; k++) {
        float best = -1e30f; int bi = 0;
#pragma unroll
        for (int e = 0; e < NEXP; e++)
            if (p[e] > best) { best = p[e]; bi = e; }
        vals[k] = best; ids[k] = bi; p[bi] = -1e30f; sum += best;
    }
    float w = 2.5f / (sum + 1e-9f);
#pragma unroll
    for (int k = 0; k < TOPK; k++) {
        g_wtop[t * TOPK + k] = vals[k] * w;
        g_topi[t * TOPK + k] = ids[k];
        atomicAdd(&g_cnt[ids[k]], 1);
    }
}

__global__ void offsets_kernel() {
    if (threadIdx.x == 0) {
        g_off[0] = 0;
        for (int e = 0; e < NEXP; e++) g_off[e + 1] = g_off[e] + g_cnt[e];
    }
}

__global__ void scatter_kernel() {
    int t = blockIdx.x * blockDim.x + threadIdx.x;
    if (t >= SEQ) return;
#pragma unroll
    for (int k = 0; k < TOPK; k++) {
        int e = g_topi[t * TOPK + k];
        int pos = atomicAdd(&g_fill[e], 1);
        int slot = g_off[e] + pos;
        g_slot[t * TOPK + k] = slot;
        g_tok[slot] = t;
    }
}

// ---------------- SiLU(a)*b, fp16 (writes into a) ----------------
__global__ void act_h_kernel(__half2* a, const __half2* b, size_t n2) {
    size_t i = (size_t)blockIdx.x * blockDim.x + threadIdx.x;
    if (i >= n2) return;
    float2 gg = __half22float2(a[i]);
    float2 uu = __half22float2(b[i]);
    gg.x = gg.x / (1.0f + expf(-gg.x)) * uu.x;
    gg.y = gg.y / (1.0f + expf(-gg.y)) * uu.y;
    a[i] = __floats2half2_rn(gg.x, gg.y);
}

// ---------------- Final combine ----------------
__global__ void combine_kernel(float* out) {
    int t = blockIdx.x;
    float w[TOPK]; int s[TOPK];
#pragma unroll
    for (int k = 0; k < TOPK; k++) { w[k] = g_wtop[t * TOPK + k]; s[k] = g_slot[t * TOPK + k]; }
    for (int hh = threadIdx.x; hh < HDIM; hh += 256) {
        float v = g_xmid[(size_t)t * HDIM + hh] + g_shr[(size_t)t * HDIM + hh];
#pragma unroll
        for (int k = 0; k < TOPK; k++)
            v += w[k] * g_down[(size_t)s[k] * HDIM + hh];
        out[(size_t)t * HDIM + hh] = v;
    }
}

// ---------------- host ----------------
static float* symf(const void* sym) { void* p = nullptr; cudaGetSymbolAddress(&p, sym); return (float*)p; }
static __half* symh(const void* sym) { void* p = nullptr; cudaGetSymbolAddress(&p, sym); return (__half*)p; }
static int*   symi(const void* sym) { void* p = nullptr; cudaGetSymbolAddress(&p, sym); return (int*)p; }

static void conv(const float* in, __half* out, size_t n) {
    int n4 = (int)(n / 4);
    conv_f2h<<<(n4 + 255) / 256, 256>>>((const float4*)in, out, n4);
}

extern "C" void kernel_launch(void* const* d_in, const int* in_sizes, int n_in,
                              void* d_out, int out_size)
{
    const float* x      = (const float*)d_in[0];
    const float* ln1_w  = (const float*)d_in[2];
    const float* ln2_w  = (const float*)d_in[3];
    const float* q_a_w  = (const float*)d_in[4];
    const float* q_a_ln = (const float*)d_in[5];
    const float* q_b_w  = (const float*)d_in[6];
    const float* kv_a_w = (const float*)d_in[7];
    const float* kv_a_ln= (const float*)d_in[8];
    const float* kv_b_w = (const float*)d_in[9];
    const float* o_w    = (const float*)d_in[10];
    const float* rout_w = (const float*)d_in[11];
    const float* rout_b = (const float*)d_in[12];
    const float* gate_w = (const float*)d_in[13];
    const float* up_w   = (const float*)d_in[14];
    const float* down_w = (const float*)d_in[15];
    const float* sg_w   = (const float*)d_in[16];
    const float* su_w   = (const float*)d_in[17];
    const float* sd_w   = (const float*)d_in[18];
    float* out = (float*)d_out;

    __half* wqa  = symh(w_qa);   __half* wkva = symh(w_kva);
    __half* wqb  = symh(w_qb);   __half* wkvb = symh(w_kvb);
    __half* wo   = symh(w_o);
    __half* wg   = symh(w_gate); __half* wu   = symh(w_up);  __half* wd = symh(w_down);
    __half* wsg  = symh(w_sg);   __half* wsu  = symh(w_su);  __half* wsd = symh(w_sd);

    __half* h1h  = symh(a_h1);
    __half* qah  = symh(a_qa);   __half* kvah = symh(a_kva);
    __half* qh   = symh(a_q);    __half* kvh  = symh(a_kv);
    __half* ctxh = symh(a_ctx);  __half* h2h  = symh(a_h2);
    __half* gth  = symh(a_gate); __half* uph  = symh(a_up);
    __half* sgh  = symh(a_sg);   __half* suh  = symh(a_su);

    float* qaf  = symf(g_qa);   float* kvaf = symf(g_kva);
    float* xmid = symf(g_xmid); float* h2f  = symf(g_h2f);
    float* down = symf(g_down); float* shr  = symf(g_shr);
    int* tok = symi(g_tok);     int* off = symi(g_off);

    cudaFuncSetAttribute(gemm_h, cudaFuncAttributeMaxDynamicSharedMemorySize, GSMEM);
    cudaFuncSetAttribute(gemm_h_moe, cudaFuncAttributeMaxDynamicSharedMemorySize, GSMEM);
    cudaFuncSetAttribute(attn_h_kernel, cudaFuncAttributeMaxDynamicSharedMemorySize, ATTN_SMEM);

    // ---- weight conversion ----
    conv(q_a_w,  wqa,  (size_t)QRNK * HDIM);
    conv(kv_a_w, wkva, (size_t)KVRNK * HDIM);
    conv(q_b_w,  wqb,  (size_t)NHEAD * DQK * QRNK);
    conv(kv_b_w, wkvb, (size_t)NHEAD * (DQK + DV) * KVRNK);
    conv(o_w,    wo,   (size_t)HDIM * NHEAD * DV);
    conv(gate_w, wg,   (size_t)NEXP * MINT * HDIM);
    conv(up_w,   wu,   (size_t)NEXP * MINT * HDIM);
    conv(down_w, wd,   (size_t)NEXP * HDIM * MINT);
    conv(sg_w,   wsg,  (size_t)MINT * HDIM);
    conv(su_w,   wsu,  (size_t)MINT * HDIM);
    conv(sd_w,   wsd,  (size_t)HDIM * MINT);

    // ---- attention branch ----
    rmsnorm_h<<<SEQ, 256>>>(x, ln1_w, h1h, nullptr, HDIM);
    // fused q_a + kv_a (same A, same K)
    gemm_h<<<dim3((QRNK + KVRNK) / BN, SEQ / BM), 256, GSMEM>>>(
        h1h, wqa, qaf, nullptr, nullptr, QRNK, HDIM,
        h1h, wkva, kvaf, nullptr, KVRNK, HDIM, SEQ);
    rmsnorm_h<<<SEQ, 256>>>(qaf, q_a_ln, qah, nullptr, QRNK);
    rmsnorm_h<<<SEQ, 256>>>(kvaf, kv_a_ln, kvah, nullptr, KVRNK);
    // fused q_b + kv_b (different A and K per segment)
    gemm_h<<<dim3((NHEAD * DQK + NHEAD * (DQK + DV)) / BN, SEQ / BM), 256, GSMEM>>>(
        qah, wqb, nullptr, qh, nullptr, NHEAD * DQK, QRNK,
        kvah, wkvb, nullptr, kvh, NHEAD * (DQK + DV), KVRNK, SEQ);
    rope_h_kernel<<<(SEQ * NHEAD * (ROPED / 2) + 255) / 256, 256>>>();
    attn_h_kernel<<<dim3(SEQ / AQ, NHEAD), 256, ATTN_SMEM>>>();
    gemm_h<<<dim3(HDIM / BN, SEQ / BM), 256, GSMEM>>>(
        ctxh, wo, xmid, nullptr, x, HDIM, NHEAD * DV,
        nullptr, nullptr, nullptr, nullptr, 0, BK, SEQ);

    // ---- MoE branch ----
    rmsnorm_h<<<SEQ, 256>>>(xmid, ln2_w, h2h, h2f, HDIM);
    router_kernel<<<SEQ, 128>>>(rout_w, rout_b);
    zero_kernel<<<1, 32>>>();
    topk_kernel<<<SEQ / 256, 256>>>();
    offsets_kernel<<<1, 1>>>();
    scatter_kernel<<<SEQ / 256, 256>>>();

    gemm_h_moe<<<dim3(2 * MINT / BN, SEQ / BM, NEXP), 256, GSMEM>>>(
        h2h, tok, wg, nullptr, gth, MINT, wu, uph, MINT, (size_t)MINT * HDIM, HDIM, off);
    act_h_kernel<<<(unsigned)(((size_t)NSLOT * MINT / 2 + 255) / 256), 256>>>(
        (__half2*)gth, (const __half2*)uph, (size_t)NSLOT * MINT / 2);
    gemm_h_moe<<<dim3(HDIM / BN, SEQ / BM, NEXP), 256, GSMEM>>>(
        gth, nullptr, wd, down, nullptr, HDIM, nullptr, nullptr, 0, (size_t)HDIM * MINT, MINT, off);

    // shared expert: fused sg + su
    gemm_h<<<dim3(2 * MINT / BN, SEQ / BM), 256, GSMEM>>>(
        h2h, wsg, nullptr, sgh, nullptr, MINT, HDIM,
        h2h, wsu, nullptr, suh, MINT, HDIM, SEQ);
    act_h_kernel<<<(unsigned)(((size_t)SEQ * MINT / 2 + 255) / 256), 256>>>(
        (__half2*)sgh, (const __half2*)suh, (size_t)SEQ * MINT / 2);
    gemm_h<<<dim3(HDIM / BN, SEQ / BM), 256, GSMEM>>>(
        sgh, wsd, shr, nullptr, nullptr, HDIM, MINT,
        nullptr, nullptr, nullptr, nullptr, 0, BK, SEQ);

    combine_kernel<<<SEQ, 256>>>(out);
}

// round 7
// speedup vs baseline: 9.7360x; 1.0102x over previous
#include <cuda_runtime.h>
#include <cuda_fp16.h>
#include <math.h>
#include <stdint.h>

// ---------------- problem constants ----------------
#define SEQ   2048
#define HDIM  2048
#define NHEAD 16
#define DQK   192
#define DV    128
#define NOPE  128
#define ROPED 64
#define QRNK  768
#define KVRNK 512
#define NEXP  16
#define TOPK  4
#define MINT  1024
#define NSLOT (SEQ*TOPK)

// GEMM tiling (fp16, m16n8k16), 3-stage pipeline
#define BM 128
#define BN 128
#define BK 64
#define SKS 72            // smem row stride in halves (64 + 8 pad)
#define NSTG 3
#define GSMEM (NSTG*(BM+BN)*SKS*2)

// attention tiling
#define AQ 128
#define AK 64
#define QST 200
#define KST 200
#define VTS 72
#define PST 72
#define ATTN_SMEM ((AQ*QST + AK*KST + DV*VTS + AQ*PST)*2)

// ---------------- fp32 scratch ----------------
__device__ float g_qa[SEQ*QRNK];
__device__ float g_kva[SEQ*KVRNK];
__device__ float g_xmid[SEQ*HDIM];
__device__ float g_h2f[SEQ*HDIM];
__device__ float g_shr[SEQ*HDIM];
__device__ float g_logits[SEQ*NEXP];
__device__ float g_wtop[SEQ*TOPK];
__device__ int   g_topi[SEQ*TOPK];
__device__ int   g_slot[SEQ*TOPK];
__device__ int   g_cnt[NEXP];
__device__ int   g_off[NEXP+1];
__device__ int   g_fill[NEXP];
__device__ int   g_tok[NSLOT];

// ---------------- fp16 weights ----------------
__device__ __half w_qa[QRNK*HDIM];
__device__ __half w_kva[KVRNK*HDIM];
__device__ __half w_qb[NHEAD*DQK*QRNK];
__device__ __half w_kvb[NHEAD*(DQK+DV)*KVRNK];
__device__ __half w_o[HDIM*NHEAD*DV];
__device__ __half w_gate[(size_t)NEXP*MINT*HDIM];
__device__ __half w_up[(size_t)NEXP*MINT*HDIM];
__device__ __half w_down[(size_t)NEXP*HDIM*MINT];
__device__ __half w_sg[MINT*HDIM];
__device__ __half w_su[MINT*HDIM];
__device__ __half w_sd[HDIM*MINT];

// ---------------- fp16 activations ----------------
__device__ __half a_h1[SEQ*HDIM];
__device__ __half a_qa[SEQ*QRNK];
__device__ __half a_kva[SEQ*KVRNK];
__device__ __half a_q[SEQ*NHEAD*DQK];
__device__ __half a_kv[SEQ*NHEAD*(DQK+DV)];
__device__ __half a_ctx[SEQ*NHEAD*DV];
__device__ __half a_h2[SEQ*HDIM];
__device__ __half a_gate[(size_t)NSLOT*MINT];
__device__ __half a_up[(size_t)NSLOT*MINT];
__device__ __half a_down[(size_t)NSLOT*HDIM];
__device__ __half a_sg[SEQ*MINT];
__device__ __half a_su[SEQ*MINT];

// ---------------- helpers ----------------
__device__ __forceinline__ void cp16(uint32_t dst, const void* src, int szbytes) {
    asm volatile("cp.async.cg.shared.global [%0], [%1], 16, %2;\n"
                 :: "r"(dst), "l"(src), "r"(szbytes));
}
__device__ __forceinline__ void cp_commit() { asm volatile("cp.async.commit_group;\n"); }
__device__ __forceinline__ void cp_wait1()  { asm volatile("cp.async.wait_group 1;\n"); }

__device__ __forceinline__ void mma_h(float* c, const uint32_t* a, const uint32_t* b) {
    asm volatile(
        "mma.sync.aligned.m16n8k16.row.col.f32.f16.f16.f32 "
        "{%0,%1,%2,%3}, {%4,%5,%6,%7}, {%8,%9}, {%0,%1,%2,%3};\n"
        : "+f"(c[0]), "+f"(c[1]), "+f"(c[2]), "+f"(c[3])
        : "r"(a[0]), "r"(a[1]), "r"(a[2]), "r"(a[3]), "r"(b[0]), "r"(b[1]));
}
__device__ __forceinline__ void ldm_x4(uint32_t* r, uint32_t addr) {
    asm volatile("ldmatrix.sync.aligned.m8n8.x4.shared.b16 {%0,%1,%2,%3}, [%4];"
                 : "=r"(r[0]), "=r"(r[1]), "=r"(r[2]), "=r"(r[3]) : "r"(addr));
}

// ---------------- fp32 -> fp16 convert (4x float4 per thread) ----------------
__global__ void conv_f2h(const float4* __restrict__ in, float4* __restrict__ out, int n16) {
    int i = blockIdx.x * blockDim.x + threadIdx.x;
    if (i >= n16) return;
    float4 v0 = in[4 * (size_t)i + 0];
    float4 v1 = in[4 * (size_t)i + 1];
    float4 v2 = in[4 * (size_t)i + 2];
    float4 v3 = in[4 * (size_t)i + 3];
    __half2 p[8];
    p[0] = __floats2half2_rn(v0.x, v0.y); p[1] = __floats2half2_rn(v0.z, v0.w);
    p[2] = __floats2half2_rn(v1.x, v1.y); p[3] = __floats2half2_rn(v1.z, v1.w);
    p[4] = __floats2half2_rn(v2.x, v2.y); p[5] = __floats2half2_rn(v2.z, v2.w);
    p[6] = __floats2half2_rn(v3.x, v3.y); p[7] = __floats2half2_rn(v3.z, v3.w);
    out[2 * (size_t)i + 0] = *(float4*)&p[0];
    out[2 * (size_t)i + 1] = *(float4*)&p[4];
}

// ---------------- fp16 tensor-core GEMM (dual segment, 3-stage) ----------------
__global__ __launch_bounds__(256, 2) void gemm_h(
    const __half* __restrict__ A1,
    const __half* __restrict__ B1, float* C1, __half* C1h, const float* add1, int N1, int K1,
    const __half* __restrict__ A2,
    const __half* __restrict__ B2, float* C2, __half* C2h, int N2, int K2,
    int M)
{
    extern __shared__ __half smh[];

    int n0 = blockIdx.x * BN;
    const __half *A, *B; float* C; __half* Ch; const float* addsrc; int N, K;
    if (n0 < N1) { A = A1; B = B1; C = C1; Ch = C1h; addsrc = add1; N = N1; K = K1; }
    else { n0 -= N1; A = A2; B = B2; C = C2; Ch = C2h; addsrc = nullptr; N = N2; K = K2; }

    const int tid = threadIdx.x;
    const int warp = tid >> 5, lane = tid & 31;
    const int g = lane >> 2, tig = lane & 3;
    const int warp_m = (warp & 1) * 64, warp_n = (warp >> 1) * 32;
    const int m0 = blockIdx.y * BM;

    float acc[4][4][4];
#pragma unroll
    for (int a = 0; a < 4; a++)
#pragma unroll
        for (int b = 0; b < 4; b++)
#pragma unroll
            for (int c = 0; c < 4; c++) acc[a][b][c] = 0.f;

    const int nk = K / BK;
    uint32_t smA[NSTG], smB[NSTG];
#pragma unroll
    for (int s = 0; s < NSTG; s++) {
        smA[s] = (uint32_t)__cvta_generic_to_shared(smh + s * BM * SKS);
        smB[s] = (uint32_t)__cvta_generic_to_shared(smh + NSTG * BM * SKS + s * BN * SKS);
    }

    const int ldrow = tid >> 3, ldc8 = (tid & 7) << 3;   // base row/col for this thread's 4 chunks
    const uint32_t aoff = ((warp_m + (lane & 15)) * SKS + ((lane >> 4) << 3)) * 2;
    const uint32_t boff = ((warp_n + ((lane >> 4) & 1) * 8 + (lane & 7)) * SKS
                           + (((lane >> 3) & 1) << 3)) * 2;

    // prologue: 2 tiles
#pragma unroll
    for (int s = 0; s < 2; s++) {
        int k0 = s * BK;
#pragma unroll
        for (int i = 0; i < 4; i++) {
            int row = ldrow + i * 32;
            cp16(smA[s] + (row * SKS + ldc8) * 2, A + (size_t)(m0 + row) * K + k0 + ldc8, 16);
        }
#pragma unroll
        for (int i = 0; i < 4; i++) {
            int row = ldrow + i * 32;
            cp16(smB[s] + (row * SKS + ldc8) * 2, B + (size_t)(n0 + row) * K + k0 + ldc8, 16);
        }
        cp_commit();
    }

    int cur = 0, pf = 2;
    for (int kt = 0; kt < nk; kt++) {
        cp_wait1();
        __syncthreads();
        if (kt + 2 < nk) {
            int k0 = (kt + 2) * BK;
#pragma unroll
            for (int i = 0; i < 4; i++) {
                int row = ldrow + i * 32;
                cp16(smA[pf] + (row * SKS + ldc8) * 2, A + (size_t)(m0 + row) * K + k0 + ldc8, 16);
            }
#pragma unroll
            for (int i = 0; i < 4; i++) {
                int row = ldrow + i * 32;
                cp16(smB[pf] + (row * SKS + ldc8) * 2, B + (size_t)(n0 + row) * K + k0 + ldc8, 16);
            }
        }
        cp_commit();

        const uint32_t sA = smA[cur], sB = smB[cur];
#pragma unroll
        for (int ks = 0; ks < 4; ks++) {
            const uint32_t kk2 = ks * 32;
            uint32_t af[4][4], bf[4][2];
#pragma unroll
            for (int mt = 0; mt < 4; mt++)
                ldm_x4(af[mt], sA + aoff + mt * 16 * SKS * 2 + kk2);
#pragma unroll
            for (int ntp = 0; ntp < 2; ntp++) {
                uint32_t tmp[4];
                ldm_x4(tmp, sB + boff + ntp * 16 * SKS * 2 + kk2);
                bf[2 * ntp][0] = tmp[0]; bf[2 * ntp][1] = tmp[1];
                bf[2 * ntp + 1][0] = tmp[2]; bf[2 * ntp + 1][1] = tmp[3];
            }
#pragma unroll
            for (int mt = 0; mt < 4; mt++)
#pragma unroll
                for (int nt = 0; nt < 4; nt++)
                    mma_h(acc[mt][nt], af[mt], bf[nt]);
        }
        cur = (cur + 1 == NSTG) ? 0 : cur + 1;
        pf = (pf + 1 == NSTG) ? 0 : pf + 1;
    }

#pragma unroll
    for (int mt = 0; mt < 4; mt++) {
        int r0 = m0 + warp_m + mt * 16 + g;
#pragma unroll
        for (int nt = 0; nt < 4; nt++) {
            int gc = n0 + warp_n + nt * 8 + tig * 2;
            float v0 = acc[mt][nt][0], v1 = acc[mt][nt][1];
            float v2 = acc[mt][nt][2], v3 = acc[mt][nt][3];
            if (addsrc) {
                v0 += addsrc[(size_t)r0 * N + gc];
                v1 += addsrc[(size_t)r0 * N + gc + 1];
                v2 += addsrc[(size_t)(r0 + 8) * N + gc];
                v3 += addsrc[(size_t)(r0 + 8) * N + gc + 1];
            }
            if (C) {
                *(float2*)(C + (size_t)r0 * N + gc) = make_float2(v0, v1);
                *(float2*)(C + (size_t)(r0 + 8) * N + gc) = make_float2(v2, v3);
            }
            if (Ch) {
                *(__half2*)(Ch + (size_t)r0 * N + gc) = __floats2half2_rn(v0, v1);
                *(__half2*)(Ch + (size_t)(r0 + 8) * N + gc) = __floats2half2_rn(v2, v3);
            }
        }
    }
}

// ---------------- fp16 grouped MoE GEMM (dual-B, gathered A, 3-stage) ----------------
__global__ __launch_bounds__(256, 2) void gemm_h_moe(
    const __half* __restrict__ A, const int* __restrict__ gather,
    const __half* __restrict__ B1b, __half* C1h, int N1,
    const __half* __restrict__ B2b, __half* C2h, int N2,
    size_t strideB, int K, const int* __restrict__ off)
{
    const int e = blockIdx.z;
    const int start = off[e];
    const int cnt = off[e + 1] - start;
    const int m0 = blockIdx.y * BM;
    if (m0 >= cnt) return;

    int n0 = blockIdx.x * BN;
    const __half* B; __half* Ch; int N;
    if (n0 < N1) { B = B1b + (size_t)e * strideB; Ch = C1h; N = N1; }
    else { n0 -= N1; B = B2b + (size_t)e * strideB; Ch = C2h; N = N2; }

    extern __shared__ __half smh[];
    __shared__ int rowmap[BM];

    const int tid = threadIdx.x;
    if (tid < BM) {
        int r = m0 + tid;
        int gr = -1;
        if (r < cnt) gr = gather ? gather[start + r] : (start + r);
        rowmap[tid] = gr;
    }
    __syncthreads();

    const int warp = tid >> 5, lane = tid & 31;
    const int g = lane >> 2, tig = lane & 3;
    const int warp_m = (warp & 1) * 64, warp_n = (warp >> 1) * 32;

    float acc[4][4][4];
#pragma unroll
    for (int a = 0; a < 4; a++)
#pragma unroll
        for (int b = 0; b < 4; b++)
#pragma unroll
            for (int c = 0; c < 4; c++) acc[a][b][c] = 0.f;

    const int nk = K / BK;
    uint32_t smA[NSTG], smB[NSTG];
#pragma unroll
    for (int s = 0; s < NSTG; s++) {
        smA[s] = (uint32_t)__cvta_generic_to_shared(smh + s * BM * SKS);
        smB[s] = (uint32_t)__cvta_generic_to_shared(smh + NSTG * BM * SKS + s * BN * SKS);
    }

    const int ldrow = tid >> 3, ldc8 = (tid & 7) << 3;
    const int grow[4] = { rowmap[ldrow], rowmap[ldrow + 32], rowmap[ldrow + 64], rowmap[ldrow + 96] };
    const uint32_t aoff = ((warp_m + (lane & 15)) * SKS + ((lane >> 4) << 3)) * 2;
    const uint32_t boff = ((warp_n + ((lane >> 4) & 1) * 8 + (lane & 7)) * SKS
                           + (((lane >> 3) & 1) << 3)) * 2;

#pragma unroll
    for (int s = 0; s < 2; s++) {
        int k0 = s * BK;
#pragma unroll
        for (int i = 0; i < 4; i++) {
            int row = ldrow + i * 32;
            const __half* src = (grow[i] >= 0) ? (A + (size_t)grow[i] * K + k0 + ldc8) : A;
            cp16(smA[s] + (row * SKS + ldc8) * 2, src, (grow[i] >= 0) ? 16 : 0);
        }
#pragma unroll
        for (int i = 0; i < 4; i++) {
            int row = ldrow + i * 32;
            cp16(smB[s] + (row * SKS + ldc8) * 2, B + (size_t)(n0 + row) * K + k0 + ldc8, 16);
        }
        cp_commit();
    }

    int cur = 0, pf = 2;
    for (int kt = 0; kt < nk; kt++) {
        cp_wait1();
        __syncthreads();
        if (kt + 2 < nk) {
            int k0 = (kt + 2) * BK;
#pragma unroll
            for (int i = 0; i < 4; i++) {
                int row = ldrow + i * 32;
                const __half* src = (grow[i] >= 0) ? (A + (size_t)grow[i] * K + k0 + ldc8) : A;
                cp16(smA[pf] + (row * SKS + ldc8) * 2, src, (grow[i] >= 0) ? 16 : 0);
            }
#pragma unroll
            for (int i = 0; i < 4; i++) {
                int row = ldrow + i * 32;
                cp16(smB[pf] + (row * SKS + ldc8) * 2, B + (size_t)(n0 + row) * K + k0 + ldc8, 16);
            }
        }
        cp_commit();

        const uint32_t sA = smA[cur], sB = smB[cur];
#pragma unroll
        for (int ks = 0; ks < 4; ks++) {
            const uint32_t kk2 = ks * 32;
            uint32_t af[4][4], bf[4][2];
#pragma unroll
            for (int mt = 0; mt < 4; mt++)
                ldm_x4(af[mt], sA + aoff + mt * 16 * SKS * 2 + kk2);
#pragma unroll
            for (int ntp = 0; ntp < 2; ntp++) {
                uint32_t tmp[4];
                ldm_x4(tmp, sB + boff + ntp * 16 * SKS * 2 + kk2);
                bf[2 * ntp][0] = tmp[0]; bf[2 * ntp][1] = tmp[1];
                bf[2 * ntp + 1][0] = tmp[2]; bf[2 * ntp + 1][1] = tmp[3];
            }
#pragma unroll
            for (int mt = 0; mt < 4; mt++)
#pragma unroll
                for (int nt = 0; nt < 4; nt++)
                    mma_h(acc[mt][nt], af[mt], bf[nt]);
        }
        cur = (cur + 1 == NSTG) ? 0 : cur + 1;
        pf = (pf + 1 == NSTG) ? 0 : pf + 1;
    }

#pragma unroll
    for (int mt = 0; mt < 4; mt++) {
        int r = warp_m + mt * 16 + g;
#pragma unroll
        for (int nt = 0; nt < 4; nt++) {
            int gc = n0 + warp_n + nt * 8 + tig * 2;
            if (m0 + r < cnt)
                *(__half2*)(Ch + (size_t)(start + m0 + r) * N + gc) =
                    __floats2half2_rn(acc[mt][nt][0], acc[mt][nt][1]);
            if (m0 + r + 8 < cnt)
                *(__half2*)(Ch + (size_t)(start + m0 + r + 8) * N + gc) =
                    __floats2half2_rn(acc[mt][nt][2], acc[mt][nt][3]);
        }
    }
}

// ---------------- fp16 tensor-core flash attention ----------------
__global__ __launch_bounds__(256) void attn_h_kernel() {
    extern __shared__ __half smh[];
    __half* Qs = smh;
    __half* Ks = Qs + AQ * QST;
    __half* Vt = Ks + AK * KST;
    __half* Ps = Vt + DV * VTS;

    const int h = blockIdx.y;
    const int qb = gridDim.x - 1 - blockIdx.x;
    const int q0 = qb * AQ;
    const int tid = threadIdx.x;
    const int warp = tid >> 5, lane = tid & 31;
    const int g = lane >> 2, tig = lane & 3;
    const int row0 = warp * 16 + g;
    const int qi0 = q0 + row0, qi1 = qi0 + 8;

    const uint32_t smQ = (uint32_t)__cvta_generic_to_shared(Qs);
    const uint32_t smK = (uint32_t)__cvta_generic_to_shared(Ks);
    const uint32_t smV = (uint32_t)__cvta_generic_to_shared(Vt);
    const uint32_t smP = (uint32_t)__cvta_generic_to_shared(Ps);

    const uint32_t qoff = smQ + ((warp * 16 + (lane & 15)) * QST + ((lane >> 4) << 3)) * 2;
    const uint32_t koff = smK + ((((lane >> 4) & 1) * 8 + (lane & 7)) * KST
                                  + (((lane >> 3) & 1) << 3)) * 2;
    const uint32_t poff = smP + ((warp * 16 + (lane & 15)) * PST + ((lane >> 4) << 3)) * 2;
    const uint32_t voff = smV + ((((lane >> 4) & 1) * 8 + (lane & 7)) * VTS
                                  + (((lane >> 3) & 1) << 3)) * 2;

#pragma unroll
    for (int i = 0; i < 12; i++) {
        int idx = tid + i * 256;
        int r = idx / 24, c = (idx % 24) * 8;
        *(float4*)(Qs + r * QST + c) =
            *(const float4*)(a_q + ((size_t)(q0 + r) * NHEAD + h) * DQK + c);
    }

    float acc[16][4];
#pragma unroll
    for (int n = 0; n < 16; n++)
#pragma unroll
        for (int c = 0; c < 4; c++) acc[n][c] = 0.f;
    float m0 = -1e30f, m1 = -1e30f, l0 = 0.f, l1 = 0.f;
    const float scale = 0.07216878364870323f; // 1/sqrt(192)

    const int ntiles = qb * 2 + 2;
    for (int tile = 0; tile < ntiles; tile++) {
        int t0 = tile * AK;
        __syncthreads();
#pragma unroll
        for (int i = 0; i < 6; i++) {
            int idx = tid + i * 256;
            int r = idx / 24, c = (idx % 24) * 8;
            *(float4*)(Ks + r * KST + c) =
                *(const float4*)(a_kv + ((size_t)(t0 + r) * NHEAD + h) * (DQK + DV) + c);
        }
#pragma unroll
        for (int i = 0; i < 16; i++) {
            int idx = tid + i * 256;
            int s = idx >> 6, d2 = idx & 63;
            __half2 v = *(const __half2*)(a_kv + ((size_t)(t0 + s) * NHEAD + h) * (DQK + DV) + DQK + 2 * d2);
            Vt[(2 * d2) * VTS + s] = __low2half(v);
            Vt[(2 * d2 + 1) * VTS + s] = __high2half(v);
        }
        __syncthreads();

        float s[8][4];
#pragma unroll
        for (int n = 0; n < 8; n++)
#pragma unroll
            for (int c = 0; c < 4; c++) s[n][c] = 0.f;
#pragma unroll
        for (int ks = 0; ks < 12; ks++) {
            const uint32_t kk2 = ks * 32;
            uint32_t af[4];
            ldm_x4(af, qoff + kk2);
#pragma unroll
            for (int ntp = 0; ntp < 4; ntp++) {
                uint32_t tmp[4];
                ldm_x4(tmp, koff + ntp * 16 * KST * 2 + kk2);
                mma_h(s[2 * ntp],     af, tmp);
                mma_h(s[2 * ntp + 1], af, tmp + 2);
            }
        }

        const bool domask = (t0 + AK - 1 > q0);
#pragma unroll
        for (int nt = 0; nt < 8; nt++) {
#pragma unroll
            for (int c = 0; c < 4; c++) s[nt][c] *= scale;
            if (domask) {
                int kj = t0 + nt * 8 + tig * 2;
                if (kj > qi0)     s[nt][0] = -1e30f;
                if (kj + 1 > qi0) s[nt][1] = -1e30f;
                if (kj > qi1)     s[nt][2] = -1e30f;
                if (kj + 1 > qi1) s[nt][3] = -1e30f;
            }
        }

        float mx0 = -1e30f, mx1 = -1e30f;
#pragma unroll
        for (int nt = 0; nt < 8; nt++) {
            mx0 = fmaxf(mx0, fmaxf(s[nt][0], s[nt][1]));
            mx1 = fmaxf(mx1, fmaxf(s[nt][2], s[nt][3]));
        }
        mx0 = fmaxf(mx0, __shfl_xor_sync(0xffffffffu, mx0, 1));
        mx0 = fmaxf(mx0, __shfl_xor_sync(0xffffffffu, mx0, 2));
        mx1 = fmaxf(mx1, __shfl_xor_sync(0xffffffffu, mx1, 1));
        mx1 = fmaxf(mx1, __shfl_xor_sync(0xffffffffu, mx1, 2));

        float mn0 = fmaxf(m0, mx0), mn1 = fmaxf(m1, mx1);
        float cf0 = __expf(m0 - mn0), cf1 = __expf(m1 - mn1);
        m0 = mn0; m1 = mn1;

        float sum0 = 0.f, sum1 = 0.f;
#pragma unroll
        for (int nt = 0; nt < 8; nt++) {
            float p0 = __expf(s[nt][0] - m0);
            float p1 = __expf(s[nt][1] - m0);
            float p2 = __expf(s[nt][2] - m1);
            float p3 = __expf(s[nt][3] - m1);
            sum0 += p0 + p1; sum1 += p2 + p3;
            *(__half2*)(Ps + row0 * PST + nt * 8 + tig * 2) = __floats2half2_rn(p0, p1);
            *(__half2*)(Ps + (row0 + 8) * PST + nt * 8 + tig * 2) = __floats2half2_rn(p2, p3);
        }
        sum0 += __shfl_xor_sync(0xffffffffu, sum0, 1);
        sum0 += __shfl_xor_sync(0xffffffffu, sum0, 2);
        sum1 += __shfl_xor_sync(0xffffffffu, sum1, 1);
        sum1 += __shfl_xor_sync(0xffffffffu, sum1, 2);
        l0 = l0 * cf0 + sum0;
        l1 = l1 * cf1 + sum1;
#pragma unroll
        for (int nt = 0; nt < 16; nt++) {
            acc[nt][0] *= cf0; acc[nt][1] *= cf0;
            acc[nt][2] *= cf1; acc[nt][3] *= cf1;
        }
        __syncwarp();

#pragma unroll
        for (int ks = 0; ks < 4; ks++) {
            const uint32_t kk2 = ks * 32;
            uint32_t af[4];
            ldm_x4(af, poff + kk2);
#pragma unroll
            for (int ntp = 0; ntp < 8; ntp++) {
                uint32_t tmp[4];
                ldm_x4(tmp, voff + ntp * 16 * VTS * 2 + kk2);
                mma_h(acc[2 * ntp],     af, tmp);
                mma_h(acc[2 * ntp + 1], af, tmp + 2);
            }
        }
    }

    float inv0 = 1.0f / l0, inv1 = 1.0f / l1;
#pragma unroll
    for (int nt = 0; nt < 16; nt++) {
        int col = h * DV + nt * 8 + tig * 2;
        *(__half2*)(a_ctx + (size_t)qi0 * (NHEAD * DV) + col) =
            __floats2half2_rn(acc[nt][0] * inv0, acc[nt][1] * inv0);
        *(__half2*)(a_ctx + (size_t)qi1 * (NHEAD * DV) + col) =
            __floats2half2_rn(acc[nt][2] * inv1, acc[nt][3] * inv1);
    }
}

// ---------------- RMSNorm fp32 in -> fp16 out (optional fp32 dual-write) ----------------
__global__ void rmsnorm_h(const float* in, const float* w, __half* out, float* outf, int D) {
    int t = blockIdx.x;
    const float* row = in + (size_t)t * D;
    float ss = 0.f;
    for (int i = threadIdx.x; i < D; i += blockDim.x) { float v = row[i]; ss += v * v; }
    __shared__ float sred[32];
    for (int o = 16; o > 0; o >>= 1) ss += __shfl_down_sync(0xffffffffu, ss, o);
    int lane = threadIdx.x & 31, warp = threadIdx.x >> 5;
    if (lane == 0) sred[warp] = ss;
    __syncthreads();
    int nw = blockDim.x >> 5;
    if (threadIdx.x == 0) {
        float tot = 0.f;
        for (int i = 0; i < nw; i++) tot += sred[i];
        sred[0] = 1.0f / sqrtf(tot / (float)D + 1e-6f);
    }
    __syncthreads();
    float scale = sred[0];
    for (int i = threadIdx.x; i < D; i += blockDim.x) {
        float v = row[i] * scale * w[i];
        out[(size_t)t * D + i] = __float2half(v);
        if (outf) outf[(size_t)t * D + i] = v;
    }
}

// ---------------- RoPE (half, in place) ----------------
__global__ void rope_h_kernel() {
    int idx = blockIdx.x * blockDim.x + threadIdx.x;
    int total = SEQ * NHEAD * (ROPED / 2);
    if (idx >= total) return;
    int i = idx & 31;
    int h = (idx >> 5) & (NHEAD - 1);
    int t = idx >> 9;
    float inv_freq = powf(10000.0f, -(float)(2 * i) / (float)ROPED);
    float f = (float)t * inv_freq;
    float c = cosf(f), s = sinf(f);
    __half* qp = a_q + ((size_t)t * NHEAD + h) * DQK + NOPE;
    float x1 = __half2float(qp[i]), x2 = __half2float(qp[i + 32]);
    qp[i] = __float2half(x1 * c - x2 * s);
    qp[i + 32] = __float2half(x2 * c + x1 * s);
    __half* kp = a_kv + ((size_t)t * NHEAD + h) * (DQK + DV) + NOPE;
    x1 = __half2float(kp[i]); x2 = __half2float(kp[i + 32]);
    kp[i] = __float2half(x1 * c - x2 * s);
    kp[i + 32] = __float2half(x2 * c + x1 * s);
}

// ---------------- Router (reads fp32 h2) ----------------
__global__ void router_kernel(const float* __restrict__ rw, const float* __restrict__ rb) {
    int t = blockIdx.x;
    float part[NEXP];
#pragma unroll
    for (int e = 0; e < NEXP; e++) part[e] = 0.f;
    for (int hh = threadIdx.x; hh < HDIM; hh += 128) {
        float xv = g_h2f[(size_t)t * HDIM + hh];
#pragma unroll
        for (int e = 0; e < NEXP; e++) part[e] += xv * rw[(size_t)e * HDIM + hh];
    }
    __shared__ float sred[4][NEXP];
#pragma unroll
    for (int e = 0; e < NEXP; e++)
        for (int o = 16; o > 0; o >>= 1) part[e] += __shfl_down_sync(0xffffffffu, part[e], o);
    int lane = threadIdx.x & 31, warp = threadIdx.x >> 5;
    if (lane == 0)
#pragma unroll
        for (int e = 0; e < NEXP; e++) sred[warp][e] = part[e];
    __syncthreads();
    if (threadIdx.x < NEXP) {
        int e = threadIdx.x;
        g_logits[t * NEXP + e] = sred[0][e] + sred[1][e] + sred[2][e] + sred[3][e] + rb[e];
    }
}

__global__ void zero_kernel() {
    if (threadIdx.x < NEXP) { g_cnt[threadIdx.x] = 0; g_fill[threadIdx.x] = 0; }
}

__global__ void topk_kernel() {
    int t = blockIdx.x * blockDim.x + threadIdx.x;
    if (t >= SEQ) return;
    float p[NEXP];
#pragma unroll
    for (int e = 0; e < NEXP; e++) p[e] = 1.0f / (1.0f + expf(-g_logits[t * NEXP + e]));
    float vals[TOPK]; int ids[TOPK];
    float sum = 0.f;
#pragma unroll
    for (int k = 0; k < TOPK; k++) {
        float best = -1e30f; int bi = 0;
#pragma unroll
        for (int e = 0; e < NEXP; e++)
            if (p[e] > best) { best = p[e]; bi = e; }
        vals[k] = best; ids[k] = bi; p[bi] = -1e30f; sum += best;
    }
    float w = 2.5f / (sum + 1e-9f);
#pragma unroll
    for (int k = 0; k < TOPK; k++) {
        g_wtop[t * TOPK + k] = vals[k] * w;
        g_topi[t * TOPK + k] = ids[k];
        atomicAdd(&g_cnt[ids[k]], 1);
    }
}

__global__ void offsets_kernel() {
    if (threadIdx.x == 0) {
        g_off[0] = 0;
        for (int e = 0; e < NEXP; e++) g_off[e + 1] = g_off[e] + g_cnt[e];
    }
}

__global__ void scatter_kernel() {
    int t = blockIdx.x * blockDim.x + threadIdx.x;
    if (t >= SEQ) return;
#pragma unroll
    for (int k = 0; k < TOPK; k++) {
        int e = g_topi[t * TOPK + k];
        int pos = atomicAdd(&g_fill[e], 1);
        int slot = g_off[e] + pos;
        g_slot[t * TOPK + k] = slot;
        g_tok[slot] = t;
    }
}

// ---------------- SiLU(a)*b, fp16 (writes into a) ----------------
__global__ void act_h_kernel(__half2* a, const __half2* b, size_t n2) {
    size_t i = (size_t)blockIdx.x * blockDim.x + threadIdx.x;
    if (i >= n2) return;
    float2 gg = __half22float2(a[i]);
    float2 uu = __half22float2(b[i]);
    gg.x = gg.x / (1.0f + expf(-gg.x)) * uu.x;
    gg.y = gg.y / (1.0f + expf(-gg.y)) * uu.y;
    a[i] = __floats2half2_rn(gg.x, gg.y);
}

// ---------------- Final combine (routed now fp16) ----------------
__global__ void combine_kernel(float* out) {
    int t = blockIdx.x;
    float w[TOPK]; int s[TOPK];
#pragma unroll
    for (int k = 0; k < TOPK; k++) { w[k] = g_wtop[t * TOPK + k]; s[k] = g_slot[t * TOPK + k]; }
    for (int hh = threadIdx.x; hh < HDIM; hh += 256) {
        float v = g_xmid[(size_t)t * HDIM + hh] + g_shr[(size_t)t * HDIM + hh];
#pragma unroll
        for (int k = 0; k < TOPK; k++)
            v += w[k] * __half2float(a_down[(size_t)s[k] * HDIM + hh]);
        out[(size_t)t * HDIM + hh] = v;
    }
}

// ---------------- host ----------------
static float* symf(const void* sym) { void* p = nullptr; cudaGetSymbolAddress(&p, sym); return (float*)p; }
static __half* symh(const void* sym) { void* p = nullptr; cudaGetSymbolAddress(&p, sym); return (__half*)p; }
static int*   symi(const void* sym) { void* p = nullptr; cudaGetSymbolAddress(&p, sym); return (int*)p; }

static void conv(const float* in, __half* out, size_t n) {
    int n16 = (int)(n / 16);
    conv_f2h<<<(n16 + 255) / 256, 256>>>((const float4*)in, (float4*)out, n16);
}

extern "C" void kernel_launch(void* const* d_in, const int* in_sizes, int n_in,
                              void* d_out, int out_size)
{
    const float* x      = (const float*)d_in[0];
    const float* ln1_w  = (const float*)d_in[2];
    const float* ln2_w  = (const float*)d_in[3];
    const float* q_a_w  = (const float*)d_in[4];
    const float* q_a_ln = (const float*)d_in[5];
    const float* q_b_w  = (const float*)d_in[6];
    const float* kv_a_w = (const float*)d_in[7];
    const float* kv_a_ln= (const float*)d_in[8];
    const float* kv_b_w = (const float*)d_in[9];
    const float* o_w    = (const float*)d_in[10];
    const float* rout_w = (const float*)d_in[11];
    const float* rout_b = (const float*)d_in[12];
    const float* gate_w = (const float*)d_in[13];
    const float* up_w   = (const float*)d_in[14];
    const float* down_w = (const float*)d_in[15];
    const float* sg_w   = (const float*)d_in[16];
    const float* su_w   = (const float*)d_in[17];
    const float* sd_w   = (const float*)d_in[18];
    float* out = (float*)d_out;

    __half* wqa  = symh(w_qa);   __half* wkva = symh(w_kva);
    __half* wqb  = symh(w_qb);   __half* wkvb = symh(w_kvb);
    __half* wo   = symh(w_o);
    __half* wg   = symh(w_gate); __half* wu   = symh(w_up);  __half* wd = symh(w_down);
    __half* wsg  = symh(w_sg);   __half* wsu  = symh(w_su);  __half* wsd = symh(w_sd);

    __half* h1h  = symh(a_h1);
    __half* qah  = symh(a_qa);   __half* kvah = symh(a_kva);
    __half* qh   = symh(a_q);    __half* kvh  = symh(a_kv);
    __half* ctxh = symh(a_ctx);  __half* h2h  = symh(a_h2);
    __half* gth  = symh(a_gate); __half* uph  = symh(a_up);
    __half* dnh  = symh(a_down);
    __half* sgh  = symh(a_sg);   __half* suh  = symh(a_su);

    float* qaf  = symf(g_qa);   float* kvaf = symf(g_kva);
    float* xmid = symf(g_xmid); float* h2f  = symf(g_h2f);
    float* shr  = symf(g_shr);
    int* tok = symi(g_tok);     int* off = symi(g_off);

    cudaFuncSetAttribute(gemm_h, cudaFuncAttributeMaxDynamicSharedMemorySize, GSMEM);
    cudaFuncSetAttribute(gemm_h_moe, cudaFuncAttributeMaxDynamicSharedMemorySize, GSMEM);
    cudaFuncSetAttribute(attn_h_kernel, cudaFuncAttributeMaxDynamicSharedMemorySize, ATTN_SMEM);

    // ---- weight conversion ----
    conv(q_a_w,  wqa,  (size_t)QRNK * HDIM);
    conv(kv_a_w, wkva, (size_t)KVRNK * HDIM);
    conv(q_b_w,  wqb,  (size_t)NHEAD * DQK * QRNK);
    conv(kv_b_w, wkvb, (size_t)NHEAD * (DQK + DV) * KVRNK);
    conv(o_w,    wo,   (size_t)HDIM * NHEAD * DV);
    conv(gate_w, wg,   (size_t)NEXP * MINT * HDIM);
    conv(up_w,   wu,   (size_t)NEXP * MINT * HDIM);
    conv(down_w, wd,   (size_t)NEXP * HDIM * MINT);
    conv(sg_w,   wsg,  (size_t)MINT * HDIM);
    conv(su_w,   wsu,  (size_t)MINT * HDIM);
    conv(sd_w,   wsd,  (size_t)HDIM * MINT);

    // ---- attention branch ----
    rmsnorm_h<<<SEQ, 256>>>(x, ln1_w, h1h, nullptr, HDIM);
    gemm_h<<<dim3((QRNK + KVRNK) / BN, SEQ / BM), 256, GSMEM>>>(
        h1h, wqa, qaf, nullptr, nullptr, QRNK, HDIM,
        h1h, wkva, kvaf, nullptr, KVRNK, HDIM, SEQ);
    rmsnorm_h<<<SEQ, 256>>>(qaf, q_a_ln, qah, nullptr, QRNK);
    rmsnorm_h<<<SEQ, 256>>>(kvaf, kv_a_ln, kvah, nullptr, KVRNK);
    gemm_h<<<dim3((NHEAD * DQK + NHEAD * (DQK + DV)) / BN, SEQ / BM), 256, GSMEM>>>(
        qah, wqb, nullptr, qh, nullptr, NHEAD * DQK, QRNK,
        kvah, wkvb, nullptr, kvh, NHEAD * (DQK + DV), KVRNK, SEQ);
    rope_h_kernel<<<(SEQ * NHEAD * (ROPED / 2) + 255) / 256, 256>>>();
    attn_h_kernel<<<dim3(SEQ / AQ, NHEAD), 256, ATTN_SMEM>>>();
    gemm_h<<<dim3(HDIM / BN, SEQ / BM), 256, GSMEM>>>(
        ctxh, wo, xmid, nullptr, x, HDIM, NHEAD * DV,
        nullptr, nullptr, nullptr, nullptr, 0, BK, SEQ);

    // ---- MoE branch ----
    rmsnorm_h<<<SEQ, 256>>>(xmid, ln2_w, h2h, h2f, HDIM);
    router_kernel<<<SEQ, 128>>>(rout_w, rout_b);
    zero_kernel<<<1, 32>>>();
    topk_kernel<<<SEQ / 256, 256>>>();
    offsets_kernel<<<1, 1>>>();
    scatter_kernel<<<SEQ / 256, 256>>>();

    gemm_h_moe<<<dim3(2 * MINT / BN, SEQ / BM, NEXP), 256, GSMEM>>>(
        h2h, tok, wg, gth, MINT, wu, uph, MINT, (size_t)MINT * HDIM, HDIM, off);
    act_h_kernel<<<(unsigned)(((size_t)NSLOT * MINT / 2 + 255) / 256), 256>>>(
        (__half2*)gth, (const __half2*)uph, (size_t)NSLOT * MINT / 2);
    gemm_h_moe<<<dim3(HDIM / BN, SEQ / BM, NEXP), 256, GSMEM>>>(
        gth, nullptr, wd, dnh, HDIM, nullptr, nullptr, 0, (size_t)HDIM * MINT, MINT, off);

    // shared expert: fused sg + su
    gemm_h<<<dim3(2 * MINT / BN, SEQ / BM), 256, GSMEM>>>(
        h2h, wsg, nullptr, sgh, nullptr, MINT, HDIM,
        h2h, wsu, nullptr, suh, MINT, HDIM, SEQ);
    act_h_kernel<<<(unsigned)(((size_t)SEQ * MINT / 2 + 255) / 256), 256>>>(
        (__half2*)sgh, (const __half2*)suh, (size_t)SEQ * MINT / 2);
    gemm_h<<<dim3(HDIM / BN, SEQ / BM), 256, GSMEM>>>(
        sgh, wsd, shr, nullptr, nullptr, HDIM, MINT,
        nullptr, nullptr, nullptr, nullptr, 0, BK, SEQ);

    combine_kernel<<<SEQ, 256>>>(out);
}